// round 2
// baseline (speedup 1.0000x reference)
#include <cuda_runtime.h>
#include <math.h>

// ---------------- problem constants ----------------
#define NTOK 4096      // B*T
#define TSEQ 2048
#define HIDD 2048
#define NH   16
#define DHEAD 128      // DQ == DV
#define RROT 32
#define D_CQ 768
#define D_CKV 512
#define D_CO 512
#define QK_SCALE 0.08838834764831845f  // 128^-0.5

// ---------------- scratch (device globals: allocation-free) ----------------
__device__ float g_qs[(size_t)NTOK * D_CQ];          // q_shared (rms'd in place)
__device__ float g_kvs[(size_t)NTOK * D_CKV];        // kv_shared
__device__ float g_q[(size_t)NTOK * 2048];           // q (rope'd in place)  [tok][h*128+d]
__device__ float g_kv[(size_t)NTOK * 4096];          // k in [:,0:2048], v in [:,2048:4096]
__device__ float g_gates[(size_t)NTOK * 2048];       // silu gates (raw gemm out)
__device__ float g_attn[(size_t)NTOK * 2048];        // attention out [tok][h*128+dv]
__device__ float g_o[(size_t)NTOK * D_CO];           // o_private (rms'd in place)

// ---------------- SGEMM: C[M,N] = A[M,K] @ B[N,K]^T (both row-major) ------
// 128x128 block tile, BK=16, 256 threads, 8x8 per thread.
__global__ __launch_bounds__(256, 2) void sgemm_nt(
    const float* __restrict__ A, const float* __restrict__ B, float* __restrict__ C,
    int M, int N, int K)
{
    __shared__ float As[16][132];   // [k][m], +4 pad keeps float4 alignment, kills conflicts
    __shared__ float Bs[16][132];   // [k][n]
    const int bm = blockIdx.y * 128;
    const int bn = blockIdx.x * 128;
    const int tid = threadIdx.x;
    const int tx = tid & 15, ty = tid >> 4;

    float acc[8][8];
#pragma unroll
    for (int i = 0; i < 8; i++)
#pragma unroll
        for (int j = 0; j < 8; j++) acc[i][j] = 0.f;

    for (int k0 = 0; k0 < K; k0 += 16) {
#pragma unroll
        for (int i = 0; i < 2; i++) {
            int f = tid + i * 256;
            int row = f >> 2;
            int kq = (f & 3) << 2;
            float4 va = *(const float4*)(A + (size_t)(bm + row) * K + k0 + kq);
            As[kq + 0][row] = va.x; As[kq + 1][row] = va.y;
            As[kq + 2][row] = va.z; As[kq + 3][row] = va.w;
            float4 vb = *(const float4*)(B + (size_t)(bn + row) * K + k0 + kq);
            Bs[kq + 0][row] = vb.x; Bs[kq + 1][row] = vb.y;
            Bs[kq + 2][row] = vb.z; Bs[kq + 3][row] = vb.w;
        }
        __syncthreads();
#pragma unroll
        for (int k = 0; k < 16; k++) {
            float a[8], b[8];
            *(float4*)&a[0] = *(const float4*)&As[k][ty * 8];
            *(float4*)&a[4] = *(const float4*)&As[k][ty * 8 + 4];
            *(float4*)&b[0] = *(const float4*)&Bs[k][tx * 8];
            *(float4*)&b[4] = *(const float4*)&Bs[k][tx * 8 + 4];
#pragma unroll
            for (int i = 0; i < 8; i++)
#pragma unroll
                for (int j = 0; j < 8; j++) acc[i][j] += a[i] * b[j];
        }
        __syncthreads();
    }
#pragma unroll
    for (int i = 0; i < 8; i++) {
        float4* dst = (float4*)(C + (size_t)(bm + ty * 8 + i) * N + bn + tx * 8);
        float4 v0 = make_float4(acc[i][0], acc[i][1], acc[i][2], acc[i][3]);
        float4 v1 = make_float4(acc[i][4], acc[i][5], acc[i][6], acc[i][7]);
        dst[0] = v0; dst[1] = v1;
    }
}

// ---------------- RMSNorm rows in place: x = w * x * rsqrt(mean(x^2)+eps) --
__global__ void rms_rows(float* __restrict__ X, const float* __restrict__ w, int D)
{
    __shared__ float red[256];
    const int row = blockIdx.x;
    const int tid = threadIdx.x;
    float* x = X + (size_t)row * D;
    float ss = 0.f;
    for (int i = tid; i < D; i += 256) { float v = x[i]; ss += v * v; }
    red[tid] = ss;
    __syncthreads();
    for (int s = 128; s > 0; s >>= 1) {
        if (tid < s) red[tid] += red[tid + s];
        __syncthreads();
    }
    float inv = rsqrtf(red[0] / (float)D + 1e-6f);
    for (int i = tid; i < D; i += 256) x[i] = w[i] * (x[i] * inv);
}

// ---------------- RoPE on first 32 dims of each head, in place ------------
// 256 threads: h = tid>>4 (16 heads), d = tid&15 (16 rotation pairs)
__global__ void rope_kernel(float* __restrict__ X, const float* __restrict__ cosT,
                            const float* __restrict__ sinT, int rowStride)
{
    const int token = blockIdx.x;
    const int t = token & (TSEQ - 1);
    const int h = threadIdx.x >> 4;
    const int d = threadIdx.x & 15;
    float* p = X + (size_t)token * rowStride + h * DHEAD;
    float c0 = cosT[t * RROT + d],      s0 = sinT[t * RROT + d];
    float c1 = cosT[t * RROT + 16 + d], s1 = sinT[t * RROT + 16 + d];
    float x0 = p[d], x1 = p[d + 16];
    p[d]      = x0 * c0 - x1 * s0;
    p[d + 16] = x1 * c1 + x0 * s1;
}

// ---------------- v *= silu(gate), v lives at g_kv[:, 2048:] --------------
__global__ void gate_v_kernel(float* __restrict__ kv, const float* __restrict__ gates)
{
    size_t idx = (size_t)blockIdx.x * 256 + threadIdx.x;   // over NTOK*2048
    size_t token = idx >> 11;
    int c = (int)(idx & 2047);
    float g = gates[idx];
    float sg = g / (1.f + __expf(-g));
    kv[token * 4096 + 2048 + c] *= sg;
}

// ---------------- flash attention (causal), fp32 --------------------------
// Block: 128 q-rows x 64 k-cols per tile, D=128, 256 threads.
// grid: (TSEQ/128, NH, B)
#define Q_OFF 0
#define Q_SZ  (128 * 132)            // Qst[d][m]
#define K_OFF (Q_OFF + Q_SZ)
#define K_SZ  (128 * 68)             // Kst[d][n]
#define V_OFF (K_OFF + K_SZ)
#define V_SZ  (64 * 132)             // Vs[j][c]
#define P_OFF (V_OFF + V_SZ)
#define P_SZ  (128 * 65)             // Pst[m][j], stride 65 (conflict-free row scan)
#define MS_OFF (P_OFF + P_SZ)
#define ATTN_SMEM_BYTES ((MS_OFF + 3 * 128) * 4)

__global__ __launch_bounds__(256, 1) void flash_attn(
    const float* __restrict__ Q, const float* __restrict__ KV, float* __restrict__ O)
{
    extern __shared__ float sm[];
    float* Qst  = sm + Q_OFF;
    float* Kst  = sm + K_OFF;
    float* Vs   = sm + V_OFF;
    float* Pst  = sm + P_OFF;
    float* Mrow = sm + MS_OFF;
    float* Lrow = Mrow + 128;
    float* Crow = Lrow + 128;

    const int qt = blockIdx.x, h = blockIdx.y, b = blockIdx.z;
    const int tid = threadIdx.x;
    const int tx = tid & 15, ty = tid >> 4;
    const size_t qbase = (size_t)b * TSEQ + qt * 128;

    // load 128x128 Q tile, transposed into Qst[d][m]
#pragma unroll
    for (int i = 0; i < 16; i++) {
        int f = tid + i * 256;
        int m = f >> 5;
        int dq = (f & 31) << 2;
        float4 v = *(const float4*)(Q + (qbase + m) * 2048 + h * 128 + dq);
        Qst[(dq + 0) * 132 + m] = v.x; Qst[(dq + 1) * 132 + m] = v.y;
        Qst[(dq + 2) * 132 + m] = v.z; Qst[(dq + 3) * 132 + m] = v.w;
    }
    if (tid < 128) { Mrow[tid] = -1e30f; Lrow[tid] = 0.f; }

    float o[8][8];
#pragma unroll
    for (int i = 0; i < 8; i++)
#pragma unroll
        for (int j = 0; j < 8; j++) o[i][j] = 0.f;

    const int nkt = 2 * qt + 2;
    for (int kt = 0; kt < nkt; kt++) {
        __syncthreads();   // prev PV done (and Q tile ready on first iter)
        const size_t kbase = (size_t)b * TSEQ + kt * 64;
        // load K tile (transposed) and V tile
#pragma unroll
        for (int i = 0; i < 8; i++) {
            int f = tid + i * 256;
            int n = f >> 5;
            int dq = (f & 31) << 2;
            float4 vk = *(const float4*)(KV + (kbase + n) * 4096 + h * 128 + dq);
            Kst[(dq + 0) * 68 + n] = vk.x; Kst[(dq + 1) * 68 + n] = vk.y;
            Kst[(dq + 2) * 68 + n] = vk.z; Kst[(dq + 3) * 68 + n] = vk.w;
            float4 vv = *(const float4*)(KV + (kbase + n) * 4096 + 2048 + h * 128 + dq);
            *(float4*)&Vs[n * 132 + dq] = vv;
        }
        __syncthreads();

        // S = Q K^T : thread owns 8 rows x 4 cols
        float s[8][4];
#pragma unroll
        for (int i = 0; i < 8; i++)
#pragma unroll
            for (int j = 0; j < 4; j++) s[i][j] = 0.f;
#pragma unroll 4
        for (int d = 0; d < 128; d++) {
            float a[8], bb[4];
            *(float4*)&a[0] = *(const float4*)&Qst[d * 132 + ty * 8];
            *(float4*)&a[4] = *(const float4*)&Qst[d * 132 + ty * 8 + 4];
            *(float4*)&bb[0] = *(const float4*)&Kst[d * 68 + tx * 4];
#pragma unroll
            for (int i = 0; i < 8; i++)
#pragma unroll
                for (int j = 0; j < 4; j++) s[i][j] += a[i] * bb[j];
        }
        // scale + causal mask -> Pst[m][j]
#pragma unroll
        for (int ii = 0; ii < 8; ii++) {
            int qg = qt * 128 + ty * 8 + ii;
#pragma unroll
            for (int jj = 0; jj < 4; jj++) {
                int kg = kt * 64 + tx * 4 + jj;
                float val = (kg <= qg) ? s[ii][jj] * QK_SCALE : -1e30f;
                Pst[(ty * 8 + ii) * 65 + tx * 4 + jj] = val;
            }
        }
        __syncthreads();

        // online softmax per row (one thread per q row)
        if (tid < 128) {
            float* pr = Pst + tid * 65;
            float mOld = Mrow[tid];
            float mx = mOld;
#pragma unroll 8
            for (int j = 0; j < 64; j++) mx = fmaxf(mx, pr[j]);
            float c = __expf(mOld - mx);
            float l = Lrow[tid] * c;
#pragma unroll 8
            for (int j = 0; j < 64; j++) {
                float p = __expf(pr[j] - mx);
                pr[j] = p;
                l += p;
            }
            Mrow[tid] = mx; Lrow[tid] = l; Crow[tid] = c;
        }
        __syncthreads();

        // rescale O, accumulate O += P @ V : thread owns 8 rows x 8 dv-cols
        float cr[8];
#pragma unroll
        for (int ii = 0; ii < 8; ii++) cr[ii] = Crow[ty * 8 + ii];
#pragma unroll
        for (int ii = 0; ii < 8; ii++)
#pragma unroll
            for (int jj = 0; jj < 8; jj++) o[ii][jj] *= cr[ii];

        for (int j = 0; j < 64; j++) {
            float a[8], bb[8];
#pragma unroll
            for (int ii = 0; ii < 8; ii++) a[ii] = Pst[(ty * 8 + ii) * 65 + j];
            *(float4*)&bb[0] = *(const float4*)&Vs[j * 132 + tx * 8];
            *(float4*)&bb[4] = *(const float4*)&Vs[j * 132 + tx * 8 + 4];
#pragma unroll
            for (int ii = 0; ii < 8; ii++)
#pragma unroll
                for (int jj = 0; jj < 8; jj++) o[ii][jj] += a[ii] * bb[jj];
        }
    }

    // epilogue: O /= l, write [tok][h*128 + c]
#pragma unroll
    for (int ii = 0; ii < 8; ii++) {
        float inv = 1.f / Lrow[ty * 8 + ii];
        float4 v0 = make_float4(o[ii][0] * inv, o[ii][1] * inv, o[ii][2] * inv, o[ii][3] * inv);
        float4 v1 = make_float4(o[ii][4] * inv, o[ii][5] * inv, o[ii][6] * inv, o[ii][7] * inv);
        float4* dst = (float4*)(O + (qbase + ty * 8 + ii) * 2048 + h * 128 + tx * 8);
        dst[0] = v0; dst[1] = v1;
    }
}

// ---------------- launcher -------------------------------------------------
extern "C" void kernel_launch(void* const* d_in, const int* in_sizes, int n_in,
                              void* d_out, int out_size)
{
    const float* x     = (const float*)d_in[0];
    const float* cosT  = (const float*)d_in[1];
    const float* sinT  = (const float*)d_in[2];
    const float* Wq_s  = (const float*)d_in[3];
    const float* qs_w  = (const float*)d_in[4];
    const float* Wkv_s = (const float*)d_in[5];
    const float* kvs_w = (const float*)d_in[6];
    const float* Wq_p  = (const float*)d_in[7];
    const float* Wkv_p = (const float*)d_in[8];
    const float* Wg_p  = (const float*)d_in[9];
    const float* Wo_p  = (const float*)d_in[10];
    const float* o_w   = (const float*)d_in[11];
    const float* Wo_s  = (const float*)d_in[12];
    float* out = (float*)d_out;

    float *qs, *kvs, *q, *kv, *gates, *attn, *o;
    cudaGetSymbolAddress((void**)&qs,    g_qs);
    cudaGetSymbolAddress((void**)&kvs,   g_kvs);
    cudaGetSymbolAddress((void**)&q,     g_q);
    cudaGetSymbolAddress((void**)&kv,    g_kv);
    cudaGetSymbolAddress((void**)&gates, g_gates);
    cudaGetSymbolAddress((void**)&attn,  g_attn);
    cudaGetSymbolAddress((void**)&o,     g_o);

    cudaFuncSetAttribute(flash_attn, cudaFuncAttributeMaxDynamicSharedMemorySize,
                         ATTN_SMEM_BYTES);

    dim3 blk(256);
    // shared projections + RMS
    sgemm_nt<<<dim3(D_CQ / 128,  NTOK / 128), blk>>>(x, Wq_s,  qs,  NTOK, D_CQ,  HIDD);
    rms_rows<<<NTOK, 256>>>(qs, qs_w, D_CQ);
    sgemm_nt<<<dim3(D_CKV / 128, NTOK / 128), blk>>>(x, Wkv_s, kvs, NTOK, D_CKV, HIDD);
    rms_rows<<<NTOK, 256>>>(kvs, kvs_w, D_CKV);
    // private projections + gates
    sgemm_nt<<<dim3(2048 / 128, NTOK / 128), blk>>>(qs,  Wq_p,  q,     NTOK, 2048, D_CQ);
    sgemm_nt<<<dim3(4096 / 128, NTOK / 128), blk>>>(kvs, Wkv_p, kv,    NTOK, 4096, D_CKV);
    sgemm_nt<<<dim3(2048 / 128, NTOK / 128), blk>>>(x,   Wg_p,  gates, NTOK, 2048, HIDD);
    // rope q, rope k, gate v
    rope_kernel<<<NTOK, 256>>>(q,  cosT, sinT, 2048);
    rope_kernel<<<NTOK, 256>>>(kv, cosT, sinT, 4096);
    gate_v_kernel<<<(NTOK * 2048) / 256, 256>>>(kv, gates);
    // attention
    flash_attn<<<dim3(TSEQ / 128, NH, 2), blk, ATTN_SMEM_BYTES>>>(q, kv, attn);
    // output projections
    sgemm_nt<<<dim3(D_CO / 128, NTOK / 128), blk>>>(attn, Wo_p, o, NTOK, D_CO, 2048);
    rms_rows<<<NTOK, 256>>>(o, o_w, D_CO);
    sgemm_nt<<<dim3(HIDD / 128, NTOK / 128), blk>>>(o, Wo_s, out, NTOK, HIDD, D_CO);
}

// round 3
// speedup vs baseline: 2.3887x; 2.3887x over previous
#include <cuda_runtime.h>
#include <math.h>
#include <stdint.h>

// ---------------- problem constants ----------------
#define NTOK 4096      // B*T
#define TSEQ 2048
#define HIDD 2048
#define NH   16
#define DHEAD 128
#define RROT 32
#define D_CQ 768
#define D_CKV 512
#define D_CO 512
#define QK_SCALE 0.08838834764831845f  // 128^-0.5

// ---------------- scratch ----------------
__device__ float g_qs[(size_t)NTOK * D_CQ];
__device__ float g_kvs[(size_t)NTOK * D_CKV];
__device__ float g_q[(size_t)NTOK * 2048];
__device__ float g_kv[(size_t)NTOK * 4096];     // k | v
__device__ float g_gates[(size_t)NTOK * 2048];
__device__ float g_attn[(size_t)NTOK * 2048];
__device__ float g_o[(size_t)NTOK * D_CO];

// ---------------- tf32 helpers ----------------
__device__ __forceinline__ float f2tf(float x) {
    float r;
    asm("cvt.rna.tf32.f32 %0, %1;" : "=f"(r) : "f"(x));
    return r;
}
__device__ __forceinline__ void mma8(float c[4], const uint32_t a[4], const uint32_t b[2]) {
    asm volatile(
        "mma.sync.aligned.m16n8k8.row.col.f32.tf32.tf32.f32 "
        "{%0,%1,%2,%3},{%4,%5,%6,%7},{%8,%9},{%0,%1,%2,%3};"
        : "+f"(c[0]), "+f"(c[1]), "+f"(c[2]), "+f"(c[3])
        : "r"(a[0]), "r"(a[1]), "r"(a[2]), "r"(a[3]), "r"(b[0]), "r"(b[1]));
}

// ---------------- tf32 GEMM: C[M,N] = A[M,K] @ B[N,K]^T -------------------
// 128x128 tile, BK=16, 256 threads; warp grid 4m x 2n, warp tile 32x64.
#define GBK 16
__global__ __launch_bounds__(256) void gemm_tf32(
    const float* __restrict__ A, const float* __restrict__ B, float* __restrict__ C,
    int M, int N, int K)
{
    __shared__ float As[GBK][136];   // [k][m], stride 136: frag banks 8*tig+g bijective
    __shared__ float Bs[GBK][136];   // [k][n]
    const int bm = blockIdx.y * 128, bn = blockIdx.x * 128;
    const int tid = threadIdx.x, lane = tid & 31, w = tid >> 5;
    const int g = lane >> 2, tig = lane & 3;
    const int wm = (w & 3) * 32, wn = (w >> 2) * 64;
    const int lrow = tid >> 2, lkq = (tid & 3) << 2;

    float acc[2][8][4];
#pragma unroll
    for (int mt = 0; mt < 2; mt++)
#pragma unroll
        for (int nt = 0; nt < 8; nt++)
#pragma unroll
            for (int r = 0; r < 4; r++) acc[mt][nt][r] = 0.f;

    // preload tile 0 into regs
    float4 ra[2], rb[2];
#pragma unroll
    for (int i = 0; i < 2; i++) {
        ra[i] = *(const float4*)(A + (size_t)(bm + lrow + i * 64) * K + lkq);
        rb[i] = *(const float4*)(B + (size_t)(bn + lrow + i * 64) * K + lkq);
    }

    for (int k0 = 0; k0 < K; k0 += GBK) {
        // stage regs -> smem (tf32 convert here, off the hot loop)
#pragma unroll
        for (int i = 0; i < 2; i++) {
            int r = lrow + i * 64;
            As[lkq + 0][r] = f2tf(ra[i].x); As[lkq + 1][r] = f2tf(ra[i].y);
            As[lkq + 2][r] = f2tf(ra[i].z); As[lkq + 3][r] = f2tf(ra[i].w);
            Bs[lkq + 0][r] = f2tf(rb[i].x); Bs[lkq + 1][r] = f2tf(rb[i].y);
            Bs[lkq + 2][r] = f2tf(rb[i].z); Bs[lkq + 3][r] = f2tf(rb[i].w);
        }
        __syncthreads();
        if (k0 + GBK < K) {      // prefetch next tile while mma runs
#pragma unroll
            for (int i = 0; i < 2; i++) {
                ra[i] = *(const float4*)(A + (size_t)(bm + lrow + i * 64) * K + k0 + GBK + lkq);
                rb[i] = *(const float4*)(B + (size_t)(bn + lrow + i * 64) * K + k0 + GBK + lkq);
            }
        }
        const uint32_t* Au = (const uint32_t*)&As[0][0];
        const uint32_t* Bu = (const uint32_t*)&Bs[0][0];
#pragma unroll
        for (int ks = 0; ks < 2; ks++) {
            const int kb = ks * 8;
            uint32_t af[2][4], bf[8][2];
#pragma unroll
            for (int mt = 0; mt < 2; mt++) {
                int m0 = wm + mt * 16;
                af[mt][0] = Au[(kb + tig) * 136 + m0 + g];
                af[mt][1] = Au[(kb + tig) * 136 + m0 + g + 8];
                af[mt][2] = Au[(kb + tig + 4) * 136 + m0 + g];
                af[mt][3] = Au[(kb + tig + 4) * 136 + m0 + g + 8];
            }
#pragma unroll
            for (int nt = 0; nt < 8; nt++) {
                int n0 = wn + nt * 8;
                bf[nt][0] = Bu[(kb + tig) * 136 + n0 + g];
                bf[nt][1] = Bu[(kb + tig + 4) * 136 + n0 + g];
            }
#pragma unroll
            for (int mt = 0; mt < 2; mt++)
#pragma unroll
                for (int nt = 0; nt < 8; nt++)
                    mma8(acc[mt][nt], af[mt], bf[nt]);
        }
        __syncthreads();
    }

#pragma unroll
    for (int mt = 0; mt < 2; mt++) {
        int r0 = bm + wm + mt * 16 + g;
#pragma unroll
        for (int nt = 0; nt < 8; nt++) {
            int c0 = bn + wn + nt * 8 + 2 * tig;
            *(float2*)(C + (size_t)r0 * N + c0)       = make_float2(acc[mt][nt][0], acc[mt][nt][1]);
            *(float2*)(C + (size_t)(r0 + 8) * N + c0) = make_float2(acc[mt][nt][2], acc[mt][nt][3]);
        }
    }
}

// ---------------- RMSNorm rows in place ----------------
__global__ void rms_rows(float* __restrict__ X, const float* __restrict__ w, int D)
{
    __shared__ float red[256];
    const int row = blockIdx.x, tid = threadIdx.x;
    float* x = X + (size_t)row * D;
    float ss = 0.f;
    for (int i = tid; i < D; i += 256) { float v = x[i]; ss += v * v; }
    red[tid] = ss;
    __syncthreads();
    for (int s = 128; s > 0; s >>= 1) {
        if (tid < s) red[tid] += red[tid + s];
        __syncthreads();
    }
    float inv = rsqrtf(red[0] / (float)D + 1e-6f);
    for (int i = tid; i < D; i += 256) x[i] = w[i] * (x[i] * inv);
}

// ---------------- RoPE ----------------
__global__ void rope_kernel(float* __restrict__ X, const float* __restrict__ cosT,
                            const float* __restrict__ sinT, int rowStride)
{
    const int token = blockIdx.x;
    const int t = token & (TSEQ - 1);
    const int h = threadIdx.x >> 4;
    const int d = threadIdx.x & 15;
    float* p = X + (size_t)token * rowStride + h * DHEAD;
    float c0 = cosT[t * RROT + d],      s0 = sinT[t * RROT + d];
    float c1 = cosT[t * RROT + 16 + d], s1 = sinT[t * RROT + 16 + d];
    float x0 = p[d], x1 = p[d + 16];
    p[d]      = x0 * c0 - x1 * s0;
    p[d + 16] = x1 * c1 + x0 * s1;
}

// ---------------- v *= silu(gate) ----------------
__global__ void gate_v_kernel(float* __restrict__ kv, const float* __restrict__ gates)
{
    size_t idx = (size_t)blockIdx.x * 256 + threadIdx.x;
    size_t token = idx >> 11;
    int c = (int)(idx & 2047);
    float g = gates[idx];
    float sg = g / (1.f + __expf(-g));
    kv[token * 4096 + 2048 + c] *= sg;
}

// ---------------- flash attention, tf32 tensor cores ----------------------
// 128 q-rows x 64 k-cols per tile, D=128, 256 threads (8 warps).
// S gemm: warp tile 32q x 32k ; PV gemm: warp tile 32q x 64dv.
#define QS_STRIDE 132   // banks (4g+tig): bijective
#define KS_STRIDE 132
#define VS_STRIDE 136   // banks (8tig+g): bijective
#define PS_STRIDE 68    // A-frag banks (4g+tig): bijective
#define FA_Q_OFF 0
#define FA_K_OFF (FA_Q_OFF + 128 * QS_STRIDE)
#define FA_V_OFF (FA_K_OFF + 64 * KS_STRIDE)
#define FA_P_OFF (FA_V_OFF + 64 * VS_STRIDE)
#define FA_M_OFF (FA_P_OFF + 128 * PS_STRIDE)
#define FA_SMEM_BYTES ((FA_M_OFF + 3 * 128) * 4)

__global__ __launch_bounds__(256, 1) void flash_tf32(
    const float* __restrict__ Q, const float* __restrict__ KV, float* __restrict__ O)
{
    extern __shared__ float sm[];
    float* Qs = sm + FA_Q_OFF;
    float* Ks = sm + FA_K_OFF;
    float* Vs = sm + FA_V_OFF;
    float* Ps = sm + FA_P_OFF;
    float* Mrow = sm + FA_M_OFF;
    float* Lrow = Mrow + 128;
    float* Crow = Lrow + 128;
    const uint32_t* Qu = (const uint32_t*)Qs;
    const uint32_t* Ku = (const uint32_t*)Ks;
    const uint32_t* Vu = (const uint32_t*)Vs;
    const uint32_t* Pu = (const uint32_t*)Ps;

    const int qt = blockIdx.x, h = blockIdx.y, b = blockIdx.z;
    const int tid = threadIdx.x, lane = tid & 31, w = tid >> 5;
    const int g = lane >> 2, tig = lane & 3;
    const int wm = (w & 3) * 32;          // q-rows for this warp
    const int wns = (w >> 2) * 32;        // S k-cols
    const int wno = (w >> 2) * 64;        // PV dv-cols
    const size_t qbase = (size_t)b * TSEQ + qt * 128;
    const int dq = lane * 4;

    // load + tf32-convert Q tile (128x128) into Qs[m][d]
#pragma unroll
    for (int i = 0; i < 16; i++) {
        int m = w + i * 8;
        float4 v = *(const float4*)(Q + (qbase + m) * 2048 + h * 128 + dq);
        float4 t = make_float4(f2tf(v.x), f2tf(v.y), f2tf(v.z), f2tf(v.w));
        *(float4*)&Qs[m * QS_STRIDE + dq] = t;
    }
    if (tid < 128) { Mrow[tid] = -1e30f; Lrow[tid] = 0.f; }

    float o[2][8][4];
#pragma unroll
    for (int mt = 0; mt < 2; mt++)
#pragma unroll
        for (int nt = 0; nt < 8; nt++)
#pragma unroll
            for (int r = 0; r < 4; r++) o[mt][nt][r] = 0.f;

    const int nkt = 2 * qt + 2;
    for (int kt = 0; kt < nkt; kt++) {
        __syncthreads();   // prev PV done reading Vs/Ps; Q ready on iter 0
        const size_t kbase = (size_t)b * TSEQ + kt * 64;
#pragma unroll
        for (int i = 0; i < 8; i++) {
            int n = w + i * 8;
            float4 vk = *(const float4*)(KV + (kbase + n) * 4096 + h * 128 + dq);
            *(float4*)&Ks[n * KS_STRIDE + dq] =
                make_float4(f2tf(vk.x), f2tf(vk.y), f2tf(vk.z), f2tf(vk.w));
            float4 vv = *(const float4*)(KV + (kbase + n) * 4096 + 2048 + h * 128 + dq);
            *(float4*)&Vs[n * VS_STRIDE + dq] =
                make_float4(f2tf(vv.x), f2tf(vv.y), f2tf(vv.z), f2tf(vv.w));
        }
        __syncthreads();

        // ---- S = Q K^T (warp 32x32), tf32 mma over D=128 ----
        float s[2][4][4];
#pragma unroll
        for (int mt = 0; mt < 2; mt++)
#pragma unroll
            for (int nt = 0; nt < 4; nt++)
#pragma unroll
                for (int r = 0; r < 4; r++) s[mt][nt][r] = 0.f;
#pragma unroll
        for (int d0 = 0; d0 < 128; d0 += 8) {
            uint32_t af[2][4], bf[4][2];
#pragma unroll
            for (int mt = 0; mt < 2; mt++) {
                int m0 = wm + mt * 16;
                af[mt][0] = Qu[(m0 + g) * QS_STRIDE + d0 + tig];
                af[mt][1] = Qu[(m0 + g + 8) * QS_STRIDE + d0 + tig];
                af[mt][2] = Qu[(m0 + g) * QS_STRIDE + d0 + tig + 4];
                af[mt][3] = Qu[(m0 + g + 8) * QS_STRIDE + d0 + tig + 4];
            }
#pragma unroll
            for (int nt = 0; nt < 4; nt++) {
                int n0 = wns + nt * 8;
                bf[nt][0] = Ku[(n0 + g) * KS_STRIDE + d0 + tig];
                bf[nt][1] = Ku[(n0 + g) * KS_STRIDE + d0 + tig + 4];
            }
#pragma unroll
            for (int mt = 0; mt < 2; mt++)
#pragma unroll
                for (int nt = 0; nt < 4; nt++)
                    mma8(s[mt][nt], af[mt], bf[nt]);
        }
        // mask + scale -> Ps
#pragma unroll
        for (int mt = 0; mt < 2; mt++) {
            int r0 = wm + mt * 16 + g;
            int qg0 = qt * 128 + r0, qg1 = qg0 + 8;
#pragma unroll
            for (int nt = 0; nt < 4; nt++) {
                int c0 = wns + nt * 8 + 2 * tig;
                int kg0 = kt * 64 + c0, kg1 = kg0 + 1;
                float v00 = (kg0 <= qg0) ? s[mt][nt][0] * QK_SCALE : -1e30f;
                float v01 = (kg1 <= qg0) ? s[mt][nt][1] * QK_SCALE : -1e30f;
                float v10 = (kg0 <= qg1) ? s[mt][nt][2] * QK_SCALE : -1e30f;
                float v11 = (kg1 <= qg1) ? s[mt][nt][3] * QK_SCALE : -1e30f;
                *(float2*)&Ps[r0 * PS_STRIDE + c0]       = make_float2(v00, v01);
                *(float2*)&Ps[(r0 + 8) * PS_STRIDE + c0] = make_float2(v10, v11);
            }
        }
        __syncthreads();

        // ---- online softmax: 2 threads per row (32 cols each) ----
        {
            int row = tid >> 1, half = tid & 1;
            float* pr = Ps + row * PS_STRIDE + half * 32;
            float mx = -1e30f;
#pragma unroll 8
            for (int j = 0; j < 32; j++) mx = fmaxf(mx, pr[j]);
            mx = fmaxf(mx, __shfl_xor_sync(0xffffffff, mx, 1));
            float mOld = Mrow[row];
            float mnew = fmaxf(mOld, mx);
            float l = 0.f;
#pragma unroll 8
            for (int j = 0; j < 32; j++) {
                float p = f2tf(__expf(pr[j] - mnew));
                pr[j] = p;
                l += p;
            }
            l += __shfl_xor_sync(0xffffffff, l, 1);
            if (half == 0) {
                float c = __expf(mOld - mnew);
                Mrow[row] = mnew;
                Lrow[row] = Lrow[row] * c + l;
                Crow[row] = c;
            }
        }
        __syncthreads();

        // ---- rescale O, then O += P @ V (warp 32x64) ----
#pragma unroll
        for (int mt = 0; mt < 2; mt++) {
            float c0 = Crow[wm + mt * 16 + g];
            float c1 = Crow[wm + mt * 16 + g + 8];
#pragma unroll
            for (int nt = 0; nt < 8; nt++) {
                o[mt][nt][0] *= c0; o[mt][nt][1] *= c0;
                o[mt][nt][2] *= c1; o[mt][nt][3] *= c1;
            }
        }
#pragma unroll
        for (int ks = 0; ks < 8; ks++) {
            const int k0 = ks * 8;
            uint32_t af[2][4], bf[8][2];
#pragma unroll
            for (int mt = 0; mt < 2; mt++) {
                int m0 = wm + mt * 16;
                af[mt][0] = Pu[(m0 + g) * PS_STRIDE + k0 + tig];
                af[mt][1] = Pu[(m0 + g + 8) * PS_STRIDE + k0 + tig];
                af[mt][2] = Pu[(m0 + g) * PS_STRIDE + k0 + tig + 4];
                af[mt][3] = Pu[(m0 + g + 8) * PS_STRIDE + k0 + tig + 4];
            }
#pragma unroll
            for (int nt = 0; nt < 8; nt++) {
                int n0 = wno + nt * 8;
                bf[nt][0] = Vu[(k0 + tig) * VS_STRIDE + n0 + g];
                bf[nt][1] = Vu[(k0 + tig + 4) * VS_STRIDE + n0 + g];
            }
#pragma unroll
            for (int mt = 0; mt < 2; mt++)
#pragma unroll
                for (int nt = 0; nt < 8; nt++)
                    mma8(o[mt][nt], af[mt], bf[nt]);
        }
    }

    // epilogue
    __syncthreads();
#pragma unroll
    for (int mt = 0; mt < 2; mt++) {
        int r0 = wm + mt * 16 + g;
        float inv0 = 1.f / Lrow[r0];
        float inv1 = 1.f / Lrow[r0 + 8];
#pragma unroll
        for (int nt = 0; nt < 8; nt++) {
            int c0 = wno + nt * 8 + 2 * tig;
            *(float2*)(O + (qbase + r0) * 2048 + h * 128 + c0) =
                make_float2(o[mt][nt][0] * inv0, o[mt][nt][1] * inv0);
            *(float2*)(O + (qbase + r0 + 8) * 2048 + h * 128 + c0) =
                make_float2(o[mt][nt][2] * inv1, o[mt][nt][3] * inv1);
        }
    }
}

// ---------------- launcher -------------------------------------------------
extern "C" void kernel_launch(void* const* d_in, const int* in_sizes, int n_in,
                              void* d_out, int out_size)
{
    const float* x     = (const float*)d_in[0];
    const float* cosT  = (const float*)d_in[1];
    const float* sinT  = (const float*)d_in[2];
    const float* Wq_s  = (const float*)d_in[3];
    const float* qs_w  = (const float*)d_in[4];
    const float* Wkv_s = (const float*)d_in[5];
    const float* kvs_w = (const float*)d_in[6];
    const float* Wq_p  = (const float*)d_in[7];
    const float* Wkv_p = (const float*)d_in[8];
    const float* Wg_p  = (const float*)d_in[9];
    const float* Wo_p  = (const float*)d_in[10];
    const float* o_w   = (const float*)d_in[11];
    const float* Wo_s  = (const float*)d_in[12];
    float* out = (float*)d_out;

    float *qs, *kvs, *q, *kv, *gates, *attn, *o;
    cudaGetSymbolAddress((void**)&qs,    g_qs);
    cudaGetSymbolAddress((void**)&kvs,   g_kvs);
    cudaGetSymbolAddress((void**)&q,     g_q);
    cudaGetSymbolAddress((void**)&kv,    g_kv);
    cudaGetSymbolAddress((void**)&gates, g_gates);
    cudaGetSymbolAddress((void**)&attn,  g_attn);
    cudaGetSymbolAddress((void**)&o,     g_o);

    cudaFuncSetAttribute(flash_tf32, cudaFuncAttributeMaxDynamicSharedMemorySize,
                         FA_SMEM_BYTES);

    dim3 blk(256);
    gemm_tf32<<<dim3(D_CQ / 128,  NTOK / 128), blk>>>(x, Wq_s,  qs,  NTOK, D_CQ,  HIDD);
    rms_rows<<<NTOK, 256>>>(qs, qs_w, D_CQ);
    gemm_tf32<<<dim3(D_CKV / 128, NTOK / 128), blk>>>(x, Wkv_s, kvs, NTOK, D_CKV, HIDD);
    rms_rows<<<NTOK, 256>>>(kvs, kvs_w, D_CKV);

    gemm_tf32<<<dim3(2048 / 128, NTOK / 128), blk>>>(qs,  Wq_p,  q,     NTOK, 2048, D_CQ);
    gemm_tf32<<<dim3(4096 / 128, NTOK / 128), blk>>>(kvs, Wkv_p, kv,    NTOK, 4096, D_CKV);
    gemm_tf32<<<dim3(2048 / 128, NTOK / 128), blk>>>(x,   Wg_p,  gates, NTOK, 2048, HIDD);

    rope_kernel<<<NTOK, 256>>>(q,  cosT, sinT, 2048);
    rope_kernel<<<NTOK, 256>>>(kv, cosT, sinT, 4096);
    gate_v_kernel<<<(NTOK * 2048) / 256, 256>>>(kv, gates);

    flash_tf32<<<dim3(TSEQ / 128, NH, 2), blk, FA_SMEM_BYTES>>>(q, kv, attn);

    gemm_tf32<<<dim3(D_CO / 128, NTOK / 128), blk>>>(attn, Wo_p, o, NTOK, D_CO, 2048);
    rms_rows<<<NTOK, 256>>>(o, o_w, D_CO);
    gemm_tf32<<<dim3(HIDD / 128, NTOK / 128), blk>>>(o, Wo_s, out, NTOK, HIDD, D_CO);
}

// round 5
// speedup vs baseline: 2.5036x; 1.0481x over previous
#include <cuda_runtime.h>
#include <math.h>
#include <stdint.h>

// ---------------- problem constants ----------------
#define NTOK 4096      // B*T
#define TSEQ 2048
#define HIDD 2048
#define NH   16
#define DHEAD 128
#define RROT 32
#define D_CQ 768
#define D_CKV 512
#define D_CO 512
#define QK_SCALE 0.08838834764831845f  // 128^-0.5

// ---------------- scratch ----------------
__device__ float g_qs[(size_t)NTOK * D_CQ];
__device__ float g_kvs[(size_t)NTOK * D_CKV];
__device__ float g_q[(size_t)NTOK * 2048];
__device__ float g_kv[(size_t)NTOK * 4096];     // k | v
__device__ float g_gates[(size_t)NTOK * 2048];
__device__ float g_attn[(size_t)NTOK * 2048];
__device__ float g_o[(size_t)NTOK * D_CO];

// ---------------- tf32 helpers ----------------
__device__ __forceinline__ float f2tf(float x) {
    float r;
    asm("cvt.rna.tf32.f32 %0, %1;" : "=f"(r) : "f"(x));
    return r;
}
__device__ __forceinline__ float4 tf4(float4 v) {
    return make_float4(f2tf(v.x), f2tf(v.y), f2tf(v.z), f2tf(v.w));
}
__device__ __forceinline__ void mma8(float c[4], const uint32_t a[4], const uint32_t b[2]) {
    asm volatile(
        "mma.sync.aligned.m16n8k8.row.col.f32.tf32.tf32.f32 "
        "{%0,%1,%2,%3},{%4,%5,%6,%7},{%8,%9},{%0,%1,%2,%3};"
        : "+f"(c[0]), "+f"(c[1]), "+f"(c[2]), "+f"(c[3])
        : "r"(a[0]), "r"(a[1]), "r"(a[2]), "r"(a[3]), "r"(b[0]), "r"(b[1]));
}

// ---------------- tf32 GEMM v2: C[M,N] = A[M,K] @ B[N,K]^T -----------------
// 256x128 block tile, BK=16, 256 threads; warp grid 4m x 2n, warp tile 64x64.
// smem [m][k] layout, row stride 20 floats (frag-load banks 20g+tig: bijective).
// Double-buffered, one __syncthreads per BK16.
#define BM 256
#define BN 128
#define AST 20
#define ABUF (BM * AST)          // 5120 floats
#define BBUF (BN * AST)          // 2560 floats
#define STAGE (ABUF + BBUF)      // 7680 floats per buffer
#define G2_SMEM_BYTES (2 * STAGE * 4)

__global__ __launch_bounds__(256) void gemm_v2(
    const float* __restrict__ A, const float* __restrict__ B, float* __restrict__ C,
    int N, int K)
{
    extern __shared__ float sh[];
    const int tid = threadIdx.x, lane = tid & 31, w = tid >> 5;
    const int g = lane >> 2, tig = lane & 3;
    const int wm = (w & 3) * 64, wn = (w >> 2) * 64;
    const int bm = blockIdx.y * BM, bn = blockIdx.x * BN;
    const int lrow = tid >> 2, lkq = (tid & 3) << 2;

    float acc[4][8][4];
#pragma unroll
    for (int mt = 0; mt < 4; mt++)
#pragma unroll
        for (int nt = 0; nt < 8; nt++)
#pragma unroll
            for (int r = 0; r < 4; r++) acc[mt][nt][r] = 0.f;

    const float* pa = A + (size_t)(bm + lrow) * K + lkq;
    const float* pb = B + (size_t)(bn + lrow) * K + lkq;

    // preload + stage tile 0
    float4 ra[4], rb[2];
#pragma unroll
    for (int j = 0; j < 4; j++) ra[j] = *(const float4*)(pa + (size_t)j * 64 * K);
#pragma unroll
    for (int j = 0; j < 2; j++) rb[j] = *(const float4*)(pb + (size_t)j * 64 * K);
#pragma unroll
    for (int j = 0; j < 4; j++)
        *(float4*)&sh[(lrow + 64 * j) * AST + lkq] = tf4(ra[j]);
#pragma unroll
    for (int j = 0; j < 2; j++)
        *(float4*)&sh[ABUF + (lrow + 64 * j) * AST + lkq] = tf4(rb[j]);
    __syncthreads();

    const int ntile = K >> 4;
    for (int i = 0; i < ntile; i++) {
        const float* Ac = sh + (i & 1) * STAGE;
        const float* Bc = Ac + ABUF;
        // prefetch next tile (gmem) while mma runs
        if (i + 1 < ntile) {
#pragma unroll
            for (int j = 0; j < 4; j++)
                ra[j] = *(const float4*)(pa + (size_t)(i + 1) * 16 + (size_t)j * 64 * K);
#pragma unroll
            for (int j = 0; j < 2; j++)
                rb[j] = *(const float4*)(pb + (size_t)(i + 1) * 16 + (size_t)j * 64 * K);
        }
#pragma unroll
        for (int ks = 0; ks < 2; ks++) {
            const int kb = ks * 8;
            uint32_t af[4][4], bf[8][2];
#pragma unroll
            for (int mt = 0; mt < 4; mt++) {
                int m0 = wm + mt * 16;
                af[mt][0] = __float_as_uint(Ac[(m0 + g) * AST + kb + tig]);
                af[mt][1] = __float_as_uint(Ac[(m0 + g + 8) * AST + kb + tig]);
                af[mt][2] = __float_as_uint(Ac[(m0 + g) * AST + kb + tig + 4]);
                af[mt][3] = __float_as_uint(Ac[(m0 + g + 8) * AST + kb + tig + 4]);
            }
#pragma unroll
            for (int nt = 0; nt < 8; nt++) {
                int n0 = wn + nt * 8;
                bf[nt][0] = __float_as_uint(Bc[(n0 + g) * AST + kb + tig]);
                bf[nt][1] = __float_as_uint(Bc[(n0 + g) * AST + kb + tig + 4]);
            }
#pragma unroll
            for (int mt = 0; mt < 4; mt++)
#pragma unroll
                for (int nt = 0; nt < 8; nt++)
                    mma8(acc[mt][nt], af[mt], bf[nt]);
        }
        // stage next tile into the other buffer
        if (i + 1 < ntile) {
            float* An = sh + ((i + 1) & 1) * STAGE;
#pragma unroll
            for (int j = 0; j < 4; j++)
                *(float4*)&An[(lrow + 64 * j) * AST + lkq] = tf4(ra[j]);
#pragma unroll
            for (int j = 0; j < 2; j++)
                *(float4*)&An[ABUF + (lrow + 64 * j) * AST + lkq] = tf4(rb[j]);
        }
        __syncthreads();
    }

#pragma unroll
    for (int mt = 0; mt < 4; mt++) {
        int r0 = bm + wm + mt * 16 + g;
#pragma unroll
        for (int nt = 0; nt < 8; nt++) {
            int c0 = bn + wn + nt * 8 + 2 * tig;
            *(float2*)(C + (size_t)r0 * N + c0)       = make_float2(acc[mt][nt][0], acc[mt][nt][1]);
            *(float2*)(C + (size_t)(r0 + 8) * N + c0) = make_float2(acc[mt][nt][2], acc[mt][nt][3]);
        }
    }
}

// ---------------- RMSNorm rows in place ----------------
__global__ void rms_rows(float* __restrict__ X, const float* __restrict__ w, int D)
{
    __shared__ float red[256];
    const int row = blockIdx.x, tid = threadIdx.x;
    float* x = X + (size_t)row * D;
    float ss = 0.f;
    for (int i = tid; i < D; i += 256) { float v = x[i]; ss += v * v; }
    red[tid] = ss;
    __syncthreads();
    for (int s = 128; s > 0; s >>= 1) {
        if (tid < s) red[tid] += red[tid + s];
        __syncthreads();
    }
    float inv = rsqrtf(red[0] / (float)D + 1e-6f);
    for (int i = tid; i < D; i += 256) x[i] = w[i] * (x[i] * inv);
}

// ---------------- RoPE ----------------
__global__ void rope_kernel(float* __restrict__ X, const float* __restrict__ cosT,
                            const float* __restrict__ sinT, int rowStride)
{
    const int token = blockIdx.x;
    const int t = token & (TSEQ - 1);
    const int h = threadIdx.x >> 4;
    const int d = threadIdx.x & 15;
    float* p = X + (size_t)token * rowStride + h * DHEAD;
    float c0 = cosT[t * RROT + d],      s0 = sinT[t * RROT + d];
    float c1 = cosT[t * RROT + 16 + d], s1 = sinT[t * RROT + 16 + d];
    float x0 = p[d], x1 = p[d + 16];
    p[d]      = x0 * c0 - x1 * s0;
    p[d + 16] = x1 * c1 + x0 * s1;
}

// ---------------- v *= silu(gate) ----------------
__global__ void gate_v_kernel(float* __restrict__ kv, const float* __restrict__ gates)
{
    size_t idx = (size_t)blockIdx.x * 256 + threadIdx.x;
    size_t token = idx >> 11;
    int c = (int)(idx & 2047);
    float g = gates[idx];
    float sg = g / (1.f + __expf(-g));
    kv[token * 4096 + 2048 + c] *= sg;
}

// ---------------- flash attention, tf32 legacy mma (verified R3) ----------
#define QS_STRIDE 132
#define KS_STRIDE 132
#define VS_STRIDE 136
#define PS_STRIDE 68
#define FA_Q_OFF 0
#define FA_K_OFF (FA_Q_OFF + 128 * QS_STRIDE)
#define FA_V_OFF (FA_K_OFF + 64 * KS_STRIDE)
#define FA_P_OFF (FA_V_OFF + 64 * VS_STRIDE)
#define FA_M_OFF (FA_P_OFF + 128 * PS_STRIDE)
#define FA_SMEM_BYTES ((FA_M_OFF + 3 * 128) * 4)

__global__ __launch_bounds__(256, 1) void flash_tf32(
    const float* __restrict__ Q, const float* __restrict__ KV, float* __restrict__ O)
{
    extern __shared__ float sm[];
    float* Qs = sm + FA_Q_OFF;
    float* Ks = sm + FA_K_OFF;
    float* Vs = sm + FA_V_OFF;
    float* Ps = sm + FA_P_OFF;
    float* Mrow = sm + FA_M_OFF;
    float* Lrow = Mrow + 128;
    float* Crow = Lrow + 128;
    const uint32_t* Qu = (const uint32_t*)Qs;
    const uint32_t* Ku = (const uint32_t*)Ks;
    const uint32_t* Vu = (const uint32_t*)Vs;
    const uint32_t* Pu = (const uint32_t*)Ps;

    const int qt = blockIdx.x, h = blockIdx.y, b = blockIdx.z;
    const int tid = threadIdx.x, lane = tid & 31, w = tid >> 5;
    const int g = lane >> 2, tig = lane & 3;
    const int wm = (w & 3) * 32;
    const int wns = (w >> 2) * 32;
    const int wno = (w >> 2) * 64;
    const size_t qbase = (size_t)b * TSEQ + qt * 128;
    const int dq = lane * 4;

#pragma unroll
    for (int i = 0; i < 16; i++) {
        int m = w + i * 8;
        float4 v = *(const float4*)(Q + (qbase + m) * 2048 + h * 128 + dq);
        *(float4*)&Qs[m * QS_STRIDE + dq] = tf4(v);
    }
    if (tid < 128) { Mrow[tid] = -1e30f; Lrow[tid] = 0.f; }

    float o[2][8][4];
#pragma unroll
    for (int mt = 0; mt < 2; mt++)
#pragma unroll
        for (int nt = 0; nt < 8; nt++)
#pragma unroll
            for (int r = 0; r < 4; r++) o[mt][nt][r] = 0.f;

    const int nkt = 2 * qt + 2;
    for (int kt = 0; kt < nkt; kt++) {
        __syncthreads();
        const size_t kbase = (size_t)b * TSEQ + kt * 64;
#pragma unroll
        for (int i = 0; i < 8; i++) {
            int n = w + i * 8;
            float4 vk = *(const float4*)(KV + (kbase + n) * 4096 + h * 128 + dq);
            *(float4*)&Ks[n * KS_STRIDE + dq] = tf4(vk);
            float4 vv = *(const float4*)(KV + (kbase + n) * 4096 + 2048 + h * 128 + dq);
            *(float4*)&Vs[n * VS_STRIDE + dq] = tf4(vv);
        }
        __syncthreads();

        float s[2][4][4];
#pragma unroll
        for (int mt = 0; mt < 2; mt++)
#pragma unroll
            for (int nt = 0; nt < 4; nt++)
#pragma unroll
                for (int r = 0; r < 4; r++) s[mt][nt][r] = 0.f;
#pragma unroll
        for (int d0 = 0; d0 < 128; d0 += 8) {
            uint32_t af[2][4], bf[4][2];
#pragma unroll
            for (int mt = 0; mt < 2; mt++) {
                int m0 = wm + mt * 16;
                af[mt][0] = Qu[(m0 + g) * QS_STRIDE + d0 + tig];
                af[mt][1] = Qu[(m0 + g + 8) * QS_STRIDE + d0 + tig];
                af[mt][2] = Qu[(m0 + g) * QS_STRIDE + d0 + tig + 4];
                af[mt][3] = Qu[(m0 + g + 8) * QS_STRIDE + d0 + tig + 4];
            }
#pragma unroll
            for (int nt = 0; nt < 4; nt++) {
                int n0 = wns + nt * 8;
                bf[nt][0] = Ku[(n0 + g) * KS_STRIDE + d0 + tig];
                bf[nt][1] = Ku[(n0 + g) * KS_STRIDE + d0 + tig + 4];
            }
#pragma unroll
            for (int mt = 0; mt < 2; mt++)
#pragma unroll
                for (int nt = 0; nt < 4; nt++)
                    mma8(s[mt][nt], af[mt], bf[nt]);
        }
#pragma unroll
        for (int mt = 0; mt < 2; mt++) {
            int r0 = wm + mt * 16 + g;
            int qg0 = qt * 128 + r0, qg1 = qg0 + 8;
#pragma unroll
            for (int nt = 0; nt < 4; nt++) {
                int c0 = wns + nt * 8 + 2 * tig;
                int kg0 = kt * 64 + c0, kg1 = kg0 + 1;
                float v00 = (kg0 <= qg0) ? s[mt][nt][0] * QK_SCALE : -1e30f;
                float v01 = (kg1 <= qg0) ? s[mt][nt][1] * QK_SCALE : -1e30f;
                float v10 = (kg0 <= qg1) ? s[mt][nt][2] * QK_SCALE : -1e30f;
                float v11 = (kg1 <= qg1) ? s[mt][nt][3] * QK_SCALE : -1e30f;
                *(float2*)&Ps[r0 * PS_STRIDE + c0]       = make_float2(v00, v01);
                *(float2*)&Ps[(r0 + 8) * PS_STRIDE + c0] = make_float2(v10, v11);
            }
        }
        __syncthreads();

        {
            int row = tid >> 1, half = tid & 1;
            float* pr = Ps + row * PS_STRIDE + half * 32;
            float mx = -1e30f;
#pragma unroll 8
            for (int j = 0; j < 32; j++) mx = fmaxf(mx, pr[j]);
            mx = fmaxf(mx, __shfl_xor_sync(0xffffffff, mx, 1));
            float mOld = Mrow[row];
            float mnew = fmaxf(mOld, mx);
            float l = 0.f;
#pragma unroll 8
            for (int j = 0; j < 32; j++) {
                float p = f2tf(__expf(pr[j] - mnew));
                pr[j] = p;
                l += p;
            }
            l += __shfl_xor_sync(0xffffffff, l, 1);
            if (half == 0) {
                float c = __expf(mOld - mnew);
                Mrow[row] = mnew;
                Lrow[row] = Lrow[row] * c + l;
                Crow[row] = c;
            }
        }
        __syncthreads();

#pragma unroll
        for (int mt = 0; mt < 2; mt++) {
            float c0 = Crow[wm + mt * 16 + g];
            float c1 = Crow[wm + mt * 16 + g + 8];
#pragma unroll
            for (int nt = 0; nt < 8; nt++) {
                o[mt][nt][0] *= c0; o[mt][nt][1] *= c0;
                o[mt][nt][2] *= c1; o[mt][nt][3] *= c1;
            }
        }
#pragma unroll
        for (int ks = 0; ks < 8; ks++) {
            const int k0 = ks * 8;
            uint32_t af[2][4], bf[8][2];
#pragma unroll
            for (int mt = 0; mt < 2; mt++) {
                int m0 = wm + mt * 16;
                af[mt][0] = Pu[(m0 + g) * PS_STRIDE + k0 + tig];
                af[mt][1] = Pu[(m0 + g + 8) * PS_STRIDE + k0 + tig];
                af[mt][2] = Pu[(m0 + g) * PS_STRIDE + k0 + tig + 4];
                af[mt][3] = Pu[(m0 + g + 8) * PS_STRIDE + k0 + tig + 4];
            }
#pragma unroll
            for (int nt = 0; nt < 8; nt++) {
                int n0 = wno + nt * 8;
                bf[nt][0] = Vu[(k0 + tig) * VS_STRIDE + n0 + g];
                bf[nt][1] = Vu[(k0 + tig + 4) * VS_STRIDE + n0 + g];
            }
#pragma unroll
            for (int mt = 0; mt < 2; mt++)
#pragma unroll
                for (int nt = 0; nt < 8; nt++)
                    mma8(o[mt][nt], af[mt], bf[nt]);
        }
    }

    __syncthreads();
#pragma unroll
    for (int mt = 0; mt < 2; mt++) {
        int r0 = wm + mt * 16 + g;
        float inv0 = 1.f / Lrow[r0];
        float inv1 = 1.f / Lrow[r0 + 8];
#pragma unroll
        for (int nt = 0; nt < 8; nt++) {
            int c0 = wno + nt * 8 + 2 * tig;
            *(float2*)(O + (qbase + r0) * 2048 + h * 128 + c0) =
                make_float2(o[mt][nt][0] * inv0, o[mt][nt][1] * inv0);
            *(float2*)(O + (qbase + r0 + 8) * 2048 + h * 128 + c0) =
                make_float2(o[mt][nt][2] * inv1, o[mt][nt][3] * inv1);
        }
    }
}

// ---------------- launcher -------------------------------------------------
extern "C" void kernel_launch(void* const* d_in, const int* in_sizes, int n_in,
                              void* d_out, int out_size)
{
    const float* x     = (const float*)d_in[0];
    const float* cosT  = (const float*)d_in[1];
    const float* sinT  = (const float*)d_in[2];
    const float* Wq_s  = (const float*)d_in[3];
    const float* qs_w  = (const float*)d_in[4];
    const float* Wkv_s = (const float*)d_in[5];
    const float* kvs_w = (const float*)d_in[6];
    const float* Wq_p  = (const float*)d_in[7];
    const float* Wkv_p = (const float*)d_in[8];
    const float* Wg_p  = (const float*)d_in[9];
    const float* Wo_p  = (const float*)d_in[10];
    const float* o_w   = (const float*)d_in[11];
    const float* Wo_s  = (const float*)d_in[12];
    float* out = (float*)d_out;

    float *qs, *kvs, *q, *kv, *gates, *attn, *o;
    cudaGetSymbolAddress((void**)&qs,    g_qs);
    cudaGetSymbolAddress((void**)&kvs,   g_kvs);
    cudaGetSymbolAddress((void**)&q,     g_q);
    cudaGetSymbolAddress((void**)&kv,    g_kv);
    cudaGetSymbolAddress((void**)&gates, g_gates);
    cudaGetSymbolAddress((void**)&attn,  g_attn);
    cudaGetSymbolAddress((void**)&o,     g_o);

    cudaFuncSetAttribute(flash_tf32, cudaFuncAttributeMaxDynamicSharedMemorySize,
                         FA_SMEM_BYTES);
    cudaFuncSetAttribute(gemm_v2, cudaFuncAttributeMaxDynamicSharedMemorySize,
                         G2_SMEM_BYTES);

    dim3 blk(256);
    gemm_v2<<<dim3(D_CQ / BN,  NTOK / BM), blk, G2_SMEM_BYTES>>>(x, Wq_s,  qs,  D_CQ,  HIDD);
    rms_rows<<<NTOK, 256>>>(qs, qs_w, D_CQ);
    gemm_v2<<<dim3(D_CKV / BN, NTOK / BM), blk, G2_SMEM_BYTES>>>(x, Wkv_s, kvs, D_CKV, HIDD);
    rms_rows<<<NTOK, 256>>>(kvs, kvs_w, D_CKV);

    gemm_v2<<<dim3(2048 / BN, NTOK / BM), blk, G2_SMEM_BYTES>>>(qs,  Wq_p,  q,     2048, D_CQ);
    gemm_v2<<<dim3(4096 / BN, NTOK / BM), blk, G2_SMEM_BYTES>>>(kvs, Wkv_p, kv,    4096, D_CKV);
    gemm_v2<<<dim3(2048 / BN, NTOK / BM), blk, G2_SMEM_BYTES>>>(x,   Wg_p,  gates, 2048, HIDD);

    rope_kernel<<<NTOK, 256>>>(q,  cosT, sinT, 2048);
    rope_kernel<<<NTOK, 256>>>(kv, cosT, sinT, 4096);
    gate_v_kernel<<<(NTOK * 2048) / 256, 256>>>(kv, gates);

    flash_tf32<<<dim3(TSEQ / 128, NH, 2), blk, FA_SMEM_BYTES>>>(q, kv, attn);

    gemm_v2<<<dim3(D_CO / BN, NTOK / BM), blk, G2_SMEM_BYTES>>>(attn, Wo_p, o, D_CO, 2048);
    rms_rows<<<NTOK, 256>>>(o, o_w, D_CO);
    gemm_v2<<<dim3(HIDD / BN, NTOK / BM), blk, G2_SMEM_BYTES>>>(o, Wo_s, out, HIDD, D_CO);
}

// round 6
// speedup vs baseline: 2.5893x; 1.0343x over previous
#include <cuda_runtime.h>
#include <math.h>
#include <stdint.h>

// ---------------- problem constants ----------------
#define NTOK 4096      // B*T
#define TSEQ 2048
#define HIDD 2048
#define NH   16
#define DHEAD 128
#define RROT 32
#define D_CQ 768
#define D_CKV 512
#define D_CO 512
#define QK_SCALE 0.08838834764831845f  // 128^-0.5

// ---------------- scratch ----------------
__device__ float g_qs[(size_t)NTOK * D_CQ];
__device__ float g_kvs[(size_t)NTOK * D_CKV];
__device__ float g_q[(size_t)NTOK * 2048];
__device__ float g_kv[(size_t)NTOK * 4096];     // k | v
__device__ float g_gates[(size_t)NTOK * 2048];
__device__ float g_attn[(size_t)NTOK * 2048];
__device__ float g_o[(size_t)NTOK * D_CO];

// ---------------- helpers ----------------
__device__ __forceinline__ float f2tf(float x) {
    float r;
    asm("cvt.rna.tf32.f32 %0, %1;" : "=f"(r) : "f"(x));
    return r;
}
__device__ __forceinline__ float4 tf4(float4 v) {
    return make_float4(f2tf(v.x), f2tf(v.y), f2tf(v.z), f2tf(v.w));
}
__device__ __forceinline__ uint32_t smem_u32(const void* p) {
    uint32_t a;
    asm("{ .reg .u64 t; cvta.to.shared.u64 t, %1; cvt.u32.u64 %0, t; }" : "=r"(a) : "l"(p));
    return a;
}
__device__ __forceinline__ void mma8(float c[4], const uint32_t a[4], const uint32_t b[2]) {
    asm volatile(
        "mma.sync.aligned.m16n8k8.row.col.f32.tf32.tf32.f32 "
        "{%0,%1,%2,%3},{%4,%5,%6,%7},{%8,%9},{%0,%1,%2,%3};"
        : "+f"(c[0]), "+f"(c[1]), "+f"(c[2]), "+f"(c[3])
        : "r"(a[0]), "r"(a[1]), "r"(a[2]), "r"(a[3]), "r"(b[0]), "r"(b[1]));
}
__device__ __forceinline__ void cpa16(uint32_t saddr, const void* g) {
    asm volatile("cp.async.cg.shared.global [%0], [%1], 16;" :: "r"(saddr), "l"(g));
}
#define CPA_COMMIT() asm volatile("cp.async.commit_group;" ::: "memory")
#define CPA_WAIT(n)  asm volatile("cp.async.wait_group %0;" :: "n"(n) : "memory")

// ---------------- tf32 GEMM v3: C[M,N] = A[M,K] @ B[N,K]^T -----------------
// 256x128 block tile, BK=16, 256 threads; warp tile 64x64 (4m x 2n grid).
// cp.async 3-stage pipeline; raw fp32 staged, cvt.rna on fragment load.
#define BM 256
#define BN 128
#define AST 20                   // smem row stride: frag banks 20g+tig bijective
#define ABUF (BM * AST)          // 5120 floats
#define BBUF (BN * AST)          // 2560 floats
#define STG  (ABUF + BBUF)       // 7680 floats / stage
#define G3_SMEM_BYTES (3 * STG * 4)   // 92160 B

__global__ __launch_bounds__(256) void gemm_v3(
    const float* __restrict__ A, const float* __restrict__ B, float* __restrict__ C,
    int N, int K)
{
    extern __shared__ float sh[];
    const uint32_t shb = smem_u32(sh);
    const int tid = threadIdx.x, lane = tid & 31, w = tid >> 5;
    const int g = lane >> 2, tig = lane & 3;
    const int wm = (w & 3) * 64, wn = (w >> 2) * 64;
    const int bm = blockIdx.y * BM, bn = blockIdx.x * BN;
    const int lrow = tid >> 2, lkq = (tid & 3) << 2;

    float acc[4][8][4];
#pragma unroll
    for (int mt = 0; mt < 4; mt++)
#pragma unroll
        for (int nt = 0; nt < 8; nt++)
#pragma unroll
            for (int r = 0; r < 4; r++) acc[mt][nt][r] = 0.f;

    const float* pa = A + (size_t)(bm + lrow) * K + lkq;
    const float* pb = B + (size_t)(bn + lrow) * K + lkq;

    const int ntile = K >> 4;

#define G3_ISSUE(t) do {                                                        \
        const int _s = (t) % 3;                                                 \
        const uint32_t _base = shb + _s * (STG * 4);                            \
        const float* _a = pa + (size_t)(t) * 16;                                \
        const float* _b = pb + (size_t)(t) * 16;                                \
        _Pragma("unroll")                                                       \
        for (int j = 0; j < 4; j++)                                             \
            cpa16(_base + (((lrow + 64 * j) * AST + lkq) << 2), _a + (size_t)j * 64 * K); \
        _Pragma("unroll")                                                       \
        for (int j = 0; j < 2; j++)                                             \
            cpa16(_base + ((ABUF + (lrow + 64 * j) * AST + lkq) << 2), _b + (size_t)j * 64 * K); \
        CPA_COMMIT();                                                           \
    } while (0)

    G3_ISSUE(0);
    G3_ISSUE(1);

    for (int i = 0; i < ntile; i++) {
        if (i < ntile - 1) { CPA_WAIT(1); } else { CPA_WAIT(0); }
        __syncthreads();
        if (i + 2 < ntile) G3_ISSUE(i + 2);

        const float* Ac = sh + (i % 3) * STG;
        const float* Bc = Ac + ABUF;
#pragma unroll
        for (int ks = 0; ks < 2; ks++) {
            const int kb = ks * 8;
            uint32_t af[4][4], bf[8][2];
#pragma unroll
            for (int mt = 0; mt < 4; mt++) {
                int m0 = wm + mt * 16;
                af[mt][0] = __float_as_uint(f2tf(Ac[(m0 + g) * AST + kb + tig]));
                af[mt][1] = __float_as_uint(f2tf(Ac[(m0 + g + 8) * AST + kb + tig]));
                af[mt][2] = __float_as_uint(f2tf(Ac[(m0 + g) * AST + kb + tig + 4]));
                af[mt][3] = __float_as_uint(f2tf(Ac[(m0 + g + 8) * AST + kb + tig + 4]));
            }
#pragma unroll
            for (int nt = 0; nt < 8; nt++) {
                int n0 = wn + nt * 8;
                bf[nt][0] = __float_as_uint(f2tf(Bc[(n0 + g) * AST + kb + tig]));
                bf[nt][1] = __float_as_uint(f2tf(Bc[(n0 + g) * AST + kb + tig + 4]));
            }
#pragma unroll
            for (int mt = 0; mt < 4; mt++)
#pragma unroll
                for (int nt = 0; nt < 8; nt++)
                    mma8(acc[mt][nt], af[mt], bf[nt]);
        }
        __syncthreads();
    }

#pragma unroll
    for (int mt = 0; mt < 4; mt++) {
        int r0 = bm + wm + mt * 16 + g;
#pragma unroll
        for (int nt = 0; nt < 8; nt++) {
            int c0 = bn + wn + nt * 8 + 2 * tig;
            *(float2*)(C + (size_t)r0 * N + c0)       = make_float2(acc[mt][nt][0], acc[mt][nt][1]);
            *(float2*)(C + (size_t)(r0 + 8) * N + c0) = make_float2(acc[mt][nt][2], acc[mt][nt][3]);
        }
    }
}

// ---------------- RMSNorm rows in place (shfl reduction) -------------------
__global__ void rms_rows(float* __restrict__ X, const float* __restrict__ w, int D)
{
    __shared__ float red[8];
    const int row = blockIdx.x, tid = threadIdx.x;
    const int lane = tid & 31, wid = tid >> 5;
    float* x = X + (size_t)row * D;
    float ss = 0.f;
    for (int i = tid; i < D; i += 256) { float v = x[i]; ss += v * v; }
#pragma unroll
    for (int m = 16; m > 0; m >>= 1) ss += __shfl_xor_sync(0xffffffff, ss, m);
    if (lane == 0) red[wid] = ss;
    __syncthreads();
    float tot = 0.f;
#pragma unroll
    for (int j = 0; j < 8; j++) tot += red[j];
    float inv = rsqrtf(tot / (float)D + 1e-6f);
    for (int i = tid; i < D; i += 256) x[i] = w[i] * (x[i] * inv);
}

// ---------------- RoPE ----------------
__global__ void rope_kernel(float* __restrict__ X, const float* __restrict__ cosT,
                            const float* __restrict__ sinT, int rowStride)
{
    const int token = blockIdx.x;
    const int t = token & (TSEQ - 1);
    const int h = threadIdx.x >> 4;
    const int d = threadIdx.x & 15;
    float* p = X + (size_t)token * rowStride + h * DHEAD;
    float c0 = cosT[t * RROT + d],      s0 = sinT[t * RROT + d];
    float c1 = cosT[t * RROT + 16 + d], s1 = sinT[t * RROT + 16 + d];
    float x0 = p[d], x1 = p[d + 16];
    p[d]      = x0 * c0 - x1 * s0;
    p[d + 16] = x1 * c1 + x0 * s1;
}

// ---------------- v *= silu(gate) ----------------
__global__ void gate_v_kernel(float* __restrict__ kv, const float* __restrict__ gates)
{
    size_t idx = (size_t)blockIdx.x * 256 + threadIdx.x;
    size_t token = idx >> 11;
    int c = (int)(idx & 2047);
    float g = gates[idx];
    float sg = g / (1.f + __expf(-g));
    kv[token * 4096 + 2048 + c] *= sg;
}

// ---------------- flash attention, tf32, fragment softmax ------------------
// 128 q x 64 k tiles, 256 threads; S warp tile 32x32, PV warp tile 32x64.
#define QS_STRIDE 132
#define KS_STRIDE 132
#define VS_STRIDE 136
#define PS_STRIDE 68
#define FA_Q_OFF 0
#define FA_K_OFF (FA_Q_OFF + 128 * QS_STRIDE)
#define FA_V_OFF (FA_K_OFF + 64 * KS_STRIDE)
#define FA_P_OFF (FA_V_OFF + 64 * VS_STRIDE)
#define FA_M_OFF (FA_P_OFF + 128 * PS_STRIDE)
// Mrow 128 | Lrow 128 | pmax 2*128 | psum 2*128
#define FA_SMEM_BYTES ((FA_M_OFF + 128 + 128 + 256 + 256) * 4)

__global__ __launch_bounds__(256, 1) void flash_tf32(
    const float* __restrict__ Q, const float* __restrict__ KV, float* __restrict__ O)
{
    extern __shared__ float sm[];
    float* Qs = sm + FA_Q_OFF;
    float* Ks = sm + FA_K_OFF;
    float* Vs = sm + FA_V_OFF;
    float* Ps = sm + FA_P_OFF;
    float* Mrow = sm + FA_M_OFF;
    float* Lrow = Mrow + 128;
    float* pmax = Lrow + 128;    // [2][128]
    float* psum = pmax + 256;    // [2][128]
    const uint32_t* Qu = (const uint32_t*)Qs;
    const uint32_t* Ku = (const uint32_t*)Ks;
    const uint32_t* Vu = (const uint32_t*)Vs;
    const uint32_t* Pu = (const uint32_t*)Ps;

    const int qt = (int)gridDim.x - 1 - blockIdx.x;   // LPT: heavy blocks first
    const int h = blockIdx.y, b = blockIdx.z;
    const int tid = threadIdx.x, lane = tid & 31, w = tid >> 5;
    const int g = lane >> 2, tig = lane & 3;
    const int wm = (w & 3) * 32;
    const int wc = w >> 2;               // warp column (0/1)
    const int wns = wc * 32;
    const int wno = wc * 64;
    const size_t qbase = (size_t)b * TSEQ + qt * 128;
    const int dq = lane * 4;

#pragma unroll
    for (int i = 0; i < 16; i++) {
        int m = w + i * 8;
        float4 v = *(const float4*)(Q + (qbase + m) * 2048 + h * 128 + dq);
        *(float4*)&Qs[m * QS_STRIDE + dq] = tf4(v);
    }
    if (tid < 128) { Mrow[tid] = -1e30f; Lrow[tid] = 0.f; }

    float o[2][8][4];
#pragma unroll
    for (int mt = 0; mt < 2; mt++)
#pragma unroll
        for (int nt = 0; nt < 8; nt++)
#pragma unroll
            for (int r = 0; r < 4; r++) o[mt][nt][r] = 0.f;

    const int nkt = 2 * qt + 2;
    for (int kt = 0; kt < nkt; kt++) {
        __syncthreads();   // prev PV done; stats updated
        const size_t kbase = (size_t)b * TSEQ + kt * 64;
#pragma unroll
        for (int i = 0; i < 8; i++) {
            int n = w + i * 8;
            float4 vk = *(const float4*)(KV + (kbase + n) * 4096 + h * 128 + dq);
            *(float4*)&Ks[n * KS_STRIDE + dq] = tf4(vk);
            float4 vv = *(const float4*)(KV + (kbase + n) * 4096 + 2048 + h * 128 + dq);
            *(float4*)&Vs[n * VS_STRIDE + dq] = tf4(vv);
        }
        __syncthreads();

        // ---- S = Q K^T (warp 32x32) ----
        float s[2][4][4];
#pragma unroll
        for (int mt = 0; mt < 2; mt++)
#pragma unroll
            for (int nt = 0; nt < 4; nt++)
#pragma unroll
                for (int r = 0; r < 4; r++) s[mt][nt][r] = 0.f;
#pragma unroll
        for (int d0 = 0; d0 < 128; d0 += 8) {
            uint32_t af[2][4], bf[4][2];
#pragma unroll
            for (int mt = 0; mt < 2; mt++) {
                int m0 = wm + mt * 16;
                af[mt][0] = Qu[(m0 + g) * QS_STRIDE + d0 + tig];
                af[mt][1] = Qu[(m0 + g + 8) * QS_STRIDE + d0 + tig];
                af[mt][2] = Qu[(m0 + g) * QS_STRIDE + d0 + tig + 4];
                af[mt][3] = Qu[(m0 + g + 8) * QS_STRIDE + d0 + tig + 4];
            }
#pragma unroll
            for (int nt = 0; nt < 4; nt++) {
                int n0 = wns + nt * 8;
                bf[nt][0] = Ku[(n0 + g) * KS_STRIDE + d0 + tig];
                bf[nt][1] = Ku[(n0 + g) * KS_STRIDE + d0 + tig + 4];
            }
#pragma unroll
            for (int mt = 0; mt < 2; mt++)
#pragma unroll
                for (int nt = 0; nt < 4; nt++)
                    mma8(s[mt][nt], af[mt], bf[nt]);
        }

        // ---- mask + scale in regs, warp-level row max ----
        float rmx[2][2] = {{-1e30f, -1e30f}, {-1e30f, -1e30f}};
#pragma unroll
        for (int mt = 0; mt < 2; mt++) {
            int qg0 = qt * 128 + wm + mt * 16 + g, qg1 = qg0 + 8;
#pragma unroll
            for (int nt = 0; nt < 4; nt++) {
                int c0 = wns + nt * 8 + 2 * tig;
                int kg0 = kt * 64 + c0, kg1 = kg0 + 1;
                s[mt][nt][0] = (kg0 <= qg0) ? s[mt][nt][0] * QK_SCALE : -1e30f;
                s[mt][nt][1] = (kg1 <= qg0) ? s[mt][nt][1] * QK_SCALE : -1e30f;
                s[mt][nt][2] = (kg0 <= qg1) ? s[mt][nt][2] * QK_SCALE : -1e30f;
                s[mt][nt][3] = (kg1 <= qg1) ? s[mt][nt][3] * QK_SCALE : -1e30f;
                rmx[mt][0] = fmaxf(rmx[mt][0], fmaxf(s[mt][nt][0], s[mt][nt][1]));
                rmx[mt][1] = fmaxf(rmx[mt][1], fmaxf(s[mt][nt][2], s[mt][nt][3]));
            }
#pragma unroll
            for (int hh = 0; hh < 2; hh++) {
                rmx[mt][hh] = fmaxf(rmx[mt][hh], __shfl_xor_sync(0xffffffff, rmx[mt][hh], 1));
                rmx[mt][hh] = fmaxf(rmx[mt][hh], __shfl_xor_sync(0xffffffff, rmx[mt][hh], 2));
            }
            if (tig == 0) {
                pmax[wc * 128 + wm + mt * 16 + g]     = rmx[mt][0];
                pmax[wc * 128 + wm + mt * 16 + g + 8] = rmx[mt][1];
            }
        }
        __syncthreads();

        // ---- combine maxes, exp in regs, row sums, write P ----
        float mnew[2][2], cc[2][2], rsum[2][2];
#pragma unroll
        for (int mt = 0; mt < 2; mt++)
#pragma unroll
            for (int hh = 0; hh < 2; hh++) {
                int row = wm + mt * 16 + g + 8 * hh;
                float mold = Mrow[row];
                float mn = fmaxf(mold, fmaxf(pmax[row], pmax[128 + row]));
                mnew[mt][hh] = mn;
                cc[mt][hh] = __expf(mold - mn);
                rsum[mt][hh] = 0.f;
            }
#pragma unroll
        for (int mt = 0; mt < 2; mt++) {
            int r0 = wm + mt * 16 + g;
#pragma unroll
            for (int nt = 0; nt < 4; nt++) {
                int c0 = wns + nt * 8 + 2 * tig;
                float p0 = f2tf(__expf(s[mt][nt][0] - mnew[mt][0]));
                float p1 = f2tf(__expf(s[mt][nt][1] - mnew[mt][0]));
                float p2 = f2tf(__expf(s[mt][nt][2] - mnew[mt][1]));
                float p3 = f2tf(__expf(s[mt][nt][3] - mnew[mt][1]));
                rsum[mt][0] += p0 + p1;
                rsum[mt][1] += p2 + p3;
                *(float2*)&Ps[r0 * PS_STRIDE + c0]       = make_float2(p0, p1);
                *(float2*)&Ps[(r0 + 8) * PS_STRIDE + c0] = make_float2(p2, p3);
            }
#pragma unroll
            for (int hh = 0; hh < 2; hh++) {
                rsum[mt][hh] += __shfl_xor_sync(0xffffffff, rsum[mt][hh], 1);
                rsum[mt][hh] += __shfl_xor_sync(0xffffffff, rsum[mt][hh], 2);
            }
            if (tig == 0) {
                psum[wc * 128 + r0]     = rsum[mt][0];
                psum[wc * 128 + r0 + 8] = rsum[mt][1];
            }
        }
        __syncthreads();

        // ---- stats update (one writer per row), rescale O, PV mma ----
        if (wc == 0 && tig == 0) {
#pragma unroll
            for (int mt = 0; mt < 2; mt++)
#pragma unroll
                for (int hh = 0; hh < 2; hh++) {
                    int row = wm + mt * 16 + g + 8 * hh;
                    Lrow[row] = Lrow[row] * cc[mt][hh] + psum[row] + psum[128 + row];
                    Mrow[row] = mnew[mt][hh];
                }
        }
#pragma unroll
        for (int mt = 0; mt < 2; mt++)
#pragma unroll
            for (int nt = 0; nt < 8; nt++) {
                o[mt][nt][0] *= cc[mt][0]; o[mt][nt][1] *= cc[mt][0];
                o[mt][nt][2] *= cc[mt][1]; o[mt][nt][3] *= cc[mt][1];
            }
#pragma unroll
        for (int ks = 0; ks < 8; ks++) {
            const int k0 = ks * 8;
            uint32_t af[2][4], bf[8][2];
#pragma unroll
            for (int mt = 0; mt < 2; mt++) {
                int m0 = wm + mt * 16;
                af[mt][0] = Pu[(m0 + g) * PS_STRIDE + k0 + tig];
                af[mt][1] = Pu[(m0 + g + 8) * PS_STRIDE + k0 + tig];
                af[mt][2] = Pu[(m0 + g) * PS_STRIDE + k0 + tig + 4];
                af[mt][3] = Pu[(m0 + g + 8) * PS_STRIDE + k0 + tig + 4];
            }
#pragma unroll
            for (int nt = 0; nt < 8; nt++) {
                int n0 = wno + nt * 8;
                bf[nt][0] = Vu[(k0 + tig) * VS_STRIDE + n0 + g];
                bf[nt][1] = Vu[(k0 + tig + 4) * VS_STRIDE + n0 + g];
            }
#pragma unroll
            for (int mt = 0; mt < 2; mt++)
#pragma unroll
                for (int nt = 0; nt < 8; nt++)
                    mma8(o[mt][nt], af[mt], bf[nt]);
        }
    }

    __syncthreads();
#pragma unroll
    for (int mt = 0; mt < 2; mt++) {
        int r0 = wm + mt * 16 + g;
        float inv0 = 1.f / Lrow[r0];
        float inv1 = 1.f / Lrow[r0 + 8];
#pragma unroll
        for (int nt = 0; nt < 8; nt++) {
            int c0 = wno + nt * 8 + 2 * tig;
            *(float2*)(O + (qbase + r0) * 2048 + h * 128 + c0) =
                make_float2(o[mt][nt][0] * inv0, o[mt][nt][1] * inv0);
            *(float2*)(O + (qbase + r0 + 8) * 2048 + h * 128 + c0) =
                make_float2(o[mt][nt][2] * inv1, o[mt][nt][3] * inv1);
        }
    }
}

// ---------------- launcher -------------------------------------------------
extern "C" void kernel_launch(void* const* d_in, const int* in_sizes, int n_in,
                              void* d_out, int out_size)
{
    const float* x     = (const float*)d_in[0];
    const float* cosT  = (const float*)d_in[1];
    const float* sinT  = (const float*)d_in[2];
    const float* Wq_s  = (const float*)d_in[3];
    const float* qs_w  = (const float*)d_in[4];
    const float* Wkv_s = (const float*)d_in[5];
    const float* kvs_w = (const float*)d_in[6];
    const float* Wq_p  = (const float*)d_in[7];
    const float* Wkv_p = (const float*)d_in[8];
    const float* Wg_p  = (const float*)d_in[9];
    const float* Wo_p  = (const float*)d_in[10];
    const float* o_w   = (const float*)d_in[11];
    const float* Wo_s  = (const float*)d_in[12];
    float* out = (float*)d_out;

    float *qs, *kvs, *q, *kv, *gates, *attn, *o;
    cudaGetSymbolAddress((void**)&qs,    g_qs);
    cudaGetSymbolAddress((void**)&kvs,   g_kvs);
    cudaGetSymbolAddress((void**)&q,     g_q);
    cudaGetSymbolAddress((void**)&kv,    g_kv);
    cudaGetSymbolAddress((void**)&gates, g_gates);
    cudaGetSymbolAddress((void**)&attn,  g_attn);
    cudaGetSymbolAddress((void**)&o,     g_o);

    cudaFuncSetAttribute(flash_tf32, cudaFuncAttributeMaxDynamicSharedMemorySize,
                         FA_SMEM_BYTES);
    cudaFuncSetAttribute(gemm_v3, cudaFuncAttributeMaxDynamicSharedMemorySize,
                         G3_SMEM_BYTES);

    dim3 blk(256);
    gemm_v3<<<dim3(D_CQ / BN,  NTOK / BM), blk, G3_SMEM_BYTES>>>(x, Wq_s,  qs,  D_CQ,  HIDD);
    rms_rows<<<NTOK, 256>>>(qs, qs_w, D_CQ);
    gemm_v3<<<dim3(D_CKV / BN, NTOK / BM), blk, G3_SMEM_BYTES>>>(x, Wkv_s, kvs, D_CKV, HIDD);
    rms_rows<<<NTOK, 256>>>(kvs, kvs_w, D_CKV);

    gemm_v3<<<dim3(2048 / BN, NTOK / BM), blk, G3_SMEM_BYTES>>>(qs,  Wq_p,  q,     2048, D_CQ);
    gemm_v3<<<dim3(4096 / BN, NTOK / BM), blk, G3_SMEM_BYTES>>>(kvs, Wkv_p, kv,    4096, D_CKV);
    gemm_v3<<<dim3(2048 / BN, NTOK / BM), blk, G3_SMEM_BYTES>>>(x,   Wg_p,  gates, 2048, HIDD);

    rope_kernel<<<NTOK, 256>>>(q,  cosT, sinT, 2048);
    rope_kernel<<<NTOK, 256>>>(kv, cosT, sinT, 4096);
    gate_v_kernel<<<(NTOK * 2048) / 256, 256>>>(kv, gates);

    flash_tf32<<<dim3(TSEQ / 128, NH, 2), blk, FA_SMEM_BYTES>>>(q, kv, attn);

    gemm_v3<<<dim3(D_CO / BN, NTOK / BM), blk, G3_SMEM_BYTES>>>(attn, Wo_p, o, D_CO, 2048);
    rms_rows<<<NTOK, 256>>>(o, o_w, D_CO);
    gemm_v3<<<dim3(HIDD / BN, NTOK / BM), blk, G3_SMEM_BYTES>>>(o, Wo_s, out, HIDD, D_CO);
}

// round 8
// speedup vs baseline: 4.2642x; 1.6468x over previous
#include <cuda_runtime.h>
#include <cuda_fp16.h>
#include <math.h>
#include <stdint.h>

// ---------------- problem constants ----------------
#define NTOK 4096      // B*T
#define TSEQ 2048
#define HIDD 2048
#define NH   16
#define DHEAD 128
#define RROT 32
#define D_CQ 768
#define D_CKV 512
#define D_CO 512
#define QK_SCALE 0.08838834764831845f  // 128^-0.5

// ---------------- scratch ----------------
__device__ float g_qs[(size_t)NTOK * D_CQ];
__device__ float g_kvs[(size_t)NTOK * D_CKV];
__device__ float g_q[(size_t)NTOK * 2048];
__device__ float g_kv[(size_t)NTOK * 4096];     // k | v
__device__ float g_gates[(size_t)NTOK * 2048];
__device__ float g_o[(size_t)NTOK * D_CO];
// half-precision copies / outputs
__device__ __half g_xh[(size_t)NTOK * HIDD];
__device__ __half g_qsh[(size_t)NTOK * D_CQ];
__device__ __half g_kvsh[(size_t)NTOK * D_CKV];
__device__ __half g_attnh[(size_t)NTOK * 2048];
__device__ __half g_oh[(size_t)NTOK * D_CO];
__device__ __half g_wqs_h[(size_t)D_CQ * HIDD];
__device__ __half g_wkvs_h[(size_t)D_CKV * HIDD];
__device__ __half g_wqp_h[(size_t)2048 * D_CQ];
__device__ __half g_wkvp_h[(size_t)4096 * D_CKV];
__device__ __half g_wgp_h[(size_t)2048 * HIDD];
__device__ __half g_wop_h[(size_t)D_CO * 2048];
__device__ __half g_wos_h[(size_t)HIDD * D_CO];

// ---------------- helpers ----------------
__device__ __forceinline__ float f2tf(float x) {
    float r;
    asm("cvt.rna.tf32.f32 %0, %1;" : "=f"(r) : "f"(x));
    return r;
}
__device__ __forceinline__ float4 tf4(float4 v) {
    return make_float4(f2tf(v.x), f2tf(v.y), f2tf(v.z), f2tf(v.w));
}
__device__ __forceinline__ uint32_t smem_u32(const void* p) {
    uint32_t a;
    asm("{ .reg .u64 t; cvta.to.shared.u64 t, %1; cvt.u32.u64 %0, t; }" : "=r"(a) : "l"(p));
    return a;
}
__device__ __forceinline__ void mma8(float c[4], const uint32_t a[4], const uint32_t b[2]) {
    asm volatile(
        "mma.sync.aligned.m16n8k8.row.col.f32.tf32.tf32.f32 "
        "{%0,%1,%2,%3},{%4,%5,%6,%7},{%8,%9},{%0,%1,%2,%3};"
        : "+f"(c[0]), "+f"(c[1]), "+f"(c[2]), "+f"(c[3])
        : "r"(a[0]), "r"(a[1]), "r"(a[2]), "r"(a[3]), "r"(b[0]), "r"(b[1]));
}
__device__ __forceinline__ void mma16(float c[4], const uint32_t a[4], uint32_t b0, uint32_t b1) {
    asm volatile(
        "mma.sync.aligned.m16n8k16.row.col.f32.f16.f16.f32 "
        "{%0,%1,%2,%3},{%4,%5,%6,%7},{%8,%9},{%0,%1,%2,%3};"
        : "+f"(c[0]), "+f"(c[1]), "+f"(c[2]), "+f"(c[3])
        : "r"(a[0]), "r"(a[1]), "r"(a[2]), "r"(a[3]), "r"(b0), "r"(b1));
}
__device__ __forceinline__ void ldsm4(uint32_t* r, uint32_t a) {
    asm volatile("ldmatrix.sync.aligned.m8n8.x4.shared.b16 {%0,%1,%2,%3}, [%4];"
        : "=r"(r[0]), "=r"(r[1]), "=r"(r[2]), "=r"(r[3]) : "r"(a));
}
__device__ __forceinline__ void cpa16(uint32_t saddr, const void* g) {
    asm volatile("cp.async.cg.shared.global [%0], [%1], 16;" :: "r"(saddr), "l"(g));
}
#define CPA_COMMIT() asm volatile("cp.async.commit_group;" ::: "memory")
#define CPA_WAIT(n)  asm volatile("cp.async.wait_group %0;" :: "n"(n) : "memory")

// ---------------- fp32 -> fp16 convert ----------------
__global__ void cvt_f2h(const float* __restrict__ s, __half* __restrict__ d, int n)
{
    int i = (blockIdx.x * 256 + threadIdx.x) * 4;
    if (i < n) {
        float4 v = *(const float4*)(s + i);
        __half2* o = (__half2*)(d + i);
        o[0] = __floats2half2_rn(v.x, v.y);
        o[1] = __floats2half2_rn(v.z, v.w);
    }
}

// ---------------- fp16 GEMM: C[M,N] = A[M,K] @ B[N,K]^T --------------------
// 128x128 tile, BK=32, 256 threads; warp grid 4m x 2n, warp tile 32x64.
// cp.async 3-stage on half data; ldmatrix (non-trans: K-major smem) fragment
// loads; XOR-swizzled smem: row = 32 half = 4 chunks of 16B, chunk c of row r
// stored at column ((c + (r>>1)) & 3).
#define GH_SMEM_BYTES (3 * 16384)

__global__ __launch_bounds__(256, 2) void gemm_h(
    const __half* __restrict__ A, const __half* __restrict__ B, float* __restrict__ C,
    int N, int K)
{
    extern __shared__ char hsm[];
    const uint32_t shb = smem_u32(hsm);
    const int tid = threadIdx.x, lane = tid & 31, w = tid >> 5;
    const int g = lane >> 2, tig = lane & 3;
    const int wm = (w & 3) * 32, wn = (w >> 2) * 64;
    const int bm = blockIdx.y * 128, bn = blockIdx.x * 128;
    const int lr = lane & 15, lc = lane >> 4;   // ldmatrix lane -> (row, chunk-col)

    float acc[2][8][4];
#pragma unroll
    for (int mt = 0; mt < 2; mt++)
#pragma unroll
        for (int nt = 0; nt < 8; nt++)
#pragma unroll
            for (int r = 0; r < 4; r++) acc[mt][nt][r] = 0.f;

    const int srow = tid >> 1, shalf = tid & 1;
    const __half* pa = A + (size_t)(bm + srow) * K + shalf * 16;
    const __half* pb = B + (size_t)(bn + srow) * K + shalf * 16;
    const uint32_t da0 = srow * 64 + ((((shalf * 2 + 0) + (srow >> 1)) & 3) << 4);
    const uint32_t da1 = srow * 64 + ((((shalf * 2 + 1) + (srow >> 1)) & 3) << 4);

    const int ntile = K >> 5;
#define GH_ISSUE(t) do {                                       \
        uint32_t _b = shb + ((t) % 3) * 16384;                 \
        const __half* _a = pa + (size_t)(t) * 32;              \
        const __half* _bb = pb + (size_t)(t) * 32;             \
        cpa16(_b + da0, _a);                                   \
        cpa16(_b + da1, _a + 8);                               \
        cpa16(_b + 8192 + da0, _bb);                           \
        cpa16(_b + 8192 + da1, _bb + 8);                       \
        CPA_COMMIT();                                          \
    } while (0)

    GH_ISSUE(0);
    GH_ISSUE(1);

    for (int i = 0; i < ntile; i++) {
        if (i < ntile - 1) { CPA_WAIT(1); } else { CPA_WAIT(0); }
        __syncthreads();
        if (i + 2 < ntile) GH_ISSUE(i + 2);
        const uint32_t base = shb + (i % 3) * 16384;
#pragma unroll
        for (int ks = 0; ks < 2; ks++) {
            const int cb = 2 * ks + lc;
            uint32_t af[2][4], bf[4][4];
#pragma unroll
            for (int mt = 0; mt < 2; mt++) {
                int r = wm + mt * 16 + lr;
                ldsm4(af[mt], base + r * 64 + (((cb + (r >> 1)) & 3) << 4));
            }
#pragma unroll
            for (int p = 0; p < 4; p++) {
                int r = wn + p * 16 + lr;
                ldsm4(bf[p], base + 8192 + r * 64 + (((cb + (r >> 1)) & 3) << 4));
            }
#pragma unroll
            for (int mt = 0; mt < 2; mt++)
#pragma unroll
                for (int nt = 0; nt < 8; nt++) {
                    int p = nt >> 1, s = nt & 1;
                    mma16(acc[mt][nt], af[mt], bf[p][s], bf[p][s + 2]);
                }
        }
        __syncthreads();
    }

#pragma unroll
    for (int mt = 0; mt < 2; mt++) {
        int r0 = bm + wm + mt * 16 + g;
#pragma unroll
        for (int nt = 0; nt < 8; nt++) {
            int c0 = bn + wn + nt * 8 + 2 * tig;
            *(float2*)(C + (size_t)r0 * N + c0)       = make_float2(acc[mt][nt][0], acc[mt][nt][1]);
            *(float2*)(C + (size_t)(r0 + 8) * N + c0) = make_float2(acc[mt][nt][2], acc[mt][nt][3]);
        }
    }
}

// ---------------- RMSNorm rows in place, optional half copy ---------------
__global__ void rms_rows(float* __restrict__ X, const float* __restrict__ w, int D,
                         __half* __restrict__ H)
{
    __shared__ float red[8];
    const int row = blockIdx.x, tid = threadIdx.x;
    const int lane = tid & 31, wid = tid >> 5;
    float* x = X + (size_t)row * D;
    __half* hh = H ? H + (size_t)row * D : (__half*)0;
    float ss = 0.f;
    for (int i = tid; i < D; i += 256) { float v = x[i]; ss += v * v; }
#pragma unroll
    for (int m = 16; m > 0; m >>= 1) ss += __shfl_xor_sync(0xffffffff, ss, m);
    if (lane == 0) red[wid] = ss;
    __syncthreads();
    float tot = 0.f;
#pragma unroll
    for (int j = 0; j < 8; j++) tot += red[j];
    float inv = rsqrtf(tot / (float)D + 1e-6f);
    for (int i = tid; i < D; i += 256) {
        float r = w[i] * (x[i] * inv);
        x[i] = r;
        if (hh) hh[i] = __float2half_rn(r);
    }
}

// ---------------- RoPE ----------------
__global__ void rope_kernel(float* __restrict__ X, const float* __restrict__ cosT,
                            const float* __restrict__ sinT, int rowStride)
{
    const int token = blockIdx.x;
    const int t = token & (TSEQ - 1);
    const int h = threadIdx.x >> 4;
    const int d = threadIdx.x & 15;
    float* p = X + (size_t)token * rowStride + h * DHEAD;
    float c0 = cosT[t * RROT + d],      s0 = sinT[t * RROT + d];
    float c1 = cosT[t * RROT + 16 + d], s1 = sinT[t * RROT + 16 + d];
    float x0 = p[d], x1 = p[d + 16];
    p[d]      = x0 * c0 - x1 * s0;
    p[d + 16] = x1 * c1 + x0 * s1;
}

// ---------------- v *= silu(gate) ----------------
__global__ void gate_v_kernel(float* __restrict__ kv, const float* __restrict__ gates)
{
    size_t idx = (size_t)blockIdx.x * 256 + threadIdx.x;
    size_t token = idx >> 11;
    int c = (int)(idx & 2047);
    float g = gates[idx];
    float sg = g / (1.f + __expf(-g));
    kv[token * 4096 + 2048 + c] *= sg;
}

// ---------------- flash attention, tf32, fragment softmax (verified R6) ---
// Output written directly as fp16 (consumed only by the Wo_p gemm).
#define QS_STRIDE 132
#define KS_STRIDE 132
#define VS_STRIDE 136
#define PS_STRIDE 68
#define FA_Q_OFF 0
#define FA_K_OFF (FA_Q_OFF + 128 * QS_STRIDE)
#define FA_V_OFF (FA_K_OFF + 64 * KS_STRIDE)
#define FA_P_OFF (FA_V_OFF + 64 * VS_STRIDE)
#define FA_M_OFF (FA_P_OFF + 128 * PS_STRIDE)
#define FA_SMEM_BYTES ((FA_M_OFF + 128 + 128 + 256 + 256) * 4)

__global__ __launch_bounds__(256, 1) void flash_tf32(
    const float* __restrict__ Q, const float* __restrict__ KV, __half* __restrict__ O)
{
    extern __shared__ float sm[];
    float* Qs = sm + FA_Q_OFF;
    float* Ks = sm + FA_K_OFF;
    float* Vs = sm + FA_V_OFF;
    float* Ps = sm + FA_P_OFF;
    float* Mrow = sm + FA_M_OFF;
    float* Lrow = Mrow + 128;
    float* pmax = Lrow + 128;
    float* psum = pmax + 256;
    const uint32_t* Qu = (const uint32_t*)Qs;
    const uint32_t* Ku = (const uint32_t*)Ks;
    const uint32_t* Vu = (const uint32_t*)Vs;
    const uint32_t* Pu = (const uint32_t*)Ps;

    const int qt = (int)gridDim.x - 1 - blockIdx.x;
    const int h = blockIdx.y, b = blockIdx.z;
    const int tid = threadIdx.x, lane = tid & 31, w = tid >> 5;
    const int g = lane >> 2, tig = lane & 3;
    const int wm = (w & 3) * 32;
    const int wc = w >> 2;
    const int wns = wc * 32;
    const int wno = wc * 64;
    const size_t qbase = (size_t)b * TSEQ + qt * 128;
    const int dq = lane * 4;

#pragma unroll
    for (int i = 0; i < 16; i++) {
        int m = w + i * 8;
        float4 v = *(const float4*)(Q + (qbase + m) * 2048 + h * 128 + dq);
        *(float4*)&Qs[m * QS_STRIDE + dq] = tf4(v);
    }
    if (tid < 128) { Mrow[tid] = -1e30f; Lrow[tid] = 0.f; }

    float o[2][8][4];
#pragma unroll
    for (int mt = 0; mt < 2; mt++)
#pragma unroll
        for (int nt = 0; nt < 8; nt++)
#pragma unroll
            for (int r = 0; r < 4; r++) o[mt][nt][r] = 0.f;

    const int nkt = 2 * qt + 2;
    for (int kt = 0; kt < nkt; kt++) {
        __syncthreads();
        const size_t kbase = (size_t)b * TSEQ + kt * 64;
#pragma unroll
        for (int i = 0; i < 8; i++) {
            int n = w + i * 8;
            float4 vk = *(const float4*)(KV + (kbase + n) * 4096 + h * 128 + dq);
            *(float4*)&Ks[n * KS_STRIDE + dq] = tf4(vk);
            float4 vv = *(const float4*)(KV + (kbase + n) * 4096 + 2048 + h * 128 + dq);
            *(float4*)&Vs[n * VS_STRIDE + dq] = tf4(vv);
        }
        __syncthreads();

        float s[2][4][4];
#pragma unroll
        for (int mt = 0; mt < 2; mt++)
#pragma unroll
            for (int nt = 0; nt < 4; nt++)
#pragma unroll
                for (int r = 0; r < 4; r++) s[mt][nt][r] = 0.f;
#pragma unroll
        for (int d0 = 0; d0 < 128; d0 += 8) {
            uint32_t af[2][4], bf[4][2];
#pragma unroll
            for (int mt = 0; mt < 2; mt++) {
                int m0 = wm + mt * 16;
                af[mt][0] = Qu[(m0 + g) * QS_STRIDE + d0 + tig];
                af[mt][1] = Qu[(m0 + g + 8) * QS_STRIDE + d0 + tig];
                af[mt][2] = Qu[(m0 + g) * QS_STRIDE + d0 + tig + 4];
                af[mt][3] = Qu[(m0 + g + 8) * QS_STRIDE + d0 + tig + 4];
            }
#pragma unroll
            for (int nt = 0; nt < 4; nt++) {
                int n0 = wns + nt * 8;
                bf[nt][0] = Ku[(n0 + g) * KS_STRIDE + d0 + tig];
                bf[nt][1] = Ku[(n0 + g) * KS_STRIDE + d0 + tig + 4];
            }
#pragma unroll
            for (int mt = 0; mt < 2; mt++)
#pragma unroll
                for (int nt = 0; nt < 4; nt++)
                    mma8(s[mt][nt], af[mt], bf[nt]);
        }

        float rmx[2][2] = {{-1e30f, -1e30f}, {-1e30f, -1e30f}};
#pragma unroll
        for (int mt = 0; mt < 2; mt++) {
            int qg0 = qt * 128 + wm + mt * 16 + g, qg1 = qg0 + 8;
#pragma unroll
            for (int nt = 0; nt < 4; nt++) {
                int c0 = wns + nt * 8 + 2 * tig;
                int kg0 = kt * 64 + c0, kg1 = kg0 + 1;
                s[mt][nt][0] = (kg0 <= qg0) ? s[mt][nt][0] * QK_SCALE : -1e30f;
                s[mt][nt][1] = (kg1 <= qg0) ? s[mt][nt][1] * QK_SCALE : -1e30f;
                s[mt][nt][2] = (kg0 <= qg1) ? s[mt][nt][2] * QK_SCALE : -1e30f;
                s[mt][nt][3] = (kg1 <= qg1) ? s[mt][nt][3] * QK_SCALE : -1e30f;
                rmx[mt][0] = fmaxf(rmx[mt][0], fmaxf(s[mt][nt][0], s[mt][nt][1]));
                rmx[mt][1] = fmaxf(rmx[mt][1], fmaxf(s[mt][nt][2], s[mt][nt][3]));
            }
#pragma unroll
            for (int hh = 0; hh < 2; hh++) {
                rmx[mt][hh] = fmaxf(rmx[mt][hh], __shfl_xor_sync(0xffffffff, rmx[mt][hh], 1));
                rmx[mt][hh] = fmaxf(rmx[mt][hh], __shfl_xor_sync(0xffffffff, rmx[mt][hh], 2));
            }
            if (tig == 0) {
                pmax[wc * 128 + wm + mt * 16 + g]     = rmx[mt][0];
                pmax[wc * 128 + wm + mt * 16 + g + 8] = rmx[mt][1];
            }
        }
        __syncthreads();

        float mnew[2][2], cc[2][2], rsum[2][2];
#pragma unroll
        for (int mt = 0; mt < 2; mt++)
#pragma unroll
            for (int hh = 0; hh < 2; hh++) {
                int row = wm + mt * 16 + g + 8 * hh;
                float mold = Mrow[row];
                float mn = fmaxf(mold, fmaxf(pmax[row], pmax[128 + row]));
                mnew[mt][hh] = mn;
                cc[mt][hh] = __expf(mold - mn);
                rsum[mt][hh] = 0.f;
            }
#pragma unroll
        for (int mt = 0; mt < 2; mt++) {
            int r0 = wm + mt * 16 + g;
#pragma unroll
            for (int nt = 0; nt < 4; nt++) {
                int c0 = wns + nt * 8 + 2 * tig;
                float p0 = f2tf(__expf(s[mt][nt][0] - mnew[mt][0]));
                float p1 = f2tf(__expf(s[mt][nt][1] - mnew[mt][0]));
                float p2 = f2tf(__expf(s[mt][nt][2] - mnew[mt][1]));
                float p3 = f2tf(__expf(s[mt][nt][3] - mnew[mt][1]));
                rsum[mt][0] += p0 + p1;
                rsum[mt][1] += p2 + p3;
                *(float2*)&Ps[r0 * PS_STRIDE + c0]       = make_float2(p0, p1);
                *(float2*)&Ps[(r0 + 8) * PS_STRIDE + c0] = make_float2(p2, p3);
            }
#pragma unroll
            for (int hh = 0; hh < 2; hh++) {
                rsum[mt][hh] += __shfl_xor_sync(0xffffffff, rsum[mt][hh], 1);
                rsum[mt][hh] += __shfl_xor_sync(0xffffffff, rsum[mt][hh], 2);
            }
            if (tig == 0) {
                psum[wc * 128 + r0]     = rsum[mt][0];
                psum[wc * 128 + r0 + 8] = rsum[mt][1];
            }
        }
        __syncthreads();

        if (wc == 0 && tig == 0) {
#pragma unroll
            for (int mt = 0; mt < 2; mt++)
#pragma unroll
                for (int hh = 0; hh < 2; hh++) {
                    int row = wm + mt * 16 + g + 8 * hh;
                    Lrow[row] = Lrow[row] * cc[mt][hh] + psum[row] + psum[128 + row];
                    Mrow[row] = mnew[mt][hh];
                }
        }
#pragma unroll
        for (int mt = 0; mt < 2; mt++)
#pragma unroll
            for (int nt = 0; nt < 8; nt++) {
                o[mt][nt][0] *= cc[mt][0]; o[mt][nt][1] *= cc[mt][0];
                o[mt][nt][2] *= cc[mt][1]; o[mt][nt][3] *= cc[mt][1];
            }
#pragma unroll
        for (int ks = 0; ks < 8; ks++) {
            const int k0 = ks * 8;
            uint32_t af[2][4], bf[8][2];
#pragma unroll
            for (int mt = 0; mt < 2; mt++) {
                int m0 = wm + mt * 16;
                af[mt][0] = Pu[(m0 + g) * PS_STRIDE + k0 + tig];
                af[mt][1] = Pu[(m0 + g + 8) * PS_STRIDE + k0 + tig];
                af[mt][2] = Pu[(m0 + g) * PS_STRIDE + k0 + tig + 4];
                af[mt][3] = Pu[(m0 + g + 8) * PS_STRIDE + k0 + tig + 4];
            }
#pragma unroll
            for (int nt = 0; nt < 8; nt++) {
                int n0 = wno + nt * 8;
                bf[nt][0] = Vu[(k0 + tig) * VS_STRIDE + n0 + g];
                bf[nt][1] = Vu[(k0 + tig + 4) * VS_STRIDE + n0 + g];
            }
#pragma unroll
            for (int mt = 0; mt < 2; mt++)
#pragma unroll
                for (int nt = 0; nt < 8; nt++)
                    mma8(o[mt][nt], af[mt], bf[nt]);
        }
    }

    __syncthreads();
#pragma unroll
    for (int mt = 0; mt < 2; mt++) {
        int r0 = wm + mt * 16 + g;
        float inv0 = 1.f / Lrow[r0];
        float inv1 = 1.f / Lrow[r0 + 8];
#pragma unroll
        for (int nt = 0; nt < 8; nt++) {
            int c0 = wno + nt * 8 + 2 * tig;
            *(__half2*)(O + (qbase + r0) * 2048 + h * 128 + c0) =
                __floats2half2_rn(o[mt][nt][0] * inv0, o[mt][nt][1] * inv0);
            *(__half2*)(O + (qbase + r0 + 8) * 2048 + h * 128 + c0) =
                __floats2half2_rn(o[mt][nt][2] * inv1, o[mt][nt][3] * inv1);
        }
    }
}

// ---------------- launcher -------------------------------------------------
extern "C" void kernel_launch(void* const* d_in, const int* in_sizes, int n_in,
                              void* d_out, int out_size)
{
    const float* x     = (const float*)d_in[0];
    const float* cosT  = (const float*)d_in[1];
    const float* sinT  = (const float*)d_in[2];
    const float* Wq_s  = (const float*)d_in[3];
    const float* qs_w  = (const float*)d_in[4];
    const float* Wkv_s = (const float*)d_in[5];
    const float* kvs_w = (const float*)d_in[6];
    const float* Wq_p  = (const float*)d_in[7];
    const float* Wkv_p = (const float*)d_in[8];
    const float* Wg_p  = (const float*)d_in[9];
    const float* Wo_p  = (const float*)d_in[10];
    const float* o_w   = (const float*)d_in[11];
    const float* Wo_s  = (const float*)d_in[12];
    float* out = (float*)d_out;

    float *qs, *kvs, *q, *kv, *gates, *o;
    __half *xh, *qsh, *kvsh, *attnh, *oh;
    __half *wqs_h, *wkvs_h, *wqp_h, *wkvp_h, *wgp_h, *wop_h, *wos_h;
    cudaGetSymbolAddress((void**)&qs,    g_qs);
    cudaGetSymbolAddress((void**)&kvs,   g_kvs);
    cudaGetSymbolAddress((void**)&q,     g_q);
    cudaGetSymbolAddress((void**)&kv,    g_kv);
    cudaGetSymbolAddress((void**)&gates, g_gates);
    cudaGetSymbolAddress((void**)&o,     g_o);
    cudaGetSymbolAddress((void**)&xh,    g_xh);
    cudaGetSymbolAddress((void**)&qsh,   g_qsh);
    cudaGetSymbolAddress((void**)&kvsh,  g_kvsh);
    cudaGetSymbolAddress((void**)&attnh, g_attnh);
    cudaGetSymbolAddress((void**)&oh,    g_oh);
    cudaGetSymbolAddress((void**)&wqs_h,  g_wqs_h);
    cudaGetSymbolAddress((void**)&wkvs_h, g_wkvs_h);
    cudaGetSymbolAddress((void**)&wqp_h,  g_wqp_h);
    cudaGetSymbolAddress((void**)&wkvp_h, g_wkvp_h);
    cudaGetSymbolAddress((void**)&wgp_h,  g_wgp_h);
    cudaGetSymbolAddress((void**)&wop_h,  g_wop_h);
    cudaGetSymbolAddress((void**)&wos_h,  g_wos_h);

    cudaFuncSetAttribute(flash_tf32, cudaFuncAttributeMaxDynamicSharedMemorySize,
                         FA_SMEM_BYTES);
    cudaFuncSetAttribute(gemm_h, cudaFuncAttributeMaxDynamicSharedMemorySize,
                         GH_SMEM_BYTES);

    dim3 blk(256);
    // convert inputs/weights to fp16
    cvt_f2h<<<(NTOK * HIDD) / 1024, 256>>>(x, xh, NTOK * HIDD);
    cvt_f2h<<<(D_CQ * HIDD) / 1024, 256>>>(Wq_s, wqs_h, D_CQ * HIDD);
    cvt_f2h<<<(D_CKV * HIDD) / 1024, 256>>>(Wkv_s, wkvs_h, D_CKV * HIDD);
    cvt_f2h<<<(2048 * D_CQ) / 1024, 256>>>(Wq_p, wqp_h, 2048 * D_CQ);
    cvt_f2h<<<(4096 * D_CKV) / 1024, 256>>>(Wkv_p, wkvp_h, 4096 * D_CKV);
    cvt_f2h<<<(2048 * HIDD) / 1024, 256>>>(Wg_p, wgp_h, 2048 * HIDD);
    cvt_f2h<<<(D_CO * 2048) / 1024, 256>>>(Wo_p, wop_h, D_CO * 2048);
    cvt_f2h<<<(HIDD * D_CO) / 1024, 256>>>(Wo_s, wos_h, HIDD * D_CO);

    gemm_h<<<dim3(D_CQ / 128,  NTOK / 128), blk, GH_SMEM_BYTES>>>(xh, wqs_h, qs, D_CQ, HIDD);
    rms_rows<<<NTOK, 256>>>(qs, qs_w, D_CQ, qsh);
    gemm_h<<<dim3(D_CKV / 128, NTOK / 128), blk, GH_SMEM_BYTES>>>(xh, wkvs_h, kvs, D_CKV, HIDD);
    rms_rows<<<NTOK, 256>>>(kvs, kvs_w, D_CKV, kvsh);

    gemm_h<<<dim3(2048 / 128, NTOK / 128), blk, GH_SMEM_BYTES>>>(qsh,  wqp_h,  q,     2048, D_CQ);
    gemm_h<<<dim3(4096 / 128, NTOK / 128), blk, GH_SMEM_BYTES>>>(kvsh, wkvp_h, kv,    4096, D_CKV);
    gemm_h<<<dim3(2048 / 128, NTOK / 128), blk, GH_SMEM_BYTES>>>(xh,   wgp_h,  gates, 2048, HIDD);

    rope_kernel<<<NTOK, 256>>>(q,  cosT, sinT, 2048);
    rope_kernel<<<NTOK, 256>>>(kv, cosT, sinT, 4096);
    gate_v_kernel<<<(NTOK * 2048) / 256, 256>>>(kv, gates);

    flash_tf32<<<dim3(TSEQ / 128, NH, 2), blk, FA_SMEM_BYTES>>>(q, kv, attnh);

    gemm_h<<<dim3(D_CO / 128, NTOK / 128), blk, GH_SMEM_BYTES>>>(attnh, wop_h, o, D_CO, 2048);
    rms_rows<<<NTOK, 256>>>(o, o_w, D_CO, oh);
    gemm_h<<<dim3(HIDD / 128, NTOK / 128), blk, GH_SMEM_BYTES>>>(oh, wos_h, out, HIDD, D_CO);
}

// round 9
// speedup vs baseline: 4.8527x; 1.1380x over previous
#include <cuda_runtime.h>
#include <cuda_fp16.h>
#include <math.h>
#include <stdint.h>

// ---------------- problem constants ----------------
#define NTOK 4096      // B*T
#define TSEQ 2048
#define HIDD 2048
#define NH   16
#define DHEAD 128
#define RROT 32
#define D_CQ 768
#define D_CKV 512
#define D_CO 512
#define QK_SCALE 0.08838834764831845f  // 128^-0.5

// ---------------- scratch ----------------
__device__ float g_qs[(size_t)NTOK * D_CQ];
__device__ float g_kvs[(size_t)NTOK * D_CKV];
__device__ float g_q[(size_t)NTOK * 2048];
__device__ float g_kv[(size_t)NTOK * 4096];     // k | v
__device__ float g_gates[(size_t)NTOK * 2048];
__device__ float g_o[(size_t)NTOK * D_CO];
// half-precision copies / outputs
__device__ __half g_xh[(size_t)NTOK * HIDD];
__device__ __half g_qsh[(size_t)NTOK * D_CQ];
__device__ __half g_kvsh[(size_t)NTOK * D_CKV];
__device__ __half g_attnh[(size_t)NTOK * 2048];
__device__ __half g_oh[(size_t)NTOK * D_CO];
__device__ __half g_wqs_h[(size_t)D_CQ * HIDD];
__device__ __half g_wkvs_h[(size_t)D_CKV * HIDD];
__device__ __half g_wqp_h[(size_t)2048 * D_CQ];
__device__ __half g_wkvp_h[(size_t)4096 * D_CKV];
__device__ __half g_wgp_h[(size_t)2048 * HIDD];
__device__ __half g_wop_h[(size_t)D_CO * 2048];
__device__ __half g_wos_h[(size_t)HIDD * D_CO];

// ---------------- helpers ----------------
__device__ __forceinline__ uint32_t smem_u32(const void* p) {
    uint32_t a;
    asm("{ .reg .u64 t; cvta.to.shared.u64 t, %1; cvt.u32.u64 %0, t; }" : "=r"(a) : "l"(p));
    return a;
}
__device__ __forceinline__ void mma16(float c[4], const uint32_t a[4], uint32_t b0, uint32_t b1) {
    asm volatile(
        "mma.sync.aligned.m16n8k16.row.col.f32.f16.f16.f32 "
        "{%0,%1,%2,%3},{%4,%5,%6,%7},{%8,%9},{%0,%1,%2,%3};"
        : "+f"(c[0]), "+f"(c[1]), "+f"(c[2]), "+f"(c[3])
        : "r"(a[0]), "r"(a[1]), "r"(a[2]), "r"(a[3]), "r"(b0), "r"(b1));
}
__device__ __forceinline__ void ldsm4(uint32_t* r, uint32_t a) {
    asm volatile("ldmatrix.sync.aligned.m8n8.x4.shared.b16 {%0,%1,%2,%3}, [%4];"
        : "=r"(r[0]), "=r"(r[1]), "=r"(r[2]), "=r"(r[3]) : "r"(a));
}
__device__ __forceinline__ void ldsm4t(uint32_t* r, uint32_t a) {
    asm volatile("ldmatrix.sync.aligned.m8n8.x4.trans.shared.b16 {%0,%1,%2,%3}, [%4];"
        : "=r"(r[0]), "=r"(r[1]), "=r"(r[2]), "=r"(r[3]) : "r"(a));
}
__device__ __forceinline__ void cpa16(uint32_t saddr, const void* g) {
    asm volatile("cp.async.cg.shared.global [%0], [%1], 16;" :: "r"(saddr), "l"(g));
}
#define CPA_COMMIT() asm volatile("cp.async.commit_group;" ::: "memory")
#define CPA_WAIT(n)  asm volatile("cp.async.wait_group %0;" :: "n"(n) : "memory")
__device__ __forceinline__ uint32_t h2u(__half2 h) {
    uint32_t u;
    asm("mov.b32 %0, %1;" : "=r"(u) : "r"(*(uint32_t*)&h));
    return u;
}

// ---------------- fp32 -> fp16 convert ----------------
__global__ void cvt_f2h(const float* __restrict__ s, __half* __restrict__ d, int n)
{
    int i = (blockIdx.x * 256 + threadIdx.x) * 4;
    if (i < n) {
        float4 v = *(const float4*)(s + i);
        __half2* o = (__half2*)(d + i);
        o[0] = __floats2half2_rn(v.x, v.y);
        o[1] = __floats2half2_rn(v.z, v.w);
    }
}

// ---------------- fp16 GEMM: C[M,N] = A[M,K] @ B[N,K]^T (verified R8) -----
#define GH_SMEM_BYTES (3 * 16384)

__global__ __launch_bounds__(256, 2) void gemm_h(
    const __half* __restrict__ A, const __half* __restrict__ B, float* __restrict__ C,
    int N, int K)
{
    extern __shared__ char hsm[];
    const uint32_t shb = smem_u32(hsm);
    const int tid = threadIdx.x, lane = tid & 31, w = tid >> 5;
    const int g = lane >> 2, tig = lane & 3;
    const int wm = (w & 3) * 32, wn = (w >> 2) * 64;
    const int bm = blockIdx.y * 128, bn = blockIdx.x * 128;
    const int lr = lane & 15, lc = lane >> 4;

    float acc[2][8][4];
#pragma unroll
    for (int mt = 0; mt < 2; mt++)
#pragma unroll
        for (int nt = 0; nt < 8; nt++)
#pragma unroll
            for (int r = 0; r < 4; r++) acc[mt][nt][r] = 0.f;

    const int srow = tid >> 1, shalf = tid & 1;
    const __half* pa = A + (size_t)(bm + srow) * K + shalf * 16;
    const __half* pb = B + (size_t)(bn + srow) * K + shalf * 16;
    const uint32_t da0 = srow * 64 + ((((shalf * 2 + 0) + (srow >> 1)) & 3) << 4);
    const uint32_t da1 = srow * 64 + ((((shalf * 2 + 1) + (srow >> 1)) & 3) << 4);

    const int ntile = K >> 5;
#define GH_ISSUE(t) do {                                       \
        uint32_t _b = shb + ((t) % 3) * 16384;                 \
        const __half* _a = pa + (size_t)(t) * 32;              \
        const __half* _bb = pb + (size_t)(t) * 32;             \
        cpa16(_b + da0, _a);                                   \
        cpa16(_b + da1, _a + 8);                               \
        cpa16(_b + 8192 + da0, _bb);                           \
        cpa16(_b + 8192 + da1, _bb + 8);                       \
        CPA_COMMIT();                                          \
    } while (0)

    GH_ISSUE(0);
    GH_ISSUE(1);

    for (int i = 0; i < ntile; i++) {
        if (i < ntile - 1) { CPA_WAIT(1); } else { CPA_WAIT(0); }
        __syncthreads();
        if (i + 2 < ntile) GH_ISSUE(i + 2);
        const uint32_t base = shb + (i % 3) * 16384;
#pragma unroll
        for (int ks = 0; ks < 2; ks++) {
            const int cb = 2 * ks + lc;
            uint32_t af[2][4], bf[4][4];
#pragma unroll
            for (int mt = 0; mt < 2; mt++) {
                int r = wm + mt * 16 + lr;
                ldsm4(af[mt], base + r * 64 + (((cb + (r >> 1)) & 3) << 4));
            }
#pragma unroll
            for (int p = 0; p < 4; p++) {
                int r = wn + p * 16 + lr;
                ldsm4(bf[p], base + 8192 + r * 64 + (((cb + (r >> 1)) & 3) << 4));
            }
#pragma unroll
            for (int mt = 0; mt < 2; mt++)
#pragma unroll
                for (int nt = 0; nt < 8; nt++) {
                    int p = nt >> 1, s = nt & 1;
                    mma16(acc[mt][nt], af[mt], bf[p][s], bf[p][s + 2]);
                }
        }
        __syncthreads();
    }

#pragma unroll
    for (int mt = 0; mt < 2; mt++) {
        int r0 = bm + wm + mt * 16 + g;
#pragma unroll
        for (int nt = 0; nt < 8; nt++) {
            int c0 = bn + wn + nt * 8 + 2 * tig;
            *(float2*)(C + (size_t)r0 * N + c0)       = make_float2(acc[mt][nt][0], acc[mt][nt][1]);
            *(float2*)(C + (size_t)(r0 + 8) * N + c0) = make_float2(acc[mt][nt][2], acc[mt][nt][3]);
        }
    }
}

// ---------------- RMSNorm rows in place, optional half copy ---------------
__global__ void rms_rows(float* __restrict__ X, const float* __restrict__ w, int D,
                         __half* __restrict__ H)
{
    __shared__ float red[8];
    const int row = blockIdx.x, tid = threadIdx.x;
    const int lane = tid & 31, wid = tid >> 5;
    float* x = X + (size_t)row * D;
    __half* hh = H ? H + (size_t)row * D : (__half*)0;
    float ss = 0.f;
    for (int i = tid; i < D; i += 256) { float v = x[i]; ss += v * v; }
#pragma unroll
    for (int m = 16; m > 0; m >>= 1) ss += __shfl_xor_sync(0xffffffff, ss, m);
    if (lane == 0) red[wid] = ss;
    __syncthreads();
    float tot = 0.f;
#pragma unroll
    for (int j = 0; j < 8; j++) tot += red[j];
    float inv = rsqrtf(tot / (float)D + 1e-6f);
    for (int i = tid; i < D; i += 256) {
        float r = w[i] * (x[i] * inv);
        x[i] = r;
        if (hh) hh[i] = __float2half_rn(r);
    }
}

// ---------------- RoPE ----------------
__global__ void rope_kernel(float* __restrict__ X, const float* __restrict__ cosT,
                            const float* __restrict__ sinT, int rowStride)
{
    const int token = blockIdx.x;
    const int t = token & (TSEQ - 1);
    const int h = threadIdx.x >> 4;
    const int d = threadIdx.x & 15;
    float* p = X + (size_t)token * rowStride + h * DHEAD;
    float c0 = cosT[t * RROT + d],      s0 = sinT[t * RROT + d];
    float c1 = cosT[t * RROT + 16 + d], s1 = sinT[t * RROT + 16 + d];
    float x0 = p[d], x1 = p[d + 16];
    p[d]      = x0 * c0 - x1 * s0;
    p[d + 16] = x1 * c1 + x0 * s1;
}

// ---------------- v *= silu(gate) ----------------
__global__ void gate_v_kernel(float* __restrict__ kv, const float* __restrict__ gates)
{
    size_t idx = (size_t)blockIdx.x * 256 + threadIdx.x;
    size_t token = idx >> 11;
    int c = (int)(idx & 2047);
    float g = gates[idx];
    float sg = g / (1.f + __expf(-g));
    kv[token * 4096 + 2048 + c] *= sg;
}

// ---------------- flash attention, fp16 mma, register softmax -------------
// 128 q x 64 k tiles, 256 threads (8 warps); warp tile 16q x 64k.
// Each warp owns its 16 q rows exclusively: m/l state and P stay in registers.
// smem strides: 136 halves (272 B) -> ldmatrix phases conflict-free.
#define FH_ST 136
#define FH_Q_OFF 0
#define FH_K_OFF (128 * FH_ST)
#define FH_V_OFF (FH_K_OFF + 64 * FH_ST)
#define FH_SMEM_BYTES ((FH_V_OFF + 64 * FH_ST) * 2)

__global__ __launch_bounds__(256) void flash_h16(
    const float* __restrict__ Q, const float* __restrict__ KV, __half* __restrict__ O)
{
    extern __shared__ __half sh2[];
    __half* Qs = sh2 + FH_Q_OFF;
    __half* Ks = sh2 + FH_K_OFF;
    __half* Vs = sh2 + FH_V_OFF;
    const uint32_t qbs = smem_u32(Qs), kbs = smem_u32(Ks), vbs = smem_u32(Vs);

    const int qt = (int)gridDim.x - 1 - blockIdx.x;   // LPT: heavy blocks first
    const int h = blockIdx.y, b = blockIdx.z;
    const int tid = threadIdx.x, lane = tid & 31, w = tid >> 5;
    const int g = lane >> 2, tig = lane & 3;
    const int lr = lane & 15, lc = lane >> 4;
    const int qrow0 = w * 16;
    const size_t qbase = (size_t)b * TSEQ + qt * 128;

    // stage Q (pre-scaled by QK_SCALE) as half
#pragma unroll
    for (int i = 0; i < 8; i++) {
        int f = tid + i * 256;
        int r = f >> 4, c = f & 15;
        const float* src = Q + (qbase + r) * 2048 + h * 128 + c * 8;
        float4 v0 = *(const float4*)src;
        float4 v1 = *(const float4*)(src + 4);
        __half2* dst = (__half2*)(Qs + r * FH_ST + c * 8);
        dst[0] = __floats2half2_rn(v0.x * QK_SCALE, v0.y * QK_SCALE);
        dst[1] = __floats2half2_rn(v0.z * QK_SCALE, v0.w * QK_SCALE);
        dst[2] = __floats2half2_rn(v1.x * QK_SCALE, v1.y * QK_SCALE);
        dst[3] = __floats2half2_rn(v1.z * QK_SCALE, v1.w * QK_SCALE);
    }
    __syncthreads();

    // preload Q fragments (reused every tile)
    uint32_t qf[8][4];
#pragma unroll
    for (int kc = 0; kc < 8; kc++)
        ldsm4(qf[kc], qbs + (qrow0 + lr) * 272 + (2 * kc + lc) * 16);

    float m0 = -1e30f, m1 = -1e30f, l0 = 0.f, l1 = 0.f;
    float o[16][4];
#pragma unroll
    for (int nt = 0; nt < 16; nt++)
#pragma unroll
        for (int r = 0; r < 4; r++) o[nt][r] = 0.f;

    const int nkt = 2 * qt + 2;
    for (int kt = 0; kt < nkt; kt++) {
        __syncthreads();   // prior tile's ldsm reads done before restaging
        const size_t kbase = (size_t)b * TSEQ + kt * 64;
#pragma unroll
        for (int i = 0; i < 4; i++) {
            int f = tid + i * 256;
            int r = f >> 4, c = f & 15;
            const float* kp = KV + (kbase + r) * 4096 + h * 128 + c * 8;
            float4 a0 = *(const float4*)kp, a1 = *(const float4*)(kp + 4);
            __half2* kd = (__half2*)(Ks + r * FH_ST + c * 8);
            kd[0] = __floats2half2_rn(a0.x, a0.y);
            kd[1] = __floats2half2_rn(a0.z, a0.w);
            kd[2] = __floats2half2_rn(a1.x, a1.y);
            kd[3] = __floats2half2_rn(a1.z, a1.w);
            const float* vp = kp + 2048;
            float4 b0 = *(const float4*)vp, b1 = *(const float4*)(vp + 4);
            __half2* vd = (__half2*)(Vs + r * FH_ST + c * 8);
            vd[0] = __floats2half2_rn(b0.x, b0.y);
            vd[1] = __floats2half2_rn(b0.z, b0.w);
            vd[2] = __floats2half2_rn(b1.x, b1.y);
            vd[3] = __floats2half2_rn(b1.z, b1.w);
        }
        __syncthreads();

        // ---- S = Q K^T (warp 16q x 64k), fp16 k16 ----
        float s[8][4];
#pragma unroll
        for (int nt = 0; nt < 8; nt++)
#pragma unroll
            for (int r = 0; r < 4; r++) s[nt][r] = 0.f;
#pragma unroll
        for (int ks = 0; ks < 8; ks++) {
            uint32_t bf[4][4];
#pragma unroll
            for (int p = 0; p < 4; p++)
                ldsm4(bf[p], kbs + (p * 16 + lr) * 272 + (2 * ks + lc) * 16);
#pragma unroll
            for (int nt = 0; nt < 8; nt++) {
                int p = nt >> 1, ss = nt & 1;
                mma16(s[nt], qf[ks], bf[p][ss], bf[p][ss + 2]);
            }
        }

        // ---- mask + register softmax (rows qrow0+g, qrow0+g+8) ----
        const int qg0 = qt * 128 + qrow0 + g, qg1 = qg0 + 8;
        float mx0 = -1e30f, mx1 = -1e30f;
#pragma unroll
        for (int nt = 0; nt < 8; nt++) {
            int kg0 = kt * 64 + nt * 8 + 2 * tig, kg1 = kg0 + 1;
            if (kg0 > qg0) s[nt][0] = -1e30f;
            if (kg1 > qg0) s[nt][1] = -1e30f;
            if (kg0 > qg1) s[nt][2] = -1e30f;
            if (kg1 > qg1) s[nt][3] = -1e30f;
            mx0 = fmaxf(mx0, fmaxf(s[nt][0], s[nt][1]));
            mx1 = fmaxf(mx1, fmaxf(s[nt][2], s[nt][3]));
        }
        mx0 = fmaxf(mx0, __shfl_xor_sync(0xffffffffu, mx0, 1));
        mx0 = fmaxf(mx0, __shfl_xor_sync(0xffffffffu, mx0, 2));
        mx1 = fmaxf(mx1, __shfl_xor_sync(0xffffffffu, mx1, 1));
        mx1 = fmaxf(mx1, __shfl_xor_sync(0xffffffffu, mx1, 2));
        float nm0 = fmaxf(m0, mx0), nm1 = fmaxf(m1, mx1);
        float sc0 = __expf(m0 - nm0), sc1 = __expf(m1 - nm1);
        m0 = nm0; m1 = nm1;

        float sum0 = 0.f, sum1 = 0.f;
        uint32_t pa[8][2];
#pragma unroll
        for (int nt = 0; nt < 8; nt++) {
            float p0 = __expf(s[nt][0] - nm0), p1 = __expf(s[nt][1] - nm0);
            float p2 = __expf(s[nt][2] - nm1), p3 = __expf(s[nt][3] - nm1);
            sum0 += p0 + p1; sum1 += p2 + p3;
            pa[nt][0] = h2u(__floats2half2_rn(p0, p1));
            pa[nt][1] = h2u(__floats2half2_rn(p2, p3));
        }
        sum0 += __shfl_xor_sync(0xffffffffu, sum0, 1);
        sum0 += __shfl_xor_sync(0xffffffffu, sum0, 2);
        sum1 += __shfl_xor_sync(0xffffffffu, sum1, 1);
        sum1 += __shfl_xor_sync(0xffffffffu, sum1, 2);
        l0 = l0 * sc0 + sum0;
        l1 = l1 * sc1 + sum1;

        // ---- rescale O, then O += P @ V (P from registers, V via ldsm.T) --
#pragma unroll
        for (int nt = 0; nt < 16; nt++) {
            o[nt][0] *= sc0; o[nt][1] *= sc0;
            o[nt][2] *= sc1; o[nt][3] *= sc1;
        }
#pragma unroll
        for (int kc = 0; kc < 4; kc++) {
            uint32_t paf[4] = { pa[2 * kc][0], pa[2 * kc][1],
                                pa[2 * kc + 1][0], pa[2 * kc + 1][1] };
#pragma unroll
            for (int j = 0; j < 8; j++) {
                uint32_t bf[4];
                ldsm4t(bf, vbs + (kc * 16 + lr) * 272 + (2 * j + lc) * 16);
                mma16(o[2 * j],     paf, bf[0], bf[1]);
                mma16(o[2 * j + 1], paf, bf[2], bf[3]);
            }
        }
    }

    // epilogue: O /= l, write fp16
    float inv0 = 1.f / l0, inv1 = 1.f / l1;
#pragma unroll
    for (int nt = 0; nt < 16; nt++) {
        int c0 = nt * 8 + 2 * tig;
        *(__half2*)(O + (qbase + qrow0 + g) * 2048 + h * 128 + c0) =
            __floats2half2_rn(o[nt][0] * inv0, o[nt][1] * inv0);
        *(__half2*)(O + (qbase + qrow0 + g + 8) * 2048 + h * 128 + c0) =
            __floats2half2_rn(o[nt][2] * inv1, o[nt][3] * inv1);
    }
}

// ---------------- launcher -------------------------------------------------
extern "C" void kernel_launch(void* const* d_in, const int* in_sizes, int n_in,
                              void* d_out, int out_size)
{
    const float* x     = (const float*)d_in[0];
    const float* cosT  = (const float*)d_in[1];
    const float* sinT  = (const float*)d_in[2];
    const float* Wq_s  = (const float*)d_in[3];
    const float* qs_w  = (const float*)d_in[4];
    const float* Wkv_s = (const float*)d_in[5];
    const float* kvs_w = (const float*)d_in[6];
    const float* Wq_p  = (const float*)d_in[7];
    const float* Wkv_p = (const float*)d_in[8];
    const float* Wg_p  = (const float*)d_in[9];
    const float* Wo_p  = (const float*)d_in[10];
    const float* o_w   = (const float*)d_in[11];
    const float* Wo_s  = (const float*)d_in[12];
    float* out = (float*)d_out;

    float *qs, *kvs, *q, *kv, *gates, *o;
    __half *xh, *qsh, *kvsh, *attnh, *oh;
    __half *wqs_h, *wkvs_h, *wqp_h, *wkvp_h, *wgp_h, *wop_h, *wos_h;
    cudaGetSymbolAddress((void**)&qs,    g_qs);
    cudaGetSymbolAddress((void**)&kvs,   g_kvs);
    cudaGetSymbolAddress((void**)&q,     g_q);
    cudaGetSymbolAddress((void**)&kv,    g_kv);
    cudaGetSymbolAddress((void**)&gates, g_gates);
    cudaGetSymbolAddress((void**)&o,     g_o);
    cudaGetSymbolAddress((void**)&xh,    g_xh);
    cudaGetSymbolAddress((void**)&qsh,   g_qsh);
    cudaGetSymbolAddress((void**)&kvsh,  g_kvsh);
    cudaGetSymbolAddress((void**)&attnh, g_attnh);
    cudaGetSymbolAddress((void**)&oh,    g_oh);
    cudaGetSymbolAddress((void**)&wqs_h,  g_wqs_h);
    cudaGetSymbolAddress((void**)&wkvs_h, g_wkvs_h);
    cudaGetSymbolAddress((void**)&wqp_h,  g_wqp_h);
    cudaGetSymbolAddress((void**)&wkvp_h, g_wkvp_h);
    cudaGetSymbolAddress((void**)&wgp_h,  g_wgp_h);
    cudaGetSymbolAddress((void**)&wop_h,  g_wop_h);
    cudaGetSymbolAddress((void**)&wos_h,  g_wos_h);

    cudaFuncSetAttribute(flash_h16, cudaFuncAttributeMaxDynamicSharedMemorySize,
                         FH_SMEM_BYTES);
    cudaFuncSetAttribute(gemm_h, cudaFuncAttributeMaxDynamicSharedMemorySize,
                         GH_SMEM_BYTES);

    dim3 blk(256);
    // convert inputs/weights to fp16
    cvt_f2h<<<(NTOK * HIDD) / 1024, 256>>>(x, xh, NTOK * HIDD);
    cvt_f2h<<<(D_CQ * HIDD) / 1024, 256>>>(Wq_s, wqs_h, D_CQ * HIDD);
    cvt_f2h<<<(D_CKV * HIDD) / 1024, 256>>>(Wkv_s, wkvs_h, D_CKV * HIDD);
    cvt_f2h<<<(2048 * D_CQ) / 1024, 256>>>(Wq_p, wqp_h, 2048 * D_CQ);
    cvt_f2h<<<(4096 * D_CKV) / 1024, 256>>>(Wkv_p, wkvp_h, 4096 * D_CKV);
    cvt_f2h<<<(2048 * HIDD) / 1024, 256>>>(Wg_p, wgp_h, 2048 * HIDD);
    cvt_f2h<<<(D_CO * 2048) / 1024, 256>>>(Wo_p, wop_h, D_CO * 2048);
    cvt_f2h<<<(HIDD * D_CO) / 1024, 256>>>(Wo_s, wos_h, HIDD * D_CO);

    gemm_h<<<dim3(D_CQ / 128,  NTOK / 128), blk, GH_SMEM_BYTES>>>(xh, wqs_h, qs, D_CQ, HIDD);
    rms_rows<<<NTOK, 256>>>(qs, qs_w, D_CQ, qsh);
    gemm_h<<<dim3(D_CKV / 128, NTOK / 128), blk, GH_SMEM_BYTES>>>(xh, wkvs_h, kvs, D_CKV, HIDD);
    rms_rows<<<NTOK, 256>>>(kvs, kvs_w, D_CKV, kvsh);

    gemm_h<<<dim3(2048 / 128, NTOK / 128), blk, GH_SMEM_BYTES>>>(qsh,  wqp_h,  q,     2048, D_CQ);
    gemm_h<<<dim3(4096 / 128, NTOK / 128), blk, GH_SMEM_BYTES>>>(kvsh, wkvp_h, kv,    4096, D_CKV);
    gemm_h<<<dim3(2048 / 128, NTOK / 128), blk, GH_SMEM_BYTES>>>(xh,   wgp_h,  gates, 2048, HIDD);

    rope_kernel<<<NTOK, 256>>>(q,  cosT, sinT, 2048);
    rope_kernel<<<NTOK, 256>>>(kv, cosT, sinT, 4096);
    gate_v_kernel<<<(NTOK * 2048) / 256, 256>>>(kv, gates);

    flash_h16<<<dim3(TSEQ / 128, NH, 2), blk, FH_SMEM_BYTES>>>(q, kv, attnh);

    gemm_h<<<dim3(D_CO / 128, NTOK / 128), blk, GH_SMEM_BYTES>>>(attnh, wop_h, o, D_CO, 2048);
    rms_rows<<<NTOK, 256>>>(o, o_w, D_CO, oh);
    gemm_h<<<dim3(HIDD / 128, NTOK / 128), blk, GH_SMEM_BYTES>>>(oh, wos_h, out, HIDD, D_CO);
}

// round 10
// speedup vs baseline: 5.2398x; 1.0798x over previous
#include <cuda_runtime.h>
#include <cuda_fp16.h>
#include <math.h>
#include <stdint.h>

// ---------------- problem constants ----------------
#define NTOK 4096      // B*T
#define TSEQ 2048
#define HIDD 2048
#define NH   16
#define DHEAD 128
#define RROT 32
#define D_CQ 768
#define D_CKV 512
#define D_CO 512
#define QK_SCALE 0.08838834764831845f  // 128^-0.5

// ---------------- scratch ----------------
__device__ float g_qs[(size_t)NTOK * D_CQ];
__device__ float g_kvs[(size_t)NTOK * D_CKV];
__device__ float g_o[(size_t)NTOK * D_CO];
// fp16 activations
__device__ __half g_xh[(size_t)NTOK * HIDD];
__device__ __half g_qsh[(size_t)NTOK * D_CQ];
__device__ __half g_kvsh[(size_t)NTOK * D_CKV];
__device__ __half g_qh[(size_t)NTOK * 2048];
__device__ __half g_kvh[(size_t)NTOK * 4096];   // k | v
__device__ __half g_gatesh[(size_t)NTOK * 2048];
__device__ __half g_attnh[(size_t)NTOK * 2048];
__device__ __half g_oh[(size_t)NTOK * D_CO];
// fp16 weights
__device__ __half g_wqs_h[(size_t)D_CQ * HIDD];
__device__ __half g_wkvs_h[(size_t)D_CKV * HIDD];
__device__ __half g_wqp_h[(size_t)2048 * D_CQ];
__device__ __half g_wkvp_h[(size_t)4096 * D_CKV];
__device__ __half g_wgp_h[(size_t)2048 * HIDD];
__device__ __half g_wop_h[(size_t)D_CO * 2048];
__device__ __half g_wos_h[(size_t)HIDD * D_CO];

// ---------------- helpers ----------------
__device__ __forceinline__ uint32_t smem_u32(const void* p) {
    uint32_t a;
    asm("{ .reg .u64 t; cvta.to.shared.u64 t, %1; cvt.u32.u64 %0, t; }" : "=r"(a) : "l"(p));
    return a;
}
__device__ __forceinline__ void mma16(float c[4], const uint32_t a[4], uint32_t b0, uint32_t b1) {
    asm volatile(
        "mma.sync.aligned.m16n8k16.row.col.f32.f16.f16.f32 "
        "{%0,%1,%2,%3},{%4,%5,%6,%7},{%8,%9},{%0,%1,%2,%3};"
        : "+f"(c[0]), "+f"(c[1]), "+f"(c[2]), "+f"(c[3])
        : "r"(a[0]), "r"(a[1]), "r"(a[2]), "r"(a[3]), "r"(b0), "r"(b1));
}
__device__ __forceinline__ void ldsm4(uint32_t* r, uint32_t a) {
    asm volatile("ldmatrix.sync.aligned.m8n8.x4.shared.b16 {%0,%1,%2,%3}, [%4];"
        : "=r"(r[0]), "=r"(r[1]), "=r"(r[2]), "=r"(r[3]) : "r"(a));
}
__device__ __forceinline__ void ldsm4t(uint32_t* r, uint32_t a) {
    asm volatile("ldmatrix.sync.aligned.m8n8.x4.trans.shared.b16 {%0,%1,%2,%3}, [%4];"
        : "=r"(r[0]), "=r"(r[1]), "=r"(r[2]), "=r"(r[3]) : "r"(a));
}
__device__ __forceinline__ void cpa16(uint32_t saddr, const void* g) {
    asm volatile("cp.async.cg.shared.global [%0], [%1], 16;" :: "r"(saddr), "l"(g));
}
#define CPA_COMMIT() asm volatile("cp.async.commit_group;" ::: "memory")
#define CPA_WAIT(n)  asm volatile("cp.async.wait_group %0;" :: "n"(n) : "memory")
__device__ __forceinline__ uint32_t h2u(__half2 h) {
    uint32_t u;
    asm("mov.b32 %0, %1;" : "=r"(u) : "r"(*(uint32_t*)&h));
    return u;
}
__device__ __forceinline__ void store2(float* C, float a, float b)  { *(float2*)C = make_float2(a, b); }
__device__ __forceinline__ void store2(__half* C, float a, float b) { *(__half2*)C = __floats2half2_rn(a, b); }

// ---------------- fp32 -> fp16 convert ----------------
__global__ void cvt_f2h(const float* __restrict__ s, __half* __restrict__ d, int n)
{
    int i = (blockIdx.x * 256 + threadIdx.x) * 4;
    if (i < n) {
        float4 v = *(const float4*)(s + i);
        __half2* o = (__half2*)(d + i);
        o[0] = __floats2half2_rn(v.x, v.y);
        o[1] = __floats2half2_rn(v.z, v.w);
    }
}

// ---------------- fp16 GEMM: C[M,N] = A[M,K] @ B[N,K]^T (verified R8) -----
// Template output: fp32 or fp16 epilogue.
#define GH_SMEM_BYTES (3 * 16384)

template <typename TOUT>
__global__ __launch_bounds__(256, 2) void gemm_h(
    const __half* __restrict__ A, const __half* __restrict__ B, TOUT* __restrict__ C,
    int N, int K)
{
    extern __shared__ char hsm[];
    const uint32_t shb = smem_u32(hsm);
    const int tid = threadIdx.x, lane = tid & 31, w = tid >> 5;
    const int g = lane >> 2, tig = lane & 3;
    const int wm = (w & 3) * 32, wn = (w >> 2) * 64;
    const int bm = blockIdx.y * 128, bn = blockIdx.x * 128;
    const int lr = lane & 15, lc = lane >> 4;

    float acc[2][8][4];
#pragma unroll
    for (int mt = 0; mt < 2; mt++)
#pragma unroll
        for (int nt = 0; nt < 8; nt++)
#pragma unroll
            for (int r = 0; r < 4; r++) acc[mt][nt][r] = 0.f;

    const int srow = tid >> 1, shalf = tid & 1;
    const __half* pa = A + (size_t)(bm + srow) * K + shalf * 16;
    const __half* pb = B + (size_t)(bn + srow) * K + shalf * 16;
    const uint32_t da0 = srow * 64 + ((((shalf * 2 + 0) + (srow >> 1)) & 3) << 4);
    const uint32_t da1 = srow * 64 + ((((shalf * 2 + 1) + (srow >> 1)) & 3) << 4);

    const int ntile = K >> 5;
#define GH_ISSUE(t) do {                                       \
        uint32_t _b = shb + ((t) % 3) * 16384;                 \
        const __half* _a = pa + (size_t)(t) * 32;              \
        const __half* _bb = pb + (size_t)(t) * 32;             \
        cpa16(_b + da0, _a);                                   \
        cpa16(_b + da1, _a + 8);                               \
        cpa16(_b + 8192 + da0, _bb);                           \
        cpa16(_b + 8192 + da1, _bb + 8);                       \
        CPA_COMMIT();                                          \
    } while (0)

    GH_ISSUE(0);
    GH_ISSUE(1);

    for (int i = 0; i < ntile; i++) {
        if (i < ntile - 1) { CPA_WAIT(1); } else { CPA_WAIT(0); }
        __syncthreads();
        if (i + 2 < ntile) GH_ISSUE(i + 2);
        const uint32_t base = shb + (i % 3) * 16384;
#pragma unroll
        for (int ks = 0; ks < 2; ks++) {
            const int cb = 2 * ks + lc;
            uint32_t af[2][4], bf[4][4];
#pragma unroll
            for (int mt = 0; mt < 2; mt++) {
                int r = wm + mt * 16 + lr;
                ldsm4(af[mt], base + r * 64 + (((cb + (r >> 1)) & 3) << 4));
            }
#pragma unroll
            for (int p = 0; p < 4; p++) {
                int r = wn + p * 16 + lr;
                ldsm4(bf[p], base + 8192 + r * 64 + (((cb + (r >> 1)) & 3) << 4));
            }
#pragma unroll
            for (int mt = 0; mt < 2; mt++)
#pragma unroll
                for (int nt = 0; nt < 8; nt++) {
                    int p = nt >> 1, s = nt & 1;
                    mma16(acc[mt][nt], af[mt], bf[p][s], bf[p][s + 2]);
                }
        }
        __syncthreads();
    }

#pragma unroll
    for (int mt = 0; mt < 2; mt++) {
        int r0 = bm + wm + mt * 16 + g;
#pragma unroll
        for (int nt = 0; nt < 8; nt++) {
            int c0 = bn + wn + nt * 8 + 2 * tig;
            store2(C + (size_t)r0 * N + c0,       acc[mt][nt][0], acc[mt][nt][1]);
            store2(C + (size_t)(r0 + 8) * N + c0, acc[mt][nt][2], acc[mt][nt][3]);
        }
    }
}

// ---------------- RMSNorm rows in place, optional half copy ---------------
__global__ void rms_rows(float* __restrict__ X, const float* __restrict__ w, int D,
                         __half* __restrict__ H)
{
    __shared__ float red[8];
    const int row = blockIdx.x, tid = threadIdx.x;
    const int lane = tid & 31, wid = tid >> 5;
    float* x = X + (size_t)row * D;
    __half* hh = H ? H + (size_t)row * D : (__half*)0;
    float ss = 0.f;
    for (int i = tid; i < D; i += 256) { float v = x[i]; ss += v * v; }
#pragma unroll
    for (int m = 16; m > 0; m >>= 1) ss += __shfl_xor_sync(0xffffffff, ss, m);
    if (lane == 0) red[wid] = ss;
    __syncthreads();
    float tot = 0.f;
#pragma unroll
    for (int j = 0; j < 8; j++) tot += red[j];
    float inv = rsqrtf(tot / (float)D + 1e-6f);
    for (int i = tid; i < D; i += 256) {
        float r = w[i] * (x[i] * inv);
        x[i] = r;
        if (hh) hh[i] = __float2half_rn(r);
    }
}

// ---------------- RoPE on half data (fp32 internal) ----------------
__global__ void rope_h(__half* __restrict__ X, const float* __restrict__ cosT,
                       const float* __restrict__ sinT, int rowStride)
{
    const int token = blockIdx.x;
    const int t = token & (TSEQ - 1);
    const int h = threadIdx.x >> 4;
    const int d = threadIdx.x & 15;
    __half* p = X + (size_t)token * rowStride + h * DHEAD;
    float c0 = cosT[t * RROT + d],      s0 = sinT[t * RROT + d];
    float c1 = cosT[t * RROT + 16 + d], s1 = sinT[t * RROT + 16 + d];
    float x0 = __half2float(p[d]), x1 = __half2float(p[d + 16]);
    p[d]      = __float2half_rn(x0 * c0 - x1 * s0);
    p[d + 16] = __float2half_rn(x1 * c1 + x0 * s1);
}

// ---------------- v *= silu(gate), half data ----------------
__global__ void gate_v_h(__half* __restrict__ kv, const __half* __restrict__ gates)
{
    size_t idx = ((size_t)blockIdx.x * 256 + threadIdx.x) * 2;   // over NTOK*2048
    size_t token = idx >> 11;
    int c = (int)(idx & 2047);
    __half2 g2 = *(const __half2*)(gates + idx);
    float g0 = __low2float(g2), g1 = __high2float(g2);
    float s0 = g0 / (1.f + __expf(-g0));
    float s1 = g1 / (1.f + __expf(-g1));
    __half2* vp = (__half2*)(kv + token * 4096 + 2048 + c);
    __half2 v2 = *vp;
    *vp = __floats2half2_rn(__low2float(v2) * s0, __high2float(v2) * s1);
}

// ---------------- flash attention: fp16 storage, cp.async double-buffer ----
// 128 q x 64 k tiles, 256 threads (8 warps); warp tile 16q x 64k.
// Q staged once; K/V double-buffered via cp.async; register softmax.
// smem (halves, stride 136/row): Q[128] | K0 V0 | K1 V1
#define FH_QB 34816u               // Q bytes (128*136*2)
#define FH_KVB 17408u              // one K or V tile bytes (64*136*2)
#define FH_SMEM_BYTES (FH_QB + 4 * FH_KVB)   // 104448

__global__ __launch_bounds__(256) void flash_h16(
    const __half* __restrict__ Qh, const __half* __restrict__ KVh, __half* __restrict__ O)
{
    extern __shared__ __half sh2[];
    const uint32_t qbs = smem_u32(sh2);
    const uint32_t kvb0 = qbs + FH_QB;
    const uint32_t kvb1 = qbs + FH_QB + 2 * FH_KVB;

    const int qt = (int)gridDim.x - 1 - blockIdx.x;   // LPT
    const int h = blockIdx.y, b = blockIdx.z;
    const int tid = threadIdx.x, lane = tid & 31, w = tid >> 5;
    const int g = lane >> 2, tig = lane & 3;
    const int lr = lane & 15, lc = lane >> 4;
    const int qrow0 = w * 16;
    const size_t qbase = (size_t)b * TSEQ + qt * 128;
    const size_t kvrow = (size_t)b * TSEQ;

#define FH_KV_ISSUE(kt) do {                                                     \
        const uint32_t _kb = ((kt) & 1) ? kvb1 : kvb0;                           \
        const __half* _base = KVh + (kvrow + (size_t)(kt) * 64) * 4096 + h * 128;\
        _Pragma("unroll")                                                        \
        for (int _j = 0; _j < 4; _j++) {                                         \
            int _f = tid * 4 + _j;                                               \
            int _r = _f >> 4, _c = _f & 15;                                      \
            uint32_t _d = _r * 272 + _c * 16;                                    \
            cpa16(_kb + _d,          _base + (size_t)_r * 4096 + _c * 8);        \
            cpa16(_kb + FH_KVB + _d, _base + (size_t)_r * 4096 + 2048 + _c * 8); \
        }                                                                        \
        CPA_COMMIT();                                                            \
    } while (0)

    // stage Q (group 0) + first KV tile (group 1)
#pragma unroll
    for (int j = 0; j < 8; j++) {
        int f = tid * 8 + j;
        int r = f >> 4, c = f & 15;
        cpa16(qbs + r * 272 + c * 16, Qh + (qbase + r) * 2048 + h * 128 + c * 8);
    }
    CPA_COMMIT();
    FH_KV_ISSUE(0);
    CPA_WAIT(1);        // Q complete
    __syncthreads();

    // preload Q fragments (reused every tile)
    uint32_t qf[8][4];
#pragma unroll
    for (int kc = 0; kc < 8; kc++)
        ldsm4(qf[kc], qbs + (qrow0 + lr) * 272 + (2 * kc + lc) * 16);

    float m0 = -1e30f, m1 = -1e30f, l0 = 0.f, l1 = 0.f;
    float o[16][4];
#pragma unroll
    for (int nt = 0; nt < 16; nt++)
#pragma unroll
        for (int r = 0; r < 4; r++) o[nt][r] = 0.f;

    const int nkt = 2 * qt + 2;
    for (int kt = 0; kt < nkt; kt++) {
        if (kt + 1 < nkt) { FH_KV_ISSUE(kt + 1); CPA_WAIT(1); }
        else              { CPA_WAIT(0); }
        __syncthreads();
        const uint32_t kbs = (kt & 1) ? kvb1 : kvb0;
        const uint32_t vbs = kbs + FH_KVB;

        // ---- S = Q K^T (warp 16q x 64k), fp16 k16 ----
        float s[8][4];
#pragma unroll
        for (int nt = 0; nt < 8; nt++)
#pragma unroll
            for (int r = 0; r < 4; r++) s[nt][r] = 0.f;
#pragma unroll
        for (int ks = 0; ks < 8; ks++) {
            uint32_t bf[4][4];
#pragma unroll
            for (int p = 0; p < 4; p++)
                ldsm4(bf[p], kbs + (p * 16 + lr) * 272 + (2 * ks + lc) * 16);
#pragma unroll
            for (int nt = 0; nt < 8; nt++) {
                int p = nt >> 1, ss = nt & 1;
                mma16(s[nt], qf[ks], bf[p][ss], bf[p][ss + 2]);
            }
        }

        // ---- scale + mask + register softmax ----
        const int qg0 = qt * 128 + qrow0 + g, qg1 = qg0 + 8;
        float mx0 = -1e30f, mx1 = -1e30f;
#pragma unroll
        for (int nt = 0; nt < 8; nt++) {
            int kg0 = kt * 64 + nt * 8 + 2 * tig, kg1 = kg0 + 1;
            s[nt][0] = (kg0 <= qg0) ? s[nt][0] * QK_SCALE : -1e30f;
            s[nt][1] = (kg1 <= qg0) ? s[nt][1] * QK_SCALE : -1e30f;
            s[nt][2] = (kg0 <= qg1) ? s[nt][2] * QK_SCALE : -1e30f;
            s[nt][3] = (kg1 <= qg1) ? s[nt][3] * QK_SCALE : -1e30f;
            mx0 = fmaxf(mx0, fmaxf(s[nt][0], s[nt][1]));
            mx1 = fmaxf(mx1, fmaxf(s[nt][2], s[nt][3]));
        }
        mx0 = fmaxf(mx0, __shfl_xor_sync(0xffffffffu, mx0, 1));
        mx0 = fmaxf(mx0, __shfl_xor_sync(0xffffffffu, mx0, 2));
        mx1 = fmaxf(mx1, __shfl_xor_sync(0xffffffffu, mx1, 1));
        mx1 = fmaxf(mx1, __shfl_xor_sync(0xffffffffu, mx1, 2));
        float nm0 = fmaxf(m0, mx0), nm1 = fmaxf(m1, mx1);
        float sc0 = __expf(m0 - nm0), sc1 = __expf(m1 - nm1);
        m0 = nm0; m1 = nm1;

        float sum0 = 0.f, sum1 = 0.f;
        uint32_t pa[8][2];
#pragma unroll
        for (int nt = 0; nt < 8; nt++) {
            float p0 = __expf(s[nt][0] - nm0), p1 = __expf(s[nt][1] - nm0);
            float p2 = __expf(s[nt][2] - nm1), p3 = __expf(s[nt][3] - nm1);
            sum0 += p0 + p1; sum1 += p2 + p3;
            pa[nt][0] = h2u(__floats2half2_rn(p0, p1));
            pa[nt][1] = h2u(__floats2half2_rn(p2, p3));
        }
        sum0 += __shfl_xor_sync(0xffffffffu, sum0, 1);
        sum0 += __shfl_xor_sync(0xffffffffu, sum0, 2);
        sum1 += __shfl_xor_sync(0xffffffffu, sum1, 1);
        sum1 += __shfl_xor_sync(0xffffffffu, sum1, 2);
        l0 = l0 * sc0 + sum0;
        l1 = l1 * sc1 + sum1;

        // ---- rescale O, then O += P @ V (P in regs, V via ldsm.T) ----
#pragma unroll
        for (int nt = 0; nt < 16; nt++) {
            o[nt][0] *= sc0; o[nt][1] *= sc0;
            o[nt][2] *= sc1; o[nt][3] *= sc1;
        }
#pragma unroll
        for (int kc = 0; kc < 4; kc++) {
            uint32_t paf[4] = { pa[2 * kc][0], pa[2 * kc][1],
                                pa[2 * kc + 1][0], pa[2 * kc + 1][1] };
#pragma unroll
            for (int j = 0; j < 8; j++) {
                uint32_t bf[4];
                ldsm4t(bf, vbs + (kc * 16 + lr) * 272 + (2 * j + lc) * 16);
                mma16(o[2 * j],     paf, bf[0], bf[1]);
                mma16(o[2 * j + 1], paf, bf[2], bf[3]);
            }
        }
        __syncthreads();   // all warps done reading this buffer before re-stage
    }

    // epilogue: O /= l, write fp16
    float inv0 = 1.f / l0, inv1 = 1.f / l1;
#pragma unroll
    for (int nt = 0; nt < 16; nt++) {
        int c0 = nt * 8 + 2 * tig;
        *(__half2*)(O + (qbase + qrow0 + g) * 2048 + h * 128 + c0) =
            __floats2half2_rn(o[nt][0] * inv0, o[nt][1] * inv0);
        *(__half2*)(O + (qbase + qrow0 + g + 8) * 2048 + h * 128 + c0) =
            __floats2half2_rn(o[nt][2] * inv1, o[nt][3] * inv1);
    }
}

// ---------------- launcher -------------------------------------------------
extern "C" void kernel_launch(void* const* d_in, const int* in_sizes, int n_in,
                              void* d_out, int out_size)
{
    const float* x     = (const float*)d_in[0];
    const float* cosT  = (const float*)d_in[1];
    const float* sinT  = (const float*)d_in[2];
    const float* Wq_s  = (const float*)d_in[3];
    const float* qs_w  = (const float*)d_in[4];
    const float* Wkv_s = (const float*)d_in[5];
    const float* kvs_w = (const float*)d_in[6];
    const float* Wq_p  = (const float*)d_in[7];
    const float* Wkv_p = (const float*)d_in[8];
    const float* Wg_p  = (const float*)d_in[9];
    const float* Wo_p  = (const float*)d_in[10];
    const float* o_w   = (const float*)d_in[11];
    const float* Wo_s  = (const float*)d_in[12];
    float* out = (float*)d_out;

    float *qs, *kvs, *o;
    __half *xh, *qsh, *kvsh, *qh, *kvh, *gatesh, *attnh, *oh;
    __half *wqs_h, *wkvs_h, *wqp_h, *wkvp_h, *wgp_h, *wop_h, *wos_h;
    cudaGetSymbolAddress((void**)&qs,     g_qs);
    cudaGetSymbolAddress((void**)&kvs,    g_kvs);
    cudaGetSymbolAddress((void**)&o,      g_o);
    cudaGetSymbolAddress((void**)&xh,     g_xh);
    cudaGetSymbolAddress((void**)&qsh,    g_qsh);
    cudaGetSymbolAddress((void**)&kvsh,   g_kvsh);
    cudaGetSymbolAddress((void**)&qh,     g_qh);
    cudaGetSymbolAddress((void**)&kvh,    g_kvh);
    cudaGetSymbolAddress((void**)&gatesh, g_gatesh);
    cudaGetSymbolAddress((void**)&attnh,  g_attnh);
    cudaGetSymbolAddress((void**)&oh,     g_oh);
    cudaGetSymbolAddress((void**)&wqs_h,  g_wqs_h);
    cudaGetSymbolAddress((void**)&wkvs_h, g_wkvs_h);
    cudaGetSymbolAddress((void**)&wqp_h,  g_wqp_h);
    cudaGetSymbolAddress((void**)&wkvp_h, g_wkvp_h);
    cudaGetSymbolAddress((void**)&wgp_h,  g_wgp_h);
    cudaGetSymbolAddress((void**)&wop_h,  g_wop_h);
    cudaGetSymbolAddress((void**)&wos_h,  g_wos_h);

    cudaFuncSetAttribute(flash_h16, cudaFuncAttributeMaxDynamicSharedMemorySize,
                         FH_SMEM_BYTES);
    cudaFuncSetAttribute(gemm_h<float>, cudaFuncAttributeMaxDynamicSharedMemorySize,
                         GH_SMEM_BYTES);
    cudaFuncSetAttribute(gemm_h<__half>, cudaFuncAttributeMaxDynamicSharedMemorySize,
                         GH_SMEM_BYTES);

    dim3 blk(256);
    // convert inputs/weights to fp16
    cvt_f2h<<<(NTOK * HIDD) / 1024, 256>>>(x, xh, NTOK * HIDD);
    cvt_f2h<<<(D_CQ * HIDD) / 1024, 256>>>(Wq_s, wqs_h, D_CQ * HIDD);
    cvt_f2h<<<(D_CKV * HIDD) / 1024, 256>>>(Wkv_s, wkvs_h, D_CKV * HIDD);
    cvt_f2h<<<(2048 * D_CQ) / 1024, 256>>>(Wq_p, wqp_h, 2048 * D_CQ);
    cvt_f2h<<<(4096 * D_CKV) / 1024, 256>>>(Wkv_p, wkvp_h, 4096 * D_CKV);
    cvt_f2h<<<(2048 * HIDD) / 1024, 256>>>(Wg_p, wgp_h, 2048 * HIDD);
    cvt_f2h<<<(D_CO * 2048) / 1024, 256>>>(Wo_p, wop_h, D_CO * 2048);
    cvt_f2h<<<(HIDD * D_CO) / 1024, 256>>>(Wo_s, wos_h, HIDD * D_CO);

    gemm_h<float><<<dim3(D_CQ / 128,  NTOK / 128), blk, GH_SMEM_BYTES>>>(xh, wqs_h, qs, D_CQ, HIDD);
    rms_rows<<<NTOK, 256>>>(qs, qs_w, D_CQ, qsh);
    gemm_h<float><<<dim3(D_CKV / 128, NTOK / 128), blk, GH_SMEM_BYTES>>>(xh, wkvs_h, kvs, D_CKV, HIDD);
    rms_rows<<<NTOK, 256>>>(kvs, kvs_w, D_CKV, kvsh);

    gemm_h<__half><<<dim3(2048 / 128, NTOK / 128), blk, GH_SMEM_BYTES>>>(qsh,  wqp_h,  qh,     2048, D_CQ);
    gemm_h<__half><<<dim3(4096 / 128, NTOK / 128), blk, GH_SMEM_BYTES>>>(kvsh, wkvp_h, kvh,    4096, D_CKV);
    gemm_h<__half><<<dim3(2048 / 128, NTOK / 128), blk, GH_SMEM_BYTES>>>(xh,   wgp_h,  gatesh, 2048, HIDD);

    rope_h<<<NTOK, 256>>>(qh,  cosT, sinT, 2048);
    rope_h<<<NTOK, 256>>>(kvh, cosT, sinT, 4096);
    gate_v_h<<<(NTOK * 2048) / 512, 256>>>(kvh, gatesh);

    flash_h16<<<dim3(TSEQ / 128, NH, 2), blk, FH_SMEM_BYTES>>>(qh, kvh, attnh);

    gemm_h<float><<<dim3(D_CO / 128, NTOK / 128), blk, GH_SMEM_BYTES>>>(attnh, wop_h, o, D_CO, 2048);
    rms_rows<<<NTOK, 256>>>(o, o_w, D_CO, oh);
    gemm_h<float><<<dim3(HIDD / 128, NTOK / 128), blk, GH_SMEM_BYTES>>>(oh, wos_h, out, HIDD, D_CO);
}

// round 11
// speedup vs baseline: 5.3113x; 1.0136x over previous
#include <cuda_runtime.h>
#include <cuda_fp16.h>
#include <math.h>
#include <stdint.h>

// ---------------- problem constants ----------------
#define NTOK 4096      // B*T
#define TSEQ 2048
#define HIDD 2048
#define NH   16
#define DHEAD 128
#define RROT 32
#define D_CQ 768
#define D_CKV 512
#define D_CO 512
#define QK_SCALE 0.08838834764831845f  // 128^-0.5

// ---------------- scratch ----------------
__device__ float g_qs[(size_t)NTOK * D_CQ];
__device__ float g_kvs[(size_t)NTOK * D_CKV];
__device__ float g_o[(size_t)NTOK * D_CO];
__device__ __half g_xh[(size_t)NTOK * HIDD];
__device__ __half g_qsh[(size_t)NTOK * D_CQ];
__device__ __half g_kvsh[(size_t)NTOK * D_CKV];
__device__ __half g_qh[(size_t)NTOK * 2048];
__device__ __half g_kvh[(size_t)NTOK * 4096];   // k | v
__device__ __half g_gatesh[(size_t)NTOK * 2048];
__device__ __half g_attnh[(size_t)NTOK * 2048];
__device__ __half g_oh[(size_t)NTOK * D_CO];
__device__ __half g_wqs_h[(size_t)D_CQ * HIDD];
__device__ __half g_wkvs_h[(size_t)D_CKV * HIDD];
__device__ __half g_wqp_h[(size_t)2048 * D_CQ];
__device__ __half g_wkvp_h[(size_t)4096 * D_CKV];
__device__ __half g_wgp_h[(size_t)2048 * HIDD];
__device__ __half g_wop_h[(size_t)D_CO * 2048];
__device__ __half g_wos_h[(size_t)HIDD * D_CO];

// ---------------- helpers ----------------
__device__ __forceinline__ uint32_t smem_u32(const void* p) {
    uint32_t a;
    asm("{ .reg .u64 t; cvta.to.shared.u64 t, %1; cvt.u32.u64 %0, t; }" : "=r"(a) : "l"(p));
    return a;
}
__device__ __forceinline__ void mma16(float c[4], const uint32_t a[4], uint32_t b0, uint32_t b1) {
    asm volatile(
        "mma.sync.aligned.m16n8k16.row.col.f32.f16.f16.f32 "
        "{%0,%1,%2,%3},{%4,%5,%6,%7},{%8,%9},{%0,%1,%2,%3};"
        : "+f"(c[0]), "+f"(c[1]), "+f"(c[2]), "+f"(c[3])
        : "r"(a[0]), "r"(a[1]), "r"(a[2]), "r"(a[3]), "r"(b0), "r"(b1));
}
__device__ __forceinline__ void ldsm4(uint32_t* r, uint32_t a) {
    asm volatile("ldmatrix.sync.aligned.m8n8.x4.shared.b16 {%0,%1,%2,%3}, [%4];"
        : "=r"(r[0]), "=r"(r[1]), "=r"(r[2]), "=r"(r[3]) : "r"(a));
}
__device__ __forceinline__ void ldsm4t(uint32_t* r, uint32_t a) {
    asm volatile("ldmatrix.sync.aligned.m8n8.x4.trans.shared.b16 {%0,%1,%2,%3}, [%4];"
        : "=r"(r[0]), "=r"(r[1]), "=r"(r[2]), "=r"(r[3]) : "r"(a));
}
__device__ __forceinline__ void cpa16(uint32_t saddr, const void* g) {
    asm volatile("cp.async.cg.shared.global [%0], [%1], 16;" :: "r"(saddr), "l"(g));
}
#define CPA_COMMIT() asm volatile("cp.async.commit_group;" ::: "memory")
#define CPA_WAIT(n)  asm volatile("cp.async.wait_group %0;" :: "n"(n) : "memory")
__device__ __forceinline__ uint32_t h2u(__half2 h) {
    uint32_t u;
    asm("mov.b32 %0, %1;" : "=r"(u) : "r"(*(uint32_t*)&h));
    return u;
}

// ---------------- merged fp32 -> fp16 convert (x + 7 weights) -------------
#define CV_N0 8388608u   // x
#define CV_P1 (CV_N0)
#define CV_P2 (CV_P1 + 1572864u)   // wqs
#define CV_P3 (CV_P2 + 1048576u)   // wkvs
#define CV_P4 (CV_P3 + 1572864u)   // wqp
#define CV_P5 (CV_P4 + 2097152u)   // wkvp
#define CV_P6 (CV_P5 + 4194304u)   // wgp
#define CV_P7 (CV_P6 + 1048576u)   // wop
#define CV_END (CV_P7 + 1048576u)  // wos -> 20971520
#define CV_BLOCKS (CV_END / 1024)

__global__ void cvt_all(
    const float* __restrict__ s0, const float* __restrict__ s1,
    const float* __restrict__ s2, const float* __restrict__ s3,
    const float* __restrict__ s4, const float* __restrict__ s5,
    const float* __restrict__ s6, const float* __restrict__ s7,
    __half* __restrict__ d0, __half* __restrict__ d1,
    __half* __restrict__ d2, __half* __restrict__ d3,
    __half* __restrict__ d4, __half* __restrict__ d5,
    __half* __restrict__ d6, __half* __restrict__ d7)
{
    uint32_t i = (blockIdx.x * 256 + threadIdx.x) * 4;
    const float* s; __half* d; uint32_t off;
    if      (i < CV_P1) { s = s0; d = d0; off = i; }
    else if (i < CV_P2) { s = s1; d = d1; off = i - CV_P1; }
    else if (i < CV_P3) { s = s2; d = d2; off = i - CV_P2; }
    else if (i < CV_P4) { s = s3; d = d3; off = i - CV_P3; }
    else if (i < CV_P5) { s = s4; d = d4; off = i - CV_P4; }
    else if (i < CV_P6) { s = s5; d = d5; off = i - CV_P5; }
    else if (i < CV_P7) { s = s6; d = d6; off = i - CV_P6; }
    else                { s = s7; d = d7; off = i - CV_P7; }
    float4 v = *(const float4*)(s + off);
    __half2* o = (__half2*)(d + off);
    o[0] = __floats2half2_rn(v.x, v.y);
    o[1] = __floats2half2_rn(v.z, v.w);
}

// ---------------- fp16 GEMM: C[M,N] = A[M,K] @ B[N,K]^T (verified R8) -----
// MODE 0: fp32 out. MODE 1: fp16 out. MODE 2: fp16 + RoPE (q layout).
// MODE 3: fp16 + RoPE on k (bn<2048) + silu-gate on v (bn>=2048).
#define GH_SMEM_BYTES (3 * 16384)

template <int MODE>
__global__ __launch_bounds__(256, 2) void gemm_h(
    const __half* __restrict__ A, const __half* __restrict__ B, void* __restrict__ Cv,
    int N, int K,
    const float* __restrict__ cosT, const float* __restrict__ sinT,
    const __half* __restrict__ gates)
{
    extern __shared__ char hsm[];
    const uint32_t shb = smem_u32(hsm);
    const int tid = threadIdx.x, lane = tid & 31, w = tid >> 5;
    const int g = lane >> 2, tig = lane & 3;
    const int wm = (w & 3) * 32, wn = (w >> 2) * 64;
    const int bm = blockIdx.y * 128, bn = blockIdx.x * 128;
    const int lr = lane & 15, lc = lane >> 4;

    float acc[2][8][4];
#pragma unroll
    for (int mt = 0; mt < 2; mt++)
#pragma unroll
        for (int nt = 0; nt < 8; nt++)
#pragma unroll
            for (int r = 0; r < 4; r++) acc[mt][nt][r] = 0.f;

    const int srow = tid >> 1, shalf = tid & 1;
    const __half* pa = A + (size_t)(bm + srow) * K + shalf * 16;
    const __half* pb = B + (size_t)(bn + srow) * K + shalf * 16;
    const uint32_t da0 = srow * 64 + ((((shalf * 2 + 0) + (srow >> 1)) & 3) << 4);
    const uint32_t da1 = srow * 64 + ((((shalf * 2 + 1) + (srow >> 1)) & 3) << 4);

    const int ntile = K >> 5;
#define GH_ISSUE(t) do {                                       \
        uint32_t _b = shb + ((t) % 3) * 16384;                 \
        const __half* _a = pa + (size_t)(t) * 32;              \
        const __half* _bb = pb + (size_t)(t) * 32;             \
        cpa16(_b + da0, _a);                                   \
        cpa16(_b + da1, _a + 8);                               \
        cpa16(_b + 8192 + da0, _bb);                           \
        cpa16(_b + 8192 + da1, _bb + 8);                       \
        CPA_COMMIT();                                          \
    } while (0)

    GH_ISSUE(0);
    GH_ISSUE(1);

    for (int i = 0; i < ntile; i++) {
        if (i < ntile - 1) { CPA_WAIT(1); } else { CPA_WAIT(0); }
        __syncthreads();
        if (i + 2 < ntile) GH_ISSUE(i + 2);
        const uint32_t base = shb + (i % 3) * 16384;
#pragma unroll
        for (int ks = 0; ks < 2; ks++) {
            const int cb = 2 * ks + lc;
            uint32_t af[2][4], bf[4][4];
#pragma unroll
            for (int mt = 0; mt < 2; mt++) {
                int r = wm + mt * 16 + lr;
                ldsm4(af[mt], base + r * 64 + (((cb + (r >> 1)) & 3) << 4));
            }
#pragma unroll
            for (int p = 0; p < 4; p++) {
                int r = wn + p * 16 + lr;
                ldsm4(bf[p], base + 8192 + r * 64 + (((cb + (r >> 1)) & 3) << 4));
            }
#pragma unroll
            for (int mt = 0; mt < 2; mt++)
#pragma unroll
                for (int nt = 0; nt < 8; nt++) {
                    int p = nt >> 1, s = nt & 1;
                    mma16(acc[mt][nt], af[mt], bf[p][s], bf[p][s + 2]);
                }
        }
        __syncthreads();
    }

    // -------- fused epilogue transforms --------
    if ((MODE == 2 || (MODE == 3 && bn < 2048)) && wn == 0) {
        // RoPE on block-local cols 0..31 (one head per 128-col block).
#pragma unroll
        for (int mt = 0; mt < 2; mt++) {
            int r0 = bm + wm + mt * 16 + g;
            int t0 = r0 & (TSEQ - 1), t1 = (r0 + 8) & (TSEQ - 1);
#pragma unroll
            for (int nt = 0; nt < 2; nt++) {
                int d = nt * 8 + 2 * tig;
                float c0a = cosT[t0 * RROT + d],      c0b = cosT[t0 * RROT + d + 1];
                float c0c = cosT[t0 * RROT + d + 16], c0d = cosT[t0 * RROT + d + 17];
                float s0a = sinT[t0 * RROT + d],      s0b = sinT[t0 * RROT + d + 1];
                float s0c = sinT[t0 * RROT + d + 16], s0d = sinT[t0 * RROT + d + 17];
                float c1a = cosT[t1 * RROT + d],      c1b = cosT[t1 * RROT + d + 1];
                float c1c = cosT[t1 * RROT + d + 16], c1d = cosT[t1 * RROT + d + 17];
                float s1a = sinT[t1 * RROT + d],      s1b = sinT[t1 * RROT + d + 1];
                float s1c = sinT[t1 * RROT + d + 16], s1d = sinT[t1 * RROT + d + 17];
                float x, y;
                x = acc[mt][nt][0]; y = acc[mt][nt + 2][0];
                acc[mt][nt][0] = x * c0a - y * s0a; acc[mt][nt + 2][0] = y * c0c + x * s0c;
                x = acc[mt][nt][1]; y = acc[mt][nt + 2][1];
                acc[mt][nt][1] = x * c0b - y * s0b; acc[mt][nt + 2][1] = y * c0d + x * s0d;
                x = acc[mt][nt][2]; y = acc[mt][nt + 2][2];
                acc[mt][nt][2] = x * c1a - y * s1a; acc[mt][nt + 2][2] = y * c1c + x * s1c;
                x = acc[mt][nt][3]; y = acc[mt][nt + 2][3];
                acc[mt][nt][3] = x * c1b - y * s1b; acc[mt][nt + 2][3] = y * c1d + x * s1d;
            }
        }
    }
    if (MODE == 3 && bn >= 2048) {
        // v *= silu(gate); gates is [NTOK][2048] fp16
#pragma unroll
        for (int mt = 0; mt < 2; mt++) {
            int r0 = bm + wm + mt * 16 + g;
#pragma unroll
            for (int nt = 0; nt < 8; nt++) {
                int cg = bn - 2048 + wn + nt * 8 + 2 * tig;
                __half2 ga = *(const __half2*)(gates + (size_t)r0 * 2048 + cg);
                __half2 gb = *(const __half2*)(gates + (size_t)(r0 + 8) * 2048 + cg);
                float g0 = __low2float(ga), g1 = __high2float(ga);
                float g2 = __low2float(gb), g3 = __high2float(gb);
                acc[mt][nt][0] *= g0 / (1.f + __expf(-g0));
                acc[mt][nt][1] *= g1 / (1.f + __expf(-g1));
                acc[mt][nt][2] *= g2 / (1.f + __expf(-g2));
                acc[mt][nt][3] *= g3 / (1.f + __expf(-g3));
            }
        }
    }

    // -------- store --------
#pragma unroll
    for (int mt = 0; mt < 2; mt++) {
        int r0 = bm + wm + mt * 16 + g;
#pragma unroll
        for (int nt = 0; nt < 8; nt++) {
            int c0 = bn + wn + nt * 8 + 2 * tig;
            if (MODE == 0) {
                float* C = (float*)Cv;
                *(float2*)(C + (size_t)r0 * N + c0)       = make_float2(acc[mt][nt][0], acc[mt][nt][1]);
                *(float2*)(C + (size_t)(r0 + 8) * N + c0) = make_float2(acc[mt][nt][2], acc[mt][nt][3]);
            } else {
                __half* C = (__half*)Cv;
                *(__half2*)(C + (size_t)r0 * N + c0)       = __floats2half2_rn(acc[mt][nt][0], acc[mt][nt][1]);
                *(__half2*)(C + (size_t)(r0 + 8) * N + c0) = __floats2half2_rn(acc[mt][nt][2], acc[mt][nt][3]);
            }
        }
    }
}

// ---------------- RMSNorm rows in place, optional half copy ---------------
__global__ void rms_rows(float* __restrict__ X, const float* __restrict__ w, int D,
                         __half* __restrict__ H)
{
    __shared__ float red[8];
    const int row = blockIdx.x, tid = threadIdx.x;
    const int lane = tid & 31, wid = tid >> 5;
    float* x = X + (size_t)row * D;
    __half* hh = H ? H + (size_t)row * D : (__half*)0;
    float ss = 0.f;
    for (int i = tid; i < D; i += 256) { float v = x[i]; ss += v * v; }
#pragma unroll
    for (int m = 16; m > 0; m >>= 1) ss += __shfl_xor_sync(0xffffffff, ss, m);
    if (lane == 0) red[wid] = ss;
    __syncthreads();
    float tot = 0.f;
#pragma unroll
    for (int j = 0; j < 8; j++) tot += red[j];
    float inv = rsqrtf(tot / (float)D + 1e-6f);
    for (int i = tid; i < D; i += 256) {
        float r = w[i] * (x[i] * inv);
        x[i] = r;
        if (hh) hh[i] = __float2half_rn(r);
    }
}

// ---------------- flash attention (verified R10) ---------------------------
#define FH_QB 34816u
#define FH_KVB 17408u
#define FH_SMEM_BYTES (FH_QB + 4 * FH_KVB)

__global__ __launch_bounds__(256) void flash_h16(
    const __half* __restrict__ Qh, const __half* __restrict__ KVh, __half* __restrict__ O)
{
    extern __shared__ __half sh2[];
    const uint32_t qbs = smem_u32(sh2);
    const uint32_t kvb0 = qbs + FH_QB;
    const uint32_t kvb1 = qbs + FH_QB + 2 * FH_KVB;

    const int qt = (int)gridDim.x - 1 - blockIdx.x;   // LPT
    const int h = blockIdx.y, b = blockIdx.z;
    const int tid = threadIdx.x, lane = tid & 31, w = tid >> 5;
    const int g = lane >> 2, tig = lane & 3;
    const int lr = lane & 15, lc = lane >> 4;
    const int qrow0 = w * 16;
    const size_t qbase = (size_t)b * TSEQ + qt * 128;
    const size_t kvrow = (size_t)b * TSEQ;

#define FH_KV_ISSUE(kt) do {                                                     \
        const uint32_t _kb = ((kt) & 1) ? kvb1 : kvb0;                           \
        const __half* _base = KVh + (kvrow + (size_t)(kt) * 64) * 4096 + h * 128;\
        _Pragma("unroll")                                                        \
        for (int _j = 0; _j < 4; _j++) {                                         \
            int _f = tid * 4 + _j;                                               \
            int _r = _f >> 4, _c = _f & 15;                                      \
            uint32_t _d = _r * 272 + _c * 16;                                    \
            cpa16(_kb + _d,          _base + (size_t)_r * 4096 + _c * 8);        \
            cpa16(_kb + FH_KVB + _d, _base + (size_t)_r * 4096 + 2048 + _c * 8); \
        }                                                                        \
        CPA_COMMIT();                                                            \
    } while (0)

#pragma unroll
    for (int j = 0; j < 8; j++) {
        int f = tid * 8 + j;
        int r = f >> 4, c = f & 15;
        cpa16(qbs + r * 272 + c * 16, Qh + (qbase + r) * 2048 + h * 128 + c * 8);
    }
    CPA_COMMIT();
    FH_KV_ISSUE(0);
    CPA_WAIT(1);
    __syncthreads();

    uint32_t qf[8][4];
#pragma unroll
    for (int kc = 0; kc < 8; kc++)
        ldsm4(qf[kc], qbs + (qrow0 + lr) * 272 + (2 * kc + lc) * 16);

    float m0 = -1e30f, m1 = -1e30f, l0 = 0.f, l1 = 0.f;
    float o[16][4];
#pragma unroll
    for (int nt = 0; nt < 16; nt++)
#pragma unroll
        for (int r = 0; r < 4; r++) o[nt][r] = 0.f;

    const int nkt = 2 * qt + 2;
    for (int kt = 0; kt < nkt; kt++) {
        if (kt + 1 < nkt) { FH_KV_ISSUE(kt + 1); CPA_WAIT(1); }
        else              { CPA_WAIT(0); }
        __syncthreads();
        const uint32_t kbs = (kt & 1) ? kvb1 : kvb0;
        const uint32_t vbs = kbs + FH_KVB;

        float s[8][4];
#pragma unroll
        for (int nt = 0; nt < 8; nt++)
#pragma unroll
            for (int r = 0; r < 4; r++) s[nt][r] = 0.f;
#pragma unroll
        for (int ks = 0; ks < 8; ks++) {
            uint32_t bf[4][4];
#pragma unroll
            for (int p = 0; p < 4; p++)
                ldsm4(bf[p], kbs + (p * 16 + lr) * 272 + (2 * ks + lc) * 16);
#pragma unroll
            for (int nt = 0; nt < 8; nt++) {
                int p = nt >> 1, ss = nt & 1;
                mma16(s[nt], qf[ks], bf[p][ss], bf[p][ss + 2]);
            }
        }

        const int qg0 = qt * 128 + qrow0 + g, qg1 = qg0 + 8;
        float mx0 = -1e30f, mx1 = -1e30f;
#pragma unroll
        for (int nt = 0; nt < 8; nt++) {
            int kg0 = kt * 64 + nt * 8 + 2 * tig, kg1 = kg0 + 1;
            s[nt][0] = (kg0 <= qg0) ? s[nt][0] * QK_SCALE : -1e30f;
            s[nt][1] = (kg1 <= qg0) ? s[nt][1] * QK_SCALE : -1e30f;
            s[nt][2] = (kg0 <= qg1) ? s[nt][2] * QK_SCALE : -1e30f;
            s[nt][3] = (kg1 <= qg1) ? s[nt][3] * QK_SCALE : -1e30f;
            mx0 = fmaxf(mx0, fmaxf(s[nt][0], s[nt][1]));
            mx1 = fmaxf(mx1, fmaxf(s[nt][2], s[nt][3]));
        }
        mx0 = fmaxf(mx0, __shfl_xor_sync(0xffffffffu, mx0, 1));
        mx0 = fmaxf(mx0, __shfl_xor_sync(0xffffffffu, mx0, 2));
        mx1 = fmaxf(mx1, __shfl_xor_sync(0xffffffffu, mx1, 1));
        mx1 = fmaxf(mx1, __shfl_xor_sync(0xffffffffu, mx1, 2));
        float nm0 = fmaxf(m0, mx0), nm1 = fmaxf(m1, mx1);
        float sc0 = __expf(m0 - nm0), sc1 = __expf(m1 - nm1);
        m0 = nm0; m1 = nm1;

        float sum0 = 0.f, sum1 = 0.f;
        uint32_t pa[8][2];
#pragma unroll
        for (int nt = 0; nt < 8; nt++) {
            float p0 = __expf(s[nt][0] - nm0), p1 = __expf(s[nt][1] - nm0);
            float p2 = __expf(s[nt][2] - nm1), p3 = __expf(s[nt][3] - nm1);
            sum0 += p0 + p1; sum1 += p2 + p3;
            pa[nt][0] = h2u(__floats2half2_rn(p0, p1));
            pa[nt][1] = h2u(__floats2half2_rn(p2, p3));
        }
        sum0 += __shfl_xor_sync(0xffffffffu, sum0, 1);
        sum0 += __shfl_xor_sync(0xffffffffu, sum0, 2);
        sum1 += __shfl_xor_sync(0xffffffffu, sum1, 1);
        sum1 += __shfl_xor_sync(0xffffffffu, sum1, 2);
        l0 = l0 * sc0 + sum0;
        l1 = l1 * sc1 + sum1;

#pragma unroll
        for (int nt = 0; nt < 16; nt++) {
            o[nt][0] *= sc0; o[nt][1] *= sc0;
            o[nt][2] *= sc1; o[nt][3] *= sc1;
        }
#pragma unroll
        for (int kc = 0; kc < 4; kc++) {
            uint32_t paf[4] = { pa[2 * kc][0], pa[2 * kc][1],
                                pa[2 * kc + 1][0], pa[2 * kc + 1][1] };
#pragma unroll
            for (int j = 0; j < 8; j++) {
                uint32_t bf[4];
                ldsm4t(bf, vbs + (kc * 16 + lr) * 272 + (2 * j + lc) * 16);
                mma16(o[2 * j],     paf, bf[0], bf[1]);
                mma16(o[2 * j + 1], paf, bf[2], bf[3]);
            }
        }
        __syncthreads();
    }

    float inv0 = 1.f / l0, inv1 = 1.f / l1;
#pragma unroll
    for (int nt = 0; nt < 16; nt++) {
        int c0 = nt * 8 + 2 * tig;
        *(__half2*)(O + (qbase + qrow0 + g) * 2048 + h * 128 + c0) =
            __floats2half2_rn(o[nt][0] * inv0, o[nt][1] * inv0);
        *(__half2*)(O + (qbase + qrow0 + g + 8) * 2048 + h * 128 + c0) =
            __floats2half2_rn(o[nt][2] * inv1, o[nt][3] * inv1);
    }
}

// ---------------- launcher -------------------------------------------------
extern "C" void kernel_launch(void* const* d_in, const int* in_sizes, int n_in,
                              void* d_out, int out_size)
{
    const float* x     = (const float*)d_in[0];
    const float* cosT  = (const float*)d_in[1];
    const float* sinT  = (const float*)d_in[2];
    const float* Wq_s  = (const float*)d_in[3];
    const float* qs_w  = (const float*)d_in[4];
    const float* Wkv_s = (const float*)d_in[5];
    const float* kvs_w = (const float*)d_in[6];
    const float* Wq_p  = (const float*)d_in[7];
    const float* Wkv_p = (const float*)d_in[8];
    const float* Wg_p  = (const float*)d_in[9];
    const float* Wo_p  = (const float*)d_in[10];
    const float* o_w   = (const float*)d_in[11];
    const float* Wo_s  = (const float*)d_in[12];
    float* out = (float*)d_out;

    float *qs, *kvs, *o;
    __half *xh, *qsh, *kvsh, *qh, *kvh, *gatesh, *attnh, *oh;
    __half *wqs_h, *wkvs_h, *wqp_h, *wkvp_h, *wgp_h, *wop_h, *wos_h;
    cudaGetSymbolAddress((void**)&qs,     g_qs);
    cudaGetSymbolAddress((void**)&kvs,    g_kvs);
    cudaGetSymbolAddress((void**)&o,      g_o);
    cudaGetSymbolAddress((void**)&xh,     g_xh);
    cudaGetSymbolAddress((void**)&qsh,    g_qsh);
    cudaGetSymbolAddress((void**)&kvsh,   g_kvsh);
    cudaGetSymbolAddress((void**)&qh,     g_qh);
    cudaGetSymbolAddress((void**)&kvh,    g_kvh);
    cudaGetSymbolAddress((void**)&gatesh, g_gatesh);
    cudaGetSymbolAddress((void**)&attnh,  g_attnh);
    cudaGetSymbolAddress((void**)&oh,     g_oh);
    cudaGetSymbolAddress((void**)&wqs_h,  g_wqs_h);
    cudaGetSymbolAddress((void**)&wkvs_h, g_wkvs_h);
    cudaGetSymbolAddress((void**)&wqp_h,  g_wqp_h);
    cudaGetSymbolAddress((void**)&wkvp_h, g_wkvp_h);
    cudaGetSymbolAddress((void**)&wgp_h,  g_wgp_h);
    cudaGetSymbolAddress((void**)&wop_h,  g_wop_h);
    cudaGetSymbolAddress((void**)&wos_h,  g_wos_h);

    cudaFuncSetAttribute(flash_h16, cudaFuncAttributeMaxDynamicSharedMemorySize,
                         FH_SMEM_BYTES);
    cudaFuncSetAttribute(gemm_h<0>, cudaFuncAttributeMaxDynamicSharedMemorySize, GH_SMEM_BYTES);
    cudaFuncSetAttribute(gemm_h<1>, cudaFuncAttributeMaxDynamicSharedMemorySize, GH_SMEM_BYTES);
    cudaFuncSetAttribute(gemm_h<2>, cudaFuncAttributeMaxDynamicSharedMemorySize, GH_SMEM_BYTES);
    cudaFuncSetAttribute(gemm_h<3>, cudaFuncAttributeMaxDynamicSharedMemorySize, GH_SMEM_BYTES);

    dim3 blk(256);
    cvt_all<<<CV_BLOCKS, 256>>>(x, Wq_s, Wkv_s, Wq_p, Wkv_p, Wg_p, Wo_p, Wo_s,
                                xh, wqs_h, wkvs_h, wqp_h, wkvp_h, wgp_h, wop_h, wos_h);

    gemm_h<0><<<dim3(D_CQ / 128,  NTOK / 128), blk, GH_SMEM_BYTES>>>(
        xh, wqs_h, qs, D_CQ, HIDD, 0, 0, 0);
    rms_rows<<<NTOK, 256>>>(qs, qs_w, D_CQ, qsh);
    gemm_h<0><<<dim3(D_CKV / 128, NTOK / 128), blk, GH_SMEM_BYTES>>>(
        xh, wkvs_h, kvs, D_CKV, HIDD, 0, 0, 0);
    rms_rows<<<NTOK, 256>>>(kvs, kvs_w, D_CKV, kvsh);

    // gates first (consumed by kvp epilogue)
    gemm_h<1><<<dim3(2048 / 128, NTOK / 128), blk, GH_SMEM_BYTES>>>(
        xh, wgp_h, gatesh, 2048, HIDD, 0, 0, 0);
    // q projection + fused rope
    gemm_h<2><<<dim3(2048 / 128, NTOK / 128), blk, GH_SMEM_BYTES>>>(
        qsh, wqp_h, qh, 2048, D_CQ, cosT, sinT, 0);
    // kv projection + fused rope(k) + gate(v)
    gemm_h<3><<<dim3(4096 / 128, NTOK / 128), blk, GH_SMEM_BYTES>>>(
        kvsh, wkvp_h, kvh, 4096, D_CKV, cosT, sinT, gatesh);

    flash_h16<<<dim3(TSEQ / 128, NH, 2), blk, FH_SMEM_BYTES>>>(qh, kvh, attnh);

    gemm_h<0><<<dim3(D_CO / 128, NTOK / 128), blk, GH_SMEM_BYTES>>>(
        attnh, wop_h, o, D_CO, 2048, 0, 0, 0);
    rms_rows<<<NTOK, 256>>>(o, o_w, D_CO, oh);
    gemm_h<0><<<dim3(HIDD / 128, NTOK / 128), blk, GH_SMEM_BYTES>>>(
        oh, wos_h, out, HIDD, D_CO, 0, 0, 0);
}

// round 12
// speedup vs baseline: 5.6106x; 1.0564x over previous
#include <cuda_runtime.h>
#include <cuda_fp16.h>
#include <math.h>
#include <stdint.h>

// ---------------- problem constants ----------------
#define NTOK 4096      // B*T
#define TSEQ 2048
#define HIDD 2048
#define NH   16
#define DHEAD 128
#define RROT 32
#define D_CQ 768
#define D_CKV 512
#define D_CO 512
#define D_QKVS 1280    // D_CQ + D_CKV
#define QK_SCALE 0.08838834764831845f  // 128^-0.5

// ---------------- scratch ----------------
__device__ float g_qskvs[(size_t)NTOK * D_QKVS];   // qs | kvs (fp32, pre-rms)
__device__ float g_o[(size_t)NTOK * D_CO];
__device__ __half g_xh[(size_t)NTOK * HIDD];
__device__ __half g_qsh[(size_t)NTOK * D_CQ];
__device__ __half g_kvsh[(size_t)NTOK * D_CKV];
__device__ __half g_qh[(size_t)NTOK * 2048];
__device__ __half g_kvh[(size_t)NTOK * 4096];   // k | v
__device__ __half g_gatesh[(size_t)NTOK * 2048];
__device__ __half g_attnh[(size_t)NTOK * 2048];
__device__ __half g_oh[(size_t)NTOK * D_CO];
__device__ __half g_wqkvs_h[(size_t)D_QKVS * HIDD];  // wqs | wkvs
__device__ __half g_wqp_h[(size_t)2048 * D_CQ];
__device__ __half g_wkvp_h[(size_t)4096 * D_CKV];
__device__ __half g_wgp_h[(size_t)2048 * HIDD];
__device__ __half g_wop_h[(size_t)D_CO * 2048];
__device__ __half g_wos_h[(size_t)HIDD * D_CO];

// ---------------- helpers ----------------
__device__ __forceinline__ uint32_t smem_u32(const void* p) {
    uint32_t a;
    asm("{ .reg .u64 t; cvta.to.shared.u64 t, %1; cvt.u32.u64 %0, t; }" : "=r"(a) : "l"(p));
    return a;
}
__device__ __forceinline__ void mma16(float c[4], const uint32_t a[4], uint32_t b0, uint32_t b1) {
    asm volatile(
        "mma.sync.aligned.m16n8k16.row.col.f32.f16.f16.f32 "
        "{%0,%1,%2,%3},{%4,%5,%6,%7},{%8,%9},{%0,%1,%2,%3};"
        : "+f"(c[0]), "+f"(c[1]), "+f"(c[2]), "+f"(c[3])
        : "r"(a[0]), "r"(a[1]), "r"(a[2]), "r"(a[3]), "r"(b0), "r"(b1));
}
__device__ __forceinline__ void ldsm4(uint32_t* r, uint32_t a) {
    asm volatile("ldmatrix.sync.aligned.m8n8.x4.shared.b16 {%0,%1,%2,%3}, [%4];"
        : "=r"(r[0]), "=r"(r[1]), "=r"(r[2]), "=r"(r[3]) : "r"(a));
}
__device__ __forceinline__ void ldsm4t(uint32_t* r, uint32_t a) {
    asm volatile("ldmatrix.sync.aligned.m8n8.x4.trans.shared.b16 {%0,%1,%2,%3}, [%4];"
        : "=r"(r[0]), "=r"(r[1]), "=r"(r[2]), "=r"(r[3]) : "r"(a));
}
__device__ __forceinline__ void cpa16(uint32_t saddr, const void* g) {
    asm volatile("cp.async.cg.shared.global [%0], [%1], 16;" :: "r"(saddr), "l"(g));
}
#define CPA_COMMIT() asm volatile("cp.async.commit_group;" ::: "memory")
#define CPA_WAIT(n)  asm volatile("cp.async.wait_group %0;" :: "n"(n) : "memory")
__device__ __forceinline__ uint32_t h2u(__half2 h) {
    uint32_t u;
    asm("mov.b32 %0, %1;" : "=r"(u) : "r"(*(uint32_t*)&h));
    return u;
}

// ---------------- merged fp32 -> fp16 convert (x + 7 weights) -------------
#define CV_P1 8388608u             // x
#define CV_P2 (CV_P1 + 1572864u)   // wqs  -> wqkvs[0:768)
#define CV_P3 (CV_P2 + 1048576u)   // wkvs -> wqkvs[768:1280)
#define CV_P4 (CV_P3 + 1572864u)   // wqp
#define CV_P5 (CV_P4 + 2097152u)   // wkvp
#define CV_P6 (CV_P5 + 4194304u)   // wgp
#define CV_P7 (CV_P6 + 1048576u)   // wop
#define CV_END (CV_P7 + 1048576u)  // wos
#define CV_BLOCKS (CV_END / 1024)

__global__ void cvt_all(
    const float* __restrict__ s0, const float* __restrict__ s1,
    const float* __restrict__ s2, const float* __restrict__ s3,
    const float* __restrict__ s4, const float* __restrict__ s5,
    const float* __restrict__ s6, const float* __restrict__ s7,
    __half* __restrict__ d0, __half* __restrict__ d1,
    __half* __restrict__ d2, __half* __restrict__ d3,
    __half* __restrict__ d4, __half* __restrict__ d5,
    __half* __restrict__ d6, __half* __restrict__ d7)
{
    uint32_t i = (blockIdx.x * 256 + threadIdx.x) * 4;
    const float* s; __half* d; uint32_t off;
    if      (i < CV_P1) { s = s0; d = d0; off = i; }
    else if (i < CV_P2) { s = s1; d = d1; off = i - CV_P1; }
    else if (i < CV_P3) { s = s2; d = d2; off = i - CV_P2; }
    else if (i < CV_P4) { s = s3; d = d3; off = i - CV_P3; }
    else if (i < CV_P5) { s = s4; d = d4; off = i - CV_P4; }
    else if (i < CV_P6) { s = s5; d = d5; off = i - CV_P5; }
    else if (i < CV_P7) { s = s6; d = d6; off = i - CV_P6; }
    else                { s = s7; d = d7; off = i - CV_P7; }
    float4 v = *(const float4*)(s + off);
    __half2* o = (__half2*)(d + off);
    o[0] = __floats2half2_rn(v.x, v.y);
    o[1] = __floats2half2_rn(v.z, v.w);
}

// ---------------- fp16 GEMM 128x128 (verified R8) --------------------------
// MODE 0: fp32 out. MODE 1: fp16 out. MODE 2: fp16 + RoPE (q layout).
// MODE 3: fp16 + RoPE on k (bn<2048) + silu-gate on v (bn>=2048).
#define GH_SMEM_BYTES (3 * 16384)

template <int MODE>
__global__ __launch_bounds__(256, 2) void gemm_h(
    const __half* __restrict__ A, const __half* __restrict__ B, void* __restrict__ Cv,
    int N, int K,
    const float* __restrict__ cosT, const float* __restrict__ sinT,
    const __half* __restrict__ gates)
{
    extern __shared__ char hsm[];
    const uint32_t shb = smem_u32(hsm);
    const int tid = threadIdx.x, lane = tid & 31, w = tid >> 5;
    const int g = lane >> 2, tig = lane & 3;
    const int wm = (w & 3) * 32, wn = (w >> 2) * 64;
    const int bm = blockIdx.y * 128, bn = blockIdx.x * 128;
    const int lr = lane & 15, lc = lane >> 4;

    float acc[2][8][4];
#pragma unroll
    for (int mt = 0; mt < 2; mt++)
#pragma unroll
        for (int nt = 0; nt < 8; nt++)
#pragma unroll
            for (int r = 0; r < 4; r++) acc[mt][nt][r] = 0.f;

    const int srow = tid >> 1, shalf = tid & 1;
    const __half* pa = A + (size_t)(bm + srow) * K + shalf * 16;
    const __half* pb = B + (size_t)(bn + srow) * K + shalf * 16;
    const uint32_t da0 = srow * 64 + ((((shalf * 2 + 0) + (srow >> 1)) & 3) << 4);
    const uint32_t da1 = srow * 64 + ((((shalf * 2 + 1) + (srow >> 1)) & 3) << 4);

    const int ntile = K >> 5;
#define GH_ISSUE(t) do {                                       \
        uint32_t _b = shb + ((t) % 3) * 16384;                 \
        const __half* _a = pa + (size_t)(t) * 32;              \
        const __half* _bb = pb + (size_t)(t) * 32;             \
        cpa16(_b + da0, _a);                                   \
        cpa16(_b + da1, _a + 8);                               \
        cpa16(_b + 8192 + da0, _bb);                           \
        cpa16(_b + 8192 + da1, _bb + 8);                       \
        CPA_COMMIT();                                          \
    } while (0)

    GH_ISSUE(0);
    GH_ISSUE(1);

    for (int i = 0; i < ntile; i++) {
        if (i < ntile - 1) { CPA_WAIT(1); } else { CPA_WAIT(0); }
        __syncthreads();
        if (i + 2 < ntile) GH_ISSUE(i + 2);
        const uint32_t base = shb + (i % 3) * 16384;
#pragma unroll
        for (int ks = 0; ks < 2; ks++) {
            const int cb = 2 * ks + lc;
            uint32_t af[2][4], bf[4][4];
#pragma unroll
            for (int mt = 0; mt < 2; mt++) {
                int r = wm + mt * 16 + lr;
                ldsm4(af[mt], base + r * 64 + (((cb + (r >> 1)) & 3) << 4));
            }
#pragma unroll
            for (int p = 0; p < 4; p++) {
                int r = wn + p * 16 + lr;
                ldsm4(bf[p], base + 8192 + r * 64 + (((cb + (r >> 1)) & 3) << 4));
            }
#pragma unroll
            for (int mt = 0; mt < 2; mt++)
#pragma unroll
                for (int nt = 0; nt < 8; nt++) {
                    int p = nt >> 1, s = nt & 1;
                    mma16(acc[mt][nt], af[mt], bf[p][s], bf[p][s + 2]);
                }
        }
        __syncthreads();
    }

    // -------- fused epilogue transforms --------
    if ((MODE == 2 || (MODE == 3 && bn < 2048)) && wn == 0) {
#pragma unroll
        for (int mt = 0; mt < 2; mt++) {
            int r0 = bm + wm + mt * 16 + g;
            int t0 = r0 & (TSEQ - 1), t1 = (r0 + 8) & (TSEQ - 1);
#pragma unroll
            for (int nt = 0; nt < 2; nt++) {
                int d = nt * 8 + 2 * tig;
                float c0a = cosT[t0 * RROT + d],      c0b = cosT[t0 * RROT + d + 1];
                float c0c = cosT[t0 * RROT + d + 16], c0d = cosT[t0 * RROT + d + 17];
                float s0a = sinT[t0 * RROT + d],      s0b = sinT[t0 * RROT + d + 1];
                float s0c = sinT[t0 * RROT + d + 16], s0d = sinT[t0 * RROT + d + 17];
                float c1a = cosT[t1 * RROT + d],      c1b = cosT[t1 * RROT + d + 1];
                float c1c = cosT[t1 * RROT + d + 16], c1d = cosT[t1 * RROT + d + 17];
                float s1a = sinT[t1 * RROT + d],      s1b = sinT[t1 * RROT + d + 1];
                float s1c = sinT[t1 * RROT + d + 16], s1d = sinT[t1 * RROT + d + 17];
                float x, y;
                x = acc[mt][nt][0]; y = acc[mt][nt + 2][0];
                acc[mt][nt][0] = x * c0a - y * s0a; acc[mt][nt + 2][0] = y * c0c + x * s0c;
                x = acc[mt][nt][1]; y = acc[mt][nt + 2][1];
                acc[mt][nt][1] = x * c0b - y * s0b; acc[mt][nt + 2][1] = y * c0d + x * s0d;
                x = acc[mt][nt][2]; y = acc[mt][nt + 2][2];
                acc[mt][nt][2] = x * c1a - y * s1a; acc[mt][nt + 2][2] = y * c1c + x * s1c;
                x = acc[mt][nt][3]; y = acc[mt][nt + 2][3];
                acc[mt][nt][3] = x * c1b - y * s1b; acc[mt][nt + 2][3] = y * c1d + x * s1d;
            }
        }
    }
    if (MODE == 3 && bn >= 2048) {
#pragma unroll
        for (int mt = 0; mt < 2; mt++) {
            int r0 = bm + wm + mt * 16 + g;
#pragma unroll
            for (int nt = 0; nt < 8; nt++) {
                int cg = bn - 2048 + wn + nt * 8 + 2 * tig;
                __half2 ga = *(const __half2*)(gates + (size_t)r0 * 2048 + cg);
                __half2 gb = *(const __half2*)(gates + (size_t)(r0 + 8) * 2048 + cg);
                float g0 = __low2float(ga), g1 = __high2float(ga);
                float g2 = __low2float(gb), g3 = __high2float(gb);
                acc[mt][nt][0] *= g0 / (1.f + __expf(-g0));
                acc[mt][nt][1] *= g1 / (1.f + __expf(-g1));
                acc[mt][nt][2] *= g2 / (1.f + __expf(-g2));
                acc[mt][nt][3] *= g3 / (1.f + __expf(-g3));
            }
        }
    }

#pragma unroll
    for (int mt = 0; mt < 2; mt++) {
        int r0 = bm + wm + mt * 16 + g;
#pragma unroll
        for (int nt = 0; nt < 8; nt++) {
            int c0 = bn + wn + nt * 8 + 2 * tig;
            if (MODE == 0) {
                float* C = (float*)Cv;
                *(float2*)(C + (size_t)r0 * N + c0)       = make_float2(acc[mt][nt][0], acc[mt][nt][1]);
                *(float2*)(C + (size_t)(r0 + 8) * N + c0) = make_float2(acc[mt][nt][2], acc[mt][nt][3]);
            } else {
                __half* C = (__half*)Cv;
                *(__half2*)(C + (size_t)r0 * N + c0)       = __floats2half2_rn(acc[mt][nt][0], acc[mt][nt][1]);
                *(__half2*)(C + (size_t)(r0 + 8) * N + c0) = __floats2half2_rn(acc[mt][nt][2], acc[mt][nt][3]);
            }
        }
    }
}

// ---------------- fp16 GEMM 64x128, 128 threads, 4 CTAs/SM -----------------
// Same warp tile (32x64), same swizzle; for small-grid GEMMs. fp32 out only.
#define G64_STG 12288            // (64+128) rows * 64 B
#define G64_SMEM_BYTES (3 * G64_STG)

__global__ __launch_bounds__(128, 4) void gemm64(
    const __half* __restrict__ A, const __half* __restrict__ B, float* __restrict__ C,
    int N, int K)
{
    extern __shared__ char hsm[];
    const uint32_t shb = smem_u32(hsm);
    const int tid = threadIdx.x, lane = tid & 31, w = tid >> 5;
    const int g = lane >> 2, tig = lane & 3;
    const int wm = (w & 1) * 32, wn = (w >> 1) * 64;
    const int bm = blockIdx.y * 64, bn = blockIdx.x * 128;
    const int lr = lane & 15, lc = lane >> 4;

    float acc[2][8][4];
#pragma unroll
    for (int mt = 0; mt < 2; mt++)
#pragma unroll
        for (int nt = 0; nt < 8; nt++)
#pragma unroll
            for (int r = 0; r < 4; r++) acc[mt][nt][r] = 0.f;

    // staging: 6 chunks/thread; f = j*128 + tid, r = f>>2 (0-63 A, 64-191 B), c = f&3
    const int ntile = K >> 5;
#define G64_ISSUE(t) do {                                                        \
        uint32_t _b = shb + ((t) % 3) * G64_STG;                                 \
        _Pragma("unroll")                                                        \
        for (int _j = 0; _j < 6; _j++) {                                         \
            int _f = _j * 128 + tid;                                             \
            int _r = _f >> 2, _c = _f & 3;                                       \
            uint32_t _d = _b + _r * 64 + (((_c + (_r >> 1)) & 3) << 4);          \
            const __half* _g = (_r < 64)                                         \
                ? A + (size_t)(bm + _r) * K + (size_t)(t) * 32 + _c * 8          \
                : B + (size_t)(bn + _r - 64) * K + (size_t)(t) * 32 + _c * 8;    \
            cpa16(_d, _g);                                                       \
        }                                                                        \
        CPA_COMMIT();                                                            \
    } while (0)

    G64_ISSUE(0);
    G64_ISSUE(1);

    for (int i = 0; i < ntile; i++) {
        if (i < ntile - 1) { CPA_WAIT(1); } else { CPA_WAIT(0); }
        __syncthreads();
        if (i + 2 < ntile) G64_ISSUE(i + 2);
        const uint32_t base = shb + (i % 3) * G64_STG;
#pragma unroll
        for (int ks = 0; ks < 2; ks++) {
            const int cb = 2 * ks + lc;
            uint32_t af[2][4], bf[4][4];
#pragma unroll
            for (int mt = 0; mt < 2; mt++) {
                int r = wm + mt * 16 + lr;
                ldsm4(af[mt], base + r * 64 + (((cb + (r >> 1)) & 3) << 4));
            }
#pragma unroll
            for (int p = 0; p < 4; p++) {
                int r = 64 + wn + p * 16 + lr;
                ldsm4(bf[p], base + r * 64 + (((cb + (r >> 1)) & 3) << 4));
            }
#pragma unroll
            for (int mt = 0; mt < 2; mt++)
#pragma unroll
                for (int nt = 0; nt < 8; nt++) {
                    int p = nt >> 1, s = nt & 1;
                    mma16(acc[mt][nt], af[mt], bf[p][s], bf[p][s + 2]);
                }
        }
        __syncthreads();
    }

#pragma unroll
    for (int mt = 0; mt < 2; mt++) {
        int r0 = bm + wm + mt * 16 + g;
#pragma unroll
        for (int nt = 0; nt < 8; nt++) {
            int c0 = bn + wn + nt * 8 + 2 * tig;
            *(float2*)(C + (size_t)r0 * N + c0)       = make_float2(acc[mt][nt][0], acc[mt][nt][1]);
            *(float2*)(C + (size_t)(r0 + 8) * N + c0) = make_float2(acc[mt][nt][2], acc[mt][nt][3]);
        }
    }
}

// ---------------- RMSNorm: read fp32 (strided), write fp16 ------------------
__global__ void rms_rows(const float* __restrict__ X, const float* __restrict__ w,
                         int D, int strideX, __half* __restrict__ H)
{
    __shared__ float red[8];
    const int row = blockIdx.x, tid = threadIdx.x;
    const int lane = tid & 31, wid = tid >> 5;
    const float* x = X + (size_t)row * strideX;
    __half* hh = H + (size_t)row * D;
    float ss = 0.f;
    for (int i = tid; i < D; i += 256) { float v = x[i]; ss += v * v; }
#pragma unroll
    for (int m = 16; m > 0; m >>= 1) ss += __shfl_xor_sync(0xffffffff, ss, m);
    if (lane == 0) red[wid] = ss;
    __syncthreads();
    float tot = 0.f;
#pragma unroll
    for (int j = 0; j < 8; j++) tot += red[j];
    float inv = rsqrtf(tot / (float)D + 1e-6f);
    for (int i = tid; i < D; i += 256)
        hh[i] = __float2half_rn(w[i] * (x[i] * inv));
}

// ---------------- flash attention (verified R10) ---------------------------
#define FH_QB 34816u
#define FH_KVB 17408u
#define FH_SMEM_BYTES (FH_QB + 4 * FH_KVB)

__global__ __launch_bounds__(256) void flash_h16(
    const __half* __restrict__ Qh, const __half* __restrict__ KVh, __half* __restrict__ O)
{
    extern __shared__ __half sh2[];
    const uint32_t qbs = smem_u32(sh2);
    const uint32_t kvb0 = qbs + FH_QB;
    const uint32_t kvb1 = qbs + FH_QB + 2 * FH_KVB;

    const int qt = (int)gridDim.x - 1 - blockIdx.x;   // LPT
    const int h = blockIdx.y, b = blockIdx.z;
    const int tid = threadIdx.x, lane = tid & 31, w = tid >> 5;
    const int g = lane >> 2, tig = lane & 3;
    const int lr = lane & 15, lc = lane >> 4;
    const int qrow0 = w * 16;
    const size_t qbase = (size_t)b * TSEQ + qt * 128;
    const size_t kvrow = (size_t)b * TSEQ;

#define FH_KV_ISSUE(kt) do {                                                     \
        const uint32_t _kb = ((kt) & 1) ? kvb1 : kvb0;                           \
        const __half* _base = KVh + (kvrow + (size_t)(kt) * 64) * 4096 + h * 128;\
        _Pragma("unroll")                                                        \
        for (int _j = 0; _j < 4; _j++) {                                         \
            int _f = tid * 4 + _j;                                               \
            int _r = _f >> 4, _c = _f & 15;                                      \
            uint32_t _d = _r * 272 + _c * 16;                                    \
            cpa16(_kb + _d,          _base + (size_t)_r * 4096 + _c * 8);        \
            cpa16(_kb + FH_KVB + _d, _base + (size_t)_r * 4096 + 2048 + _c * 8); \
        }                                                                        \
        CPA_COMMIT();                                                            \
    } while (0)

#pragma unroll
    for (int j = 0; j < 8; j++) {
        int f = tid * 8 + j;
        int r = f >> 4, c = f & 15;
        cpa16(qbs + r * 272 + c * 16, Qh + (qbase + r) * 2048 + h * 128 + c * 8);
    }
    CPA_COMMIT();
    FH_KV_ISSUE(0);
    CPA_WAIT(1);
    __syncthreads();

    uint32_t qf[8][4];
#pragma unroll
    for (int kc = 0; kc < 8; kc++)
        ldsm4(qf[kc], qbs + (qrow0 + lr) * 272 + (2 * kc + lc) * 16);

    float m0 = -1e30f, m1 = -1e30f, l0 = 0.f, l1 = 0.f;
    float o[16][4];
#pragma unroll
    for (int nt = 0; nt < 16; nt++)
#pragma unroll
        for (int r = 0; r < 4; r++) o[nt][r] = 0.f;

    const int nkt = 2 * qt + 2;
    for (int kt = 0; kt < nkt; kt++) {
        if (kt + 1 < nkt) { FH_KV_ISSUE(kt + 1); CPA_WAIT(1); }
        else              { CPA_WAIT(0); }
        __syncthreads();
        const uint32_t kbs = (kt & 1) ? kvb1 : kvb0;
        const uint32_t vbs = kbs + FH_KVB;

        float s[8][4];
#pragma unroll
        for (int nt = 0; nt < 8; nt++)
#pragma unroll
            for (int r = 0; r < 4; r++) s[nt][r] = 0.f;
#pragma unroll
        for (int ks = 0; ks < 8; ks++) {
            uint32_t bf[4][4];
#pragma unroll
            for (int p = 0; p < 4; p++)
                ldsm4(bf[p], kbs + (p * 16 + lr) * 272 + (2 * ks + lc) * 16);
#pragma unroll
            for (int nt = 0; nt < 8; nt++) {
                int p = nt >> 1, ss = nt & 1;
                mma16(s[nt], qf[ks], bf[p][ss], bf[p][ss + 2]);
            }
        }

        const int qg0 = qt * 128 + qrow0 + g, qg1 = qg0 + 8;
        float mx0 = -1e30f, mx1 = -1e30f;
#pragma unroll
        for (int nt = 0; nt < 8; nt++) {
            int kg0 = kt * 64 + nt * 8 + 2 * tig, kg1 = kg0 + 1;
            s[nt][0] = (kg0 <= qg0) ? s[nt][0] * QK_SCALE : -1e30f;
            s[nt][1] = (kg1 <= qg0) ? s[nt][1] * QK_SCALE : -1e30f;
            s[nt][2] = (kg0 <= qg1) ? s[nt][2] * QK_SCALE : -1e30f;
            s[nt][3] = (kg1 <= qg1) ? s[nt][3] * QK_SCALE : -1e30f;
            mx0 = fmaxf(mx0, fmaxf(s[nt][0], s[nt][1]));
            mx1 = fmaxf(mx1, fmaxf(s[nt][2], s[nt][3]));
        }
        mx0 = fmaxf(mx0, __shfl_xor_sync(0xffffffffu, mx0, 1));
        mx0 = fmaxf(mx0, __shfl_xor_sync(0xffffffffu, mx0, 2));
        mx1 = fmaxf(mx1, __shfl_xor_sync(0xffffffffu, mx1, 1));
        mx1 = fmaxf(mx1, __shfl_xor_sync(0xffffffffu, mx1, 2));
        float nm0 = fmaxf(m0, mx0), nm1 = fmaxf(m1, mx1);
        float sc0 = __expf(m0 - nm0), sc1 = __expf(m1 - nm1);
        m0 = nm0; m1 = nm1;

        float sum0 = 0.f, sum1 = 0.f;
        uint32_t pa[8][2];
#pragma unroll
        for (int nt = 0; nt < 8; nt++) {
            float p0 = __expf(s[nt][0] - nm0), p1 = __expf(s[nt][1] - nm0);
            float p2 = __expf(s[nt][2] - nm1), p3 = __expf(s[nt][3] - nm1);
            sum0 += p0 + p1; sum1 += p2 + p3;
            pa[nt][0] = h2u(__floats2half2_rn(p0, p1));
            pa[nt][1] = h2u(__floats2half2_rn(p2, p3));
        }
        sum0 += __shfl_xor_sync(0xffffffffu, sum0, 1);
        sum0 += __shfl_xor_sync(0xffffffffu, sum0, 2);
        sum1 += __shfl_xor_sync(0xffffffffu, sum1, 1);
        sum1 += __shfl_xor_sync(0xffffffffu, sum1, 2);
        l0 = l0 * sc0 + sum0;
        l1 = l1 * sc1 + sum1;

#pragma unroll
        for (int nt = 0; nt < 16; nt++) {
            o[nt][0] *= sc0; o[nt][1] *= sc0;
            o[nt][2] *= sc1; o[nt][3] *= sc1;
        }
#pragma unroll
        for (int kc = 0; kc < 4; kc++) {
            uint32_t paf[4] = { pa[2 * kc][0], pa[2 * kc][1],
                                pa[2 * kc + 1][0], pa[2 * kc + 1][1] };
#pragma unroll
            for (int j = 0; j < 8; j++) {
                uint32_t bf[4];
                ldsm4t(bf, vbs + (kc * 16 + lr) * 272 + (2 * j + lc) * 16);
                mma16(o[2 * j],     paf, bf[0], bf[1]);
                mma16(o[2 * j + 1], paf, bf[2], bf[3]);
            }
        }
        __syncthreads();
    }

    float inv0 = 1.f / l0, inv1 = 1.f / l1;
#pragma unroll
    for (int nt = 0; nt < 16; nt++) {
        int c0 = nt * 8 + 2 * tig;
        *(__half2*)(O + (qbase + qrow0 + g) * 2048 + h * 128 + c0) =
            __floats2half2_rn(o[nt][0] * inv0, o[nt][1] * inv0);
        *(__half2*)(O + (qbase + qrow0 + g + 8) * 2048 + h * 128 + c0) =
            __floats2half2_rn(o[nt][2] * inv1, o[nt][3] * inv1);
    }
}

// ---------------- launcher -------------------------------------------------
extern "C" void kernel_launch(void* const* d_in, const int* in_sizes, int n_in,
                              void* d_out, int out_size)
{
    const float* x     = (const float*)d_in[0];
    const float* cosT  = (const float*)d_in[1];
    const float* sinT  = (const float*)d_in[2];
    const float* Wq_s  = (const float*)d_in[3];
    const float* qs_w  = (const float*)d_in[4];
    const float* Wkv_s = (const float*)d_in[5];
    const float* kvs_w = (const float*)d_in[6];
    const float* Wq_p  = (const float*)d_in[7];
    const float* Wkv_p = (const float*)d_in[8];
    const float* Wg_p  = (const float*)d_in[9];
    const float* Wo_p  = (const float*)d_in[10];
    const float* o_w   = (const float*)d_in[11];
    const float* Wo_s  = (const float*)d_in[12];
    float* out = (float*)d_out;

    float *qskvs, *o;
    __half *xh, *qsh, *kvsh, *qh, *kvh, *gatesh, *attnh, *oh;
    __half *wqkvs_h, *wqp_h, *wkvp_h, *wgp_h, *wop_h, *wos_h;
    cudaGetSymbolAddress((void**)&qskvs,  g_qskvs);
    cudaGetSymbolAddress((void**)&o,      g_o);
    cudaGetSymbolAddress((void**)&xh,     g_xh);
    cudaGetSymbolAddress((void**)&qsh,    g_qsh);
    cudaGetSymbolAddress((void**)&kvsh,   g_kvsh);
    cudaGetSymbolAddress((void**)&qh,     g_qh);
    cudaGetSymbolAddress((void**)&kvh,    g_kvh);
    cudaGetSymbolAddress((void**)&gatesh, g_gatesh);
    cudaGetSymbolAddress((void**)&attnh,  g_attnh);
    cudaGetSymbolAddress((void**)&oh,     g_oh);
    cudaGetSymbolAddress((void**)&wqkvs_h, g_wqkvs_h);
    cudaGetSymbolAddress((void**)&wqp_h,  g_wqp_h);
    cudaGetSymbolAddress((void**)&wkvp_h, g_wkvp_h);
    cudaGetSymbolAddress((void**)&wgp_h,  g_wgp_h);
    cudaGetSymbolAddress((void**)&wop_h,  g_wop_h);
    cudaGetSymbolAddress((void**)&wos_h,  g_wos_h);

    cudaFuncSetAttribute(flash_h16, cudaFuncAttributeMaxDynamicSharedMemorySize, FH_SMEM_BYTES);
    cudaFuncSetAttribute(gemm_h<0>, cudaFuncAttributeMaxDynamicSharedMemorySize, GH_SMEM_BYTES);
    cudaFuncSetAttribute(gemm_h<1>, cudaFuncAttributeMaxDynamicSharedMemorySize, GH_SMEM_BYTES);
    cudaFuncSetAttribute(gemm_h<2>, cudaFuncAttributeMaxDynamicSharedMemorySize, GH_SMEM_BYTES);
    cudaFuncSetAttribute(gemm_h<3>, cudaFuncAttributeMaxDynamicSharedMemorySize, GH_SMEM_BYTES);
    cudaFuncSetAttribute(gemm64, cudaFuncAttributeMaxDynamicSharedMemorySize, G64_SMEM_BYTES);

    dim3 blk(256);
    cvt_all<<<CV_BLOCKS, 256>>>(x, Wq_s, Wkv_s, Wq_p, Wkv_p, Wg_p, Wo_p, Wo_s,
                                xh, wqkvs_h, wqkvs_h + (size_t)D_CQ * HIDD,
                                wqp_h, wkvp_h, wgp_h, wop_h, wos_h);

    // merged shared projection (qs | kvs), 64-row tiles -> 640 blocks
    gemm64<<<dim3(D_QKVS / 128, NTOK / 64), dim3(128), G64_SMEM_BYTES>>>(
        xh, wqkvs_h, qskvs, D_QKVS, HIDD);
    rms_rows<<<NTOK, 256>>>(qskvs,        qs_w,  D_CQ,  D_QKVS, qsh);
    rms_rows<<<NTOK, 256>>>(qskvs + D_CQ, kvs_w, D_CKV, D_QKVS, kvsh);

    // gates first (consumed by kvp epilogue)
    gemm_h<1><<<dim3(2048 / 128, NTOK / 128), blk, GH_SMEM_BYTES>>>(
        xh, wgp_h, gatesh, 2048, HIDD, 0, 0, 0);
    // q projection + fused rope
    gemm_h<2><<<dim3(2048 / 128, NTOK / 128), blk, GH_SMEM_BYTES>>>(
        qsh, wqp_h, qh, 2048, D_CQ, cosT, sinT, 0);
    // kv projection + fused rope(k) + gate(v)
    gemm_h<3><<<dim3(4096 / 128, NTOK / 128), blk, GH_SMEM_BYTES>>>(
        kvsh, wkvp_h, kvh, 4096, D_CKV, cosT, sinT, gatesh);

    flash_h16<<<dim3(TSEQ / 128, NH, 2), blk, FH_SMEM_BYTES>>>(qh, kvh, attnh);

    // o projection, 64-row tiles -> 256 blocks
    gemm64<<<dim3(D_CO / 128, NTOK / 64), dim3(128), G64_SMEM_BYTES>>>(
        attnh, wop_h, o, D_CO, 2048);
    rms_rows<<<NTOK, 256>>>(o, o_w, D_CO, D_CO, oh);
    gemm_h<0><<<dim3(HIDD / 128, NTOK / 128), blk, GH_SMEM_BYTES>>>(
        oh, wos_h, out, HIDD, D_CO, 0, 0, 0);
}

// round 13
// speedup vs baseline: 5.7613x; 1.0269x over previous
#include <cuda_runtime.h>
#include <cuda_fp16.h>
#include <math.h>
#include <stdint.h>

// ---------------- problem constants ----------------
#define NTOK 4096      // B*T
#define TSEQ 2048
#define HIDD 2048
#define NH   16
#define DHEAD 128
#define RROT 32
#define D_CQ 768
#define D_CKV 512
#define D_CO 512
#define D_QKVS 1280    // D_CQ + D_CKV
#define QK_SCALE 0.08838834764831845f  // 128^-0.5

// ---------------- scratch ----------------
__device__ float g_qskvs[(size_t)NTOK * D_QKVS];   // qs | kvs (fp32, pre-rms)
__device__ float g_o[(size_t)NTOK * D_CO];
__device__ __half g_xh[(size_t)NTOK * HIDD];
__device__ __half g_qsh[(size_t)NTOK * D_CQ];
__device__ __half g_kvsh[(size_t)NTOK * D_CKV];
__device__ __half g_qh[(size_t)NTOK * 2048];
__device__ __half g_kvh[(size_t)NTOK * 4096];   // k | v
__device__ __half g_gatesh[(size_t)NTOK * 2048];
__device__ __half g_attnh[(size_t)NTOK * 2048];
__device__ __half g_oh[(size_t)NTOK * D_CO];
__device__ __half g_wqkvs_h[(size_t)D_QKVS * HIDD];  // wqs | wkvs
__device__ __half g_wqp_h[(size_t)2048 * D_CQ];
__device__ __half g_wkvp_h[(size_t)4096 * D_CKV];
__device__ __half g_wgp_h[(size_t)2048 * HIDD];
__device__ __half g_wop_h[(size_t)D_CO * 2048];
__device__ __half g_wos_h[(size_t)HIDD * D_CO];

// ---------------- helpers ----------------
__device__ __forceinline__ uint32_t smem_u32(const void* p) {
    uint32_t a;
    asm("{ .reg .u64 t; cvta.to.shared.u64 t, %1; cvt.u32.u64 %0, t; }" : "=r"(a) : "l"(p));
    return a;
}
__device__ __forceinline__ void mma16(float c[4], const uint32_t a[4], uint32_t b0, uint32_t b1) {
    asm volatile(
        "mma.sync.aligned.m16n8k16.row.col.f32.f16.f16.f32 "
        "{%0,%1,%2,%3},{%4,%5,%6,%7},{%8,%9},{%0,%1,%2,%3};"
        : "+f"(c[0]), "+f"(c[1]), "+f"(c[2]), "+f"(c[3])
        : "r"(a[0]), "r"(a[1]), "r"(a[2]), "r"(a[3]), "r"(b0), "r"(b1));
}
__device__ __forceinline__ void ldsm4(uint32_t* r, uint32_t a) {
    asm volatile("ldmatrix.sync.aligned.m8n8.x4.shared.b16 {%0,%1,%2,%3}, [%4];"
        : "=r"(r[0]), "=r"(r[1]), "=r"(r[2]), "=r"(r[3]) : "r"(a));
}
__device__ __forceinline__ void ldsm4t(uint32_t* r, uint32_t a) {
    asm volatile("ldmatrix.sync.aligned.m8n8.x4.trans.shared.b16 {%0,%1,%2,%3}, [%4];"
        : "=r"(r[0]), "=r"(r[1]), "=r"(r[2]), "=r"(r[3]) : "r"(a));
}
__device__ __forceinline__ void cpa16(uint32_t saddr, const void* g) {
    asm volatile("cp.async.cg.shared.global [%0], [%1], 16;" :: "r"(saddr), "l"(g));
}
#define CPA_COMMIT() asm volatile("cp.async.commit_group;" ::: "memory")
#define CPA_WAIT(n)  asm volatile("cp.async.wait_group %0;" :: "n"(n) : "memory")
__device__ __forceinline__ uint32_t h2u(__half2 h) {
    uint32_t u;
    asm("mov.b32 %0, %1;" : "=r"(u) : "r"(*(uint32_t*)&h));
    return u;
}

// ---------------- merged fp32 -> fp16 convert (x + 7 weights) -------------
#define CV_P1 8388608u             // x
#define CV_P2 (CV_P1 + 1572864u)   // wqs  -> wqkvs[0:768)
#define CV_P3 (CV_P2 + 1048576u)   // wkvs -> wqkvs[768:1280)
#define CV_P4 (CV_P3 + 1572864u)   // wqp
#define CV_P5 (CV_P4 + 2097152u)   // wkvp
#define CV_P6 (CV_P5 + 4194304u)   // wgp
#define CV_P7 (CV_P6 + 1048576u)   // wop
#define CV_END (CV_P7 + 1048576u)  // wos
#define CV_BLOCKS (CV_END / 1024)

__global__ void cvt_all(
    const float* __restrict__ s0, const float* __restrict__ s1,
    const float* __restrict__ s2, const float* __restrict__ s3,
    const float* __restrict__ s4, const float* __restrict__ s5,
    const float* __restrict__ s6, const float* __restrict__ s7,
    __half* __restrict__ d0, __half* __restrict__ d1,
    __half* __restrict__ d2, __half* __restrict__ d3,
    __half* __restrict__ d4, __half* __restrict__ d5,
    __half* __restrict__ d6, __half* __restrict__ d7)
{
    uint32_t i = (blockIdx.x * 256 + threadIdx.x) * 4;
    const float* s; __half* d; uint32_t off;
    if      (i < CV_P1) { s = s0; d = d0; off = i; }
    else if (i < CV_P2) { s = s1; d = d1; off = i - CV_P1; }
    else if (i < CV_P3) { s = s2; d = d2; off = i - CV_P2; }
    else if (i < CV_P4) { s = s3; d = d3; off = i - CV_P3; }
    else if (i < CV_P5) { s = s4; d = d4; off = i - CV_P4; }
    else if (i < CV_P6) { s = s5; d = d5; off = i - CV_P5; }
    else if (i < CV_P7) { s = s6; d = d6; off = i - CV_P6; }
    else                { s = s7; d = d7; off = i - CV_P7; }
    float4 v = *(const float4*)(s + off);
    __half2* o = (__half2*)(d + off);
    o[0] = __floats2half2_rn(v.x, v.y);
    o[1] = __floats2half2_rn(v.z, v.w);
}

// ---------------- fp16 GEMM 128x128 (verified R8) --------------------------
// MODE 0: fp32 out. MODE 1: fp16 out. MODE 2: fp16 + RoPE (q layout).
// MODE 3: fp16 + RoPE on k (bn<2048) + silu-gate on v (bn>=2048).
#define GH_SMEM_BYTES (3 * 16384)

template <int MODE>
__global__ __launch_bounds__(256, 2) void gemm_h(
    const __half* __restrict__ A, const __half* __restrict__ B, void* __restrict__ Cv,
    int N, int K,
    const float* __restrict__ cosT, const float* __restrict__ sinT,
    const __half* __restrict__ gates)
{
    extern __shared__ char hsm[];
    const uint32_t shb = smem_u32(hsm);
    const int tid = threadIdx.x, lane = tid & 31, w = tid >> 5;
    const int g = lane >> 2, tig = lane & 3;
    const int wm = (w & 3) * 32, wn = (w >> 2) * 64;
    const int bm = blockIdx.y * 128, bn = blockIdx.x * 128;
    const int lr = lane & 15, lc = lane >> 4;

    float acc[2][8][4];
#pragma unroll
    for (int mt = 0; mt < 2; mt++)
#pragma unroll
        for (int nt = 0; nt < 8; nt++)
#pragma unroll
            for (int r = 0; r < 4; r++) acc[mt][nt][r] = 0.f;

    const int srow = tid >> 1, shalf = tid & 1;
    const __half* pa = A + (size_t)(bm + srow) * K + shalf * 16;
    const __half* pb = B + (size_t)(bn + srow) * K + shalf * 16;
    const uint32_t da0 = srow * 64 + ((((shalf * 2 + 0) + (srow >> 1)) & 3) << 4);
    const uint32_t da1 = srow * 64 + ((((shalf * 2 + 1) + (srow >> 1)) & 3) << 4);

    const int ntile = K >> 5;
#define GH_ISSUE(t) do {                                       \
        uint32_t _b = shb + ((t) % 3) * 16384;                 \
        const __half* _a = pa + (size_t)(t) * 32;              \
        const __half* _bb = pb + (size_t)(t) * 32;             \
        cpa16(_b + da0, _a);                                   \
        cpa16(_b + da1, _a + 8);                               \
        cpa16(_b + 8192 + da0, _bb);                           \
        cpa16(_b + 8192 + da1, _bb + 8);                       \
        CPA_COMMIT();                                          \
    } while (0)

    GH_ISSUE(0);
    GH_ISSUE(1);

    for (int i = 0; i < ntile; i++) {
        if (i < ntile - 1) { CPA_WAIT(1); } else { CPA_WAIT(0); }
        __syncthreads();
        if (i + 2 < ntile) GH_ISSUE(i + 2);
        const uint32_t base = shb + (i % 3) * 16384;
#pragma unroll
        for (int ks = 0; ks < 2; ks++) {
            const int cb = 2 * ks + lc;
            uint32_t af[2][4], bf[4][4];
#pragma unroll
            for (int mt = 0; mt < 2; mt++) {
                int r = wm + mt * 16 + lr;
                ldsm4(af[mt], base + r * 64 + (((cb + (r >> 1)) & 3) << 4));
            }
#pragma unroll
            for (int p = 0; p < 4; p++) {
                int r = wn + p * 16 + lr;
                ldsm4(bf[p], base + 8192 + r * 64 + (((cb + (r >> 1)) & 3) << 4));
            }
#pragma unroll
            for (int mt = 0; mt < 2; mt++)
#pragma unroll
                for (int nt = 0; nt < 8; nt++) {
                    int p = nt >> 1, s = nt & 1;
                    mma16(acc[mt][nt], af[mt], bf[p][s], bf[p][s + 2]);
                }
        }
        __syncthreads();
    }

    // -------- fused epilogue transforms --------
    if ((MODE == 2 || (MODE == 3 && bn < 2048)) && wn == 0) {
#pragma unroll
        for (int mt = 0; mt < 2; mt++) {
            int r0 = bm + wm + mt * 16 + g;
            int t0 = r0 & (TSEQ - 1), t1 = (r0 + 8) & (TSEQ - 1);
#pragma unroll
            for (int nt = 0; nt < 2; nt++) {
                int d = nt * 8 + 2 * tig;
                float c0a = cosT[t0 * RROT + d],      c0b = cosT[t0 * RROT + d + 1];
                float c0c = cosT[t0 * RROT + d + 16], c0d = cosT[t0 * RROT + d + 17];
                float s0a = sinT[t0 * RROT + d],      s0b = sinT[t0 * RROT + d + 1];
                float s0c = sinT[t0 * RROT + d + 16], s0d = sinT[t0 * RROT + d + 17];
                float c1a = cosT[t1 * RROT + d],      c1b = cosT[t1 * RROT + d + 1];
                float c1c = cosT[t1 * RROT + d + 16], c1d = cosT[t1 * RROT + d + 17];
                float s1a = sinT[t1 * RROT + d],      s1b = sinT[t1 * RROT + d + 1];
                float s1c = sinT[t1 * RROT + d + 16], s1d = sinT[t1 * RROT + d + 17];
                float x, y;
                x = acc[mt][nt][0]; y = acc[mt][nt + 2][0];
                acc[mt][nt][0] = x * c0a - y * s0a; acc[mt][nt + 2][0] = y * c0c + x * s0c;
                x = acc[mt][nt][1]; y = acc[mt][nt + 2][1];
                acc[mt][nt][1] = x * c0b - y * s0b; acc[mt][nt + 2][1] = y * c0d + x * s0d;
                x = acc[mt][nt][2]; y = acc[mt][nt + 2][2];
                acc[mt][nt][2] = x * c1a - y * s1a; acc[mt][nt + 2][2] = y * c1c + x * s1c;
                x = acc[mt][nt][3]; y = acc[mt][nt + 2][3];
                acc[mt][nt][3] = x * c1b - y * s1b; acc[mt][nt + 2][3] = y * c1d + x * s1d;
            }
        }
    }
    if (MODE == 3 && bn >= 2048) {
#pragma unroll
        for (int mt = 0; mt < 2; mt++) {
            int r0 = bm + wm + mt * 16 + g;
#pragma unroll
            for (int nt = 0; nt < 8; nt++) {
                int cg = bn - 2048 + wn + nt * 8 + 2 * tig;
                __half2 ga = *(const __half2*)(gates + (size_t)r0 * 2048 + cg);
                __half2 gb = *(const __half2*)(gates + (size_t)(r0 + 8) * 2048 + cg);
                float g0 = __low2float(ga), g1 = __high2float(ga);
                float g2 = __low2float(gb), g3 = __high2float(gb);
                acc[mt][nt][0] *= g0 / (1.f + __expf(-g0));
                acc[mt][nt][1] *= g1 / (1.f + __expf(-g1));
                acc[mt][nt][2] *= g2 / (1.f + __expf(-g2));
                acc[mt][nt][3] *= g3 / (1.f + __expf(-g3));
            }
        }
    }

#pragma unroll
    for (int mt = 0; mt < 2; mt++) {
        int r0 = bm + wm + mt * 16 + g;
#pragma unroll
        for (int nt = 0; nt < 8; nt++) {
            int c0 = bn + wn + nt * 8 + 2 * tig;
            if (MODE == 0) {
                float* C = (float*)Cv;
                *(float2*)(C + (size_t)r0 * N + c0)       = make_float2(acc[mt][nt][0], acc[mt][nt][1]);
                *(float2*)(C + (size_t)(r0 + 8) * N + c0) = make_float2(acc[mt][nt][2], acc[mt][nt][3]);
            } else {
                __half* C = (__half*)Cv;
                *(__half2*)(C + (size_t)r0 * N + c0)       = __floats2half2_rn(acc[mt][nt][0], acc[mt][nt][1]);
                *(__half2*)(C + (size_t)(r0 + 8) * N + c0) = __floats2half2_rn(acc[mt][nt][2], acc[mt][nt][3]);
            }
        }
    }
}

// ---------------- fp16 GEMM 64x128, 128 threads, 4 CTAs/SM -----------------
#define G64_STG 12288            // (64+128) rows * 64 B
#define G64_SMEM_BYTES (3 * G64_STG)

__global__ __launch_bounds__(128, 4) void gemm64(
    const __half* __restrict__ A, const __half* __restrict__ B, float* __restrict__ C,
    int N, int K)
{
    extern __shared__ char hsm[];
    const uint32_t shb = smem_u32(hsm);
    const int tid = threadIdx.x, lane = tid & 31, w = tid >> 5;
    const int g = lane >> 2, tig = lane & 3;
    const int wm = (w & 1) * 32, wn = (w >> 1) * 64;
    const int bm = blockIdx.y * 64, bn = blockIdx.x * 128;
    const int lr = lane & 15, lc = lane >> 4;

    float acc[2][8][4];
#pragma unroll
    for (int mt = 0; mt < 2; mt++)
#pragma unroll
        for (int nt = 0; nt < 8; nt++)
#pragma unroll
            for (int r = 0; r < 4; r++) acc[mt][nt][r] = 0.f;

    const int ntile = K >> 5;
#define G64_ISSUE(t) do {                                                        \
        uint32_t _b = shb + ((t) % 3) * G64_STG;                                 \
        _Pragma("unroll")                                                        \
        for (int _j = 0; _j < 6; _j++) {                                         \
            int _f = _j * 128 + tid;                                             \
            int _r = _f >> 2, _c = _f & 3;                                       \
            uint32_t _d = _b + _r * 64 + (((_c + (_r >> 1)) & 3) << 4);          \
            const __half* _g = (_r < 64)                                         \
                ? A + (size_t)(bm + _r) * K + (size_t)(t) * 32 + _c * 8          \
                : B + (size_t)(bn + _r - 64) * K + (size_t)(t) * 32 + _c * 8;    \
            cpa16(_d, _g);                                                       \
        }                                                                        \
        CPA_COMMIT();                                                            \
    } while (0)

    G64_ISSUE(0);
    G64_ISSUE(1);

    for (int i = 0; i < ntile; i++) {
        if (i < ntile - 1) { CPA_WAIT(1); } else { CPA_WAIT(0); }
        __syncthreads();
        if (i + 2 < ntile) G64_ISSUE(i + 2);
        const uint32_t base = shb + (i % 3) * G64_STG;
#pragma unroll
        for (int ks = 0; ks < 2; ks++) {
            const int cb = 2 * ks + lc;
            uint32_t af[2][4], bf[4][4];
#pragma unroll
            for (int mt = 0; mt < 2; mt++) {
                int r = wm + mt * 16 + lr;
                ldsm4(af[mt], base + r * 64 + (((cb + (r >> 1)) & 3) << 4));
            }
#pragma unroll
            for (int p = 0; p < 4; p++) {
                int r = 64 + wn + p * 16 + lr;
                ldsm4(bf[p], base + r * 64 + (((cb + (r >> 1)) & 3) << 4));
            }
#pragma unroll
            for (int mt = 0; mt < 2; mt++)
#pragma unroll
                for (int nt = 0; nt < 8; nt++) {
                    int p = nt >> 1, s = nt & 1;
                    mma16(acc[mt][nt], af[mt], bf[p][s], bf[p][s + 2]);
                }
        }
        __syncthreads();
    }

#pragma unroll
    for (int mt = 0; mt < 2; mt++) {
        int r0 = bm + wm + mt * 16 + g;
#pragma unroll
        for (int nt = 0; nt < 8; nt++) {
            int c0 = bn + wn + nt * 8 + 2 * tig;
            *(float2*)(C + (size_t)r0 * N + c0)       = make_float2(acc[mt][nt][0], acc[mt][nt][1]);
            *(float2*)(C + (size_t)(r0 + 8) * N + c0) = make_float2(acc[mt][nt][2], acc[mt][nt][3]);
        }
    }
}

// ---------------- RMSNorm: read fp32 (strided), write fp16 ------------------
__global__ void rms_rows(const float* __restrict__ X, const float* __restrict__ w,
                         int D, int strideX, __half* __restrict__ H)
{
    __shared__ float red[8];
    const int row = blockIdx.x, tid = threadIdx.x;
    const int lane = tid & 31, wid = tid >> 5;
    const float* x = X + (size_t)row * strideX;
    __half* hh = H + (size_t)row * D;
    float ss = 0.f;
    for (int i = tid; i < D; i += 256) { float v = x[i]; ss += v * v; }
#pragma unroll
    for (int m = 16; m > 0; m >>= 1) ss += __shfl_xor_sync(0xffffffff, ss, m);
    if (lane == 0) red[wid] = ss;
    __syncthreads();
    float tot = 0.f;
#pragma unroll
    for (int j = 0; j < 8; j++) tot += red[j];
    float inv = rsqrtf(tot / (float)D + 1e-6f);
    for (int i = tid; i < D; i += 256)
        hh[i] = __float2half_rn(w[i] * (x[i] * inv));
}

// ---------------- flash attention (verified R10) ---------------------------
#define FH_QB 34816u
#define FH_KVB 17408u
#define FH_SMEM_BYTES (FH_QB + 4 * FH_KVB)

__global__ __launch_bounds__(256) void flash_h16(
    const __half* __restrict__ Qh, const __half* __restrict__ KVh, __half* __restrict__ O)
{
    extern __shared__ __half sh2[];
    const uint32_t qbs = smem_u32(sh2);
    const uint32_t kvb0 = qbs + FH_QB;
    const uint32_t kvb1 = qbs + FH_QB + 2 * FH_KVB;

    const int qt = (int)gridDim.x - 1 - blockIdx.x;   // LPT
    const int h = blockIdx.y, b = blockIdx.z;
    const int tid = threadIdx.x, lane = tid & 31, w = tid >> 5;
    const int g = lane >> 2, tig = lane & 3;
    const int lr = lane & 15, lc = lane >> 4;
    const int qrow0 = w * 16;
    const size_t qbase = (size_t)b * TSEQ + qt * 128;
    const size_t kvrow = (size_t)b * TSEQ;

#define FH_KV_ISSUE(kt) do {                                                     \
        const uint32_t _kb = ((kt) & 1) ? kvb1 : kvb0;                           \
        const __half* _base = KVh + (kvrow + (size_t)(kt) * 64) * 4096 + h * 128;\
        _Pragma("unroll")                                                        \
        for (int _j = 0; _j < 4; _j++) {                                         \
            int _f = tid * 4 + _j;                                               \
            int _r = _f >> 4, _c = _f & 15;                                      \
            uint32_t _d = _r * 272 + _c * 16;                                    \
            cpa16(_kb + _d,          _base + (size_t)_r * 4096 + _c * 8);        \
            cpa16(_kb + FH_KVB + _d, _base + (size_t)_r * 4096 + 2048 + _c * 8); \
        }                                                                        \
        CPA_COMMIT();                                                            \
    } while (0)

#pragma unroll
    for (int j = 0; j < 8; j++) {
        int f = tid * 8 + j;
        int r = f >> 4, c = f & 15;
        cpa16(qbs + r * 272 + c * 16, Qh + (qbase + r) * 2048 + h * 128 + c * 8);
    }
    CPA_COMMIT();
    FH_KV_ISSUE(0);
    CPA_WAIT(1);
    __syncthreads();

    uint32_t qf[8][4];
#pragma unroll
    for (int kc = 0; kc < 8; kc++)
        ldsm4(qf[kc], qbs + (qrow0 + lr) * 272 + (2 * kc + lc) * 16);

    float m0 = -1e30f, m1 = -1e30f, l0 = 0.f, l1 = 0.f;
    float o[16][4];
#pragma unroll
    for (int nt = 0; nt < 16; nt++)
#pragma unroll
        for (int r = 0; r < 4; r++) o[nt][r] = 0.f;

    const int nkt = 2 * qt + 2;
    for (int kt = 0; kt < nkt; kt++) {
        if (kt + 1 < nkt) { FH_KV_ISSUE(kt + 1); CPA_WAIT(1); }
        else              { CPA_WAIT(0); }
        __syncthreads();
        const uint32_t kbs = (kt & 1) ? kvb1 : kvb0;
        const uint32_t vbs = kbs + FH_KVB;

        float s[8][4];
#pragma unroll
        for (int nt = 0; nt < 8; nt++)
#pragma unroll
            for (int r = 0; r < 4; r++) s[nt][r] = 0.f;
#pragma unroll
        for (int ks = 0; ks < 8; ks++) {
            uint32_t bf[4][4];
#pragma unroll
            for (int p = 0; p < 4; p++)
                ldsm4(bf[p], kbs + (p * 16 + lr) * 272 + (2 * ks + lc) * 16);
#pragma unroll
            for (int nt = 0; nt < 8; nt++) {
                int p = nt >> 1, ss = nt & 1;
                mma16(s[nt], qf[ks], bf[p][ss], bf[p][ss + 2]);
            }
        }

        const int qg0 = qt * 128 + qrow0 + g, qg1 = qg0 + 8;
        float mx0 = -1e30f, mx1 = -1e30f;
#pragma unroll
        for (int nt = 0; nt < 8; nt++) {
            int kg0 = kt * 64 + nt * 8 + 2 * tig, kg1 = kg0 + 1;
            s[nt][0] = (kg0 <= qg0) ? s[nt][0] * QK_SCALE : -1e30f;
            s[nt][1] = (kg1 <= qg0) ? s[nt][1] * QK_SCALE : -1e30f;
            s[nt][2] = (kg0 <= qg1) ? s[nt][2] * QK_SCALE : -1e30f;
            s[nt][3] = (kg1 <= qg1) ? s[nt][3] * QK_SCALE : -1e30f;
            mx0 = fmaxf(mx0, fmaxf(s[nt][0], s[nt][1]));
            mx1 = fmaxf(mx1, fmaxf(s[nt][2], s[nt][3]));
        }
        mx0 = fmaxf(mx0, __shfl_xor_sync(0xffffffffu, mx0, 1));
        mx0 = fmaxf(mx0, __shfl_xor_sync(0xffffffffu, mx0, 2));
        mx1 = fmaxf(mx1, __shfl_xor_sync(0xffffffffu, mx1, 1));
        mx1 = fmaxf(mx1, __shfl_xor_sync(0xffffffffu, mx1, 2));
        float nm0 = fmaxf(m0, mx0), nm1 = fmaxf(m1, mx1);
        float sc0 = __expf(m0 - nm0), sc1 = __expf(m1 - nm1);
        m0 = nm0; m1 = nm1;

        float sum0 = 0.f, sum1 = 0.f;
        uint32_t pa[8][2];
#pragma unroll
        for (int nt = 0; nt < 8; nt++) {
            float p0 = __expf(s[nt][0] - nm0), p1 = __expf(s[nt][1] - nm0);
            float p2 = __expf(s[nt][2] - nm1), p3 = __expf(s[nt][3] - nm1);
            sum0 += p0 + p1; sum1 += p2 + p3;
            pa[nt][0] = h2u(__floats2half2_rn(p0, p1));
            pa[nt][1] = h2u(__floats2half2_rn(p2, p3));
        }
        sum0 += __shfl_xor_sync(0xffffffffu, sum0, 1);
        sum0 += __shfl_xor_sync(0xffffffffu, sum0, 2);
        sum1 += __shfl_xor_sync(0xffffffffu, sum1, 1);
        sum1 += __shfl_xor_sync(0xffffffffu, sum1, 2);
        l0 = l0 * sc0 + sum0;
        l1 = l1 * sc1 + sum1;

#pragma unroll
        for (int nt = 0; nt < 16; nt++) {
            o[nt][0] *= sc0; o[nt][1] *= sc0;
            o[nt][2] *= sc1; o[nt][3] *= sc1;
        }
#pragma unroll
        for (int kc = 0; kc < 4; kc++) {
            uint32_t paf[4] = { pa[2 * kc][0], pa[2 * kc][1],
                                pa[2 * kc + 1][0], pa[2 * kc + 1][1] };
#pragma unroll
            for (int j = 0; j < 8; j++) {
                uint32_t bf[4];
                ldsm4t(bf, vbs + (kc * 16 + lr) * 272 + (2 * j + lc) * 16);
                mma16(o[2 * j],     paf, bf[0], bf[1]);
                mma16(o[2 * j + 1], paf, bf[2], bf[3]);
            }
        }
        __syncthreads();
    }

    float inv0 = 1.f / l0, inv1 = 1.f / l1;
#pragma unroll
    for (int nt = 0; nt < 16; nt++) {
        int c0 = nt * 8 + 2 * tig;
        *(__half2*)(O + (qbase + qrow0 + g) * 2048 + h * 128 + c0) =
            __floats2half2_rn(o[nt][0] * inv0, o[nt][1] * inv0);
        *(__half2*)(O + (qbase + qrow0 + g + 8) * 2048 + h * 128 + c0) =
            __floats2half2_rn(o[nt][2] * inv1, o[nt][3] * inv1);
    }
}

// ---------------- launcher -------------------------------------------------
extern "C" void kernel_launch(void* const* d_in, const int* in_sizes, int n_in,
                              void* d_out, int out_size)
{
    const float* x     = (const float*)d_in[0];
    const float* cosT  = (const float*)d_in[1];
    const float* sinT  = (const float*)d_in[2];
    const float* Wq_s  = (const float*)d_in[3];
    const float* qs_w  = (const float*)d_in[4];
    const float* Wkv_s = (const float*)d_in[5];
    const float* kvs_w = (const float*)d_in[6];
    const float* Wq_p  = (const float*)d_in[7];
    const float* Wkv_p = (const float*)d_in[8];
    const float* Wg_p  = (const float*)d_in[9];
    const float* Wo_p  = (const float*)d_in[10];
    const float* o_w   = (const float*)d_in[11];
    const float* Wo_s  = (const float*)d_in[12];
    float* out = (float*)d_out;

    float *qskvs, *o;
    __half *xh, *qsh, *kvsh, *qh, *kvh, *gatesh, *attnh, *oh;
    __half *wqkvs_h, *wqp_h, *wkvp_h, *wgp_h, *wop_h, *wos_h;
    cudaGetSymbolAddress((void**)&qskvs,  g_qskvs);
    cudaGetSymbolAddress((void**)&o,      g_o);
    cudaGetSymbolAddress((void**)&xh,     g_xh);
    cudaGetSymbolAddress((void**)&qsh,    g_qsh);
    cudaGetSymbolAddress((void**)&kvsh,   g_kvsh);
    cudaGetSymbolAddress((void**)&qh,     g_qh);
    cudaGetSymbolAddress((void**)&kvh,    g_kvh);
    cudaGetSymbolAddress((void**)&gatesh, g_gatesh);
    cudaGetSymbolAddress((void**)&attnh,  g_attnh);
    cudaGetSymbolAddress((void**)&oh,     g_oh);
    cudaGetSymbolAddress((void**)&wqkvs_h, g_wqkvs_h);
    cudaGetSymbolAddress((void**)&wqp_h,  g_wqp_h);
    cudaGetSymbolAddress((void**)&wkvp_h, g_wkvp_h);
    cudaGetSymbolAddress((void**)&wgp_h,  g_wgp_h);
    cudaGetSymbolAddress((void**)&wop_h,  g_wop_h);
    cudaGetSymbolAddress((void**)&wos_h,  g_wos_h);

    cudaFuncSetAttribute(flash_h16, cudaFuncAttributeMaxDynamicSharedMemorySize, FH_SMEM_BYTES);
    cudaFuncSetAttribute(gemm_h<0>, cudaFuncAttributeMaxDynamicSharedMemorySize, GH_SMEM_BYTES);
    cudaFuncSetAttribute(gemm_h<1>, cudaFuncAttributeMaxDynamicSharedMemorySize, GH_SMEM_BYTES);
    cudaFuncSetAttribute(gemm_h<2>, cudaFuncAttributeMaxDynamicSharedMemorySize, GH_SMEM_BYTES);
    cudaFuncSetAttribute(gemm_h<3>, cudaFuncAttributeMaxDynamicSharedMemorySize, GH_SMEM_BYTES);
    cudaFuncSetAttribute(gemm64, cudaFuncAttributeMaxDynamicSharedMemorySize, G64_SMEM_BYTES);

    // fork/join streams + events (created per call, intentionally leaked:
    // kernel_launch runs only a handful of times; no device-memory alloc)
    cudaStream_t s1;
    cudaStreamCreateWithFlags(&s1, cudaStreamNonBlocking);
    cudaEvent_t evCvt, evGates;
    cudaEventCreateWithFlags(&evCvt, cudaEventDisableTiming);
    cudaEventCreateWithFlags(&evGates, cudaEventDisableTiming);

    dim3 blk(256);
    cvt_all<<<CV_BLOCKS, 256>>>(x, Wq_s, Wkv_s, Wq_p, Wkv_p, Wg_p, Wo_p, Wo_s,
                                xh, wqkvs_h, wqkvs_h + (size_t)D_CQ * HIDD,
                                wqp_h, wkvp_h, wgp_h, wop_h, wos_h);
    cudaEventRecord(evCvt, 0);

    // s1: gates GEMM, independent of the qkvs chain
    cudaStreamWaitEvent(s1, evCvt, 0);
    gemm_h<1><<<dim3(2048 / 128, NTOK / 128), blk, GH_SMEM_BYTES, s1>>>(
        xh, wgp_h, gatesh, 2048, HIDD, 0, 0, 0);
    cudaEventRecord(evGates, s1);

    // default stream: qkvs projection -> rms -> q projection
    gemm64<<<dim3(D_QKVS / 128, NTOK / 64), dim3(128), G64_SMEM_BYTES>>>(
        xh, wqkvs_h, qskvs, D_QKVS, HIDD);
    rms_rows<<<NTOK, 256>>>(qskvs,        qs_w,  D_CQ,  D_QKVS, qsh);
    rms_rows<<<NTOK, 256>>>(qskvs + D_CQ, kvs_w, D_CKV, D_QKVS, kvsh);
    gemm_h<2><<<dim3(2048 / 128, NTOK / 128), blk, GH_SMEM_BYTES>>>(
        qsh, wqp_h, qh, 2048, D_CQ, cosT, sinT, 0);

    // join: kvp consumes gates
    cudaStreamWaitEvent(0, evGates, 0);
    gemm_h<3><<<dim3(4096 / 128, NTOK / 128), blk, GH_SMEM_BYTES>>>(
        kvsh, wkvp_h, kvh, 4096, D_CKV, cosT, sinT, gatesh);

    flash_h16<<<dim3(TSEQ / 128, NH, 2), blk, FH_SMEM_BYTES>>>(qh, kvh, attnh);

    gemm64<<<dim3(D_CO / 128, NTOK / 64), dim3(128), G64_SMEM_BYTES>>>(
        attnh, wop_h, o, D_CO, 2048);
    rms_rows<<<NTOK, 256>>>(o, o_w, D_CO, D_CO, oh);
    gemm_h<0><<<dim3(HIDD / 128, NTOK / 128), blk, GH_SMEM_BYTES>>>(
        oh, wos_h, out, HIDD, D_CO, 0, 0, 0);
}